// round 1
// baseline (speedup 1.0000x reference)
#include <cuda_runtime.h>
#include <math.h>

// ---------------- problem constants ----------------
#define B_    8
#define N_    4096      // tokens per batch (64x64)
#define C_    512
#define Hh_   32        // pooled grid 32x32
#define NHI_  1024      // pooled tokens per batch
#define NH_   8         // heads
#define HD_   64        // head dim
#define SCALE 0.125f    // hd^-0.5

// ---------------- scratch (device globals; no allocation allowed) ----------------
__device__ float g_xhi   [B_*NHI_*C_];     //  16 MB  pooled tokens
__device__ float g_qkv_hi[B_*NHI_*3*C_];   //  50 MB
__device__ float g_out_hi[B_*NHI_*C_];     //  16 MB
__device__ float g_win   [B_*N_*C_];       //  64 MB  gathered window tokens
__device__ float g_qkv_lo[B_*N_*3*C_];     // 201 MB
__device__ float g_comb  [B_*N_*C_];       //  64 MB  out_lo + upsampled out_hi

// ---------------- prep: fused avg-pool + window gather ----------------
// One thread per (b, w, ch).  The 2x2 spatial quad of channel `ch` is both:
//   - the avg-pool input for x_hi[b, w, ch]
//   - one aligned float4 of the window matrix (torch-unfold reinterpretation)
__global__ void prep_kernel(const float* __restrict__ x) {
    int id = blockIdx.x * blockDim.x + threadIdx.x;   // 8*1024*512 = 4M threads
    int ch = id & 511;
    int w  = (id >> 9) & 1023;
    int b  = id >> 19;
    int hh = w >> 5, wh = w & 31;

    int r0 = (b * 4096 + (2 * hh) * 64 + 2 * wh) * 512 + ch;
    float v00 = x[r0];
    float v01 = x[r0 + 512];
    float v10 = x[r0 + 64 * 512];
    float v11 = x[r0 + 65 * 512];

    g_xhi[(b * 1024 + w) * 512 + ch] = 0.25f * (v00 + v01 + v10 + v11);

    int t = ch >> 7;            // window-token index
    int c = (4 * ch) & 511;     // window-column (float4 aligned)
    float4 f4 = make_float4(v00, v01, v10, v11);
    *(float4*)&g_win[(long)((b * 1024 + w) * 4 + t) * 512 + c] = f4;
}

// ---------------- SGEMM  C[M,N] = A[M,K] * B[N,K]^T  (+ bias) ----------------
// 128x128 block tile, BK=8, 256 threads, 8x8 microtile. M%128==0, N%128==0, K%8==0.
template <bool BIAS>
__global__ void __launch_bounds__(256) sgemm_nt(
    const float* __restrict__ A, const float* __restrict__ Bm,
    const float* __restrict__ bias, float* __restrict__ Cm,
    int M, int N, int K)
{
    __shared__ float As[8][128];
    __shared__ float Bs[8][128];

    int t  = threadIdx.x;
    int bm = blockIdx.y, bn = blockIdx.x;
    int lr = t >> 1;                // 0..127 load row
    int lc = (t & 1) * 4;           // 0 or 4 load col (k)
    const float* Ap = A  + (long)(bm * 128 + lr) * K + lc;
    const float* Bp = Bm + (long)(bn * 128 + lr) * K + lc;

    int tx = t & 15, ty = t >> 4;

    float acc[8][8];
#pragma unroll
    for (int i = 0; i < 8; i++)
#pragma unroll
        for (int j = 0; j < 8; j++) acc[i][j] = 0.f;

    for (int k0 = 0; k0 < K; k0 += 8) {
        float4 a4 = *(const float4*)(Ap + k0);
        float4 b4 = *(const float4*)(Bp + k0);
        __syncthreads();
        As[lc + 0][lr] = a4.x; As[lc + 1][lr] = a4.y;
        As[lc + 2][lr] = a4.z; As[lc + 3][lr] = a4.w;
        Bs[lc + 0][lr] = b4.x; Bs[lc + 1][lr] = b4.y;
        Bs[lc + 2][lr] = b4.z; Bs[lc + 3][lr] = b4.w;
        __syncthreads();
#pragma unroll
        for (int kk = 0; kk < 8; kk++) {
            float af[8], bf[8];
            *(float4*)(af)     = *(const float4*)&As[kk][ty * 4];
            *(float4*)(af + 4) = *(const float4*)&As[kk][ty * 4 + 64];
            *(float4*)(bf)     = *(const float4*)&Bs[kk][tx * 4];
            *(float4*)(bf + 4) = *(const float4*)&Bs[kk][tx * 4 + 64];
#pragma unroll
            for (int i = 0; i < 8; i++)
#pragma unroll
                for (int j = 0; j < 8; j++)
                    acc[i][j] += af[i] * bf[j];
        }
    }

#pragma unroll
    for (int ri = 0; ri < 2; ri++)
#pragma unroll
    for (int ii = 0; ii < 4; ii++) {
        int r = bm * 128 + ri * 64 + ty * 4 + ii;
#pragma unroll
        for (int ci = 0; ci < 2; ci++) {
            int c = bn * 128 + ci * 64 + tx * 4;
            float4 o;
            o.x = acc[ri * 4 + ii][ci * 4 + 0];
            o.y = acc[ri * 4 + ii][ci * 4 + 1];
            o.z = acc[ri * 4 + ii][ci * 4 + 2];
            o.w = acc[ri * 4 + ii][ci * 4 + 3];
            if (BIAS) {
                o.x += bias[c + 0]; o.y += bias[c + 1];
                o.z += bias[c + 2]; o.w += bias[c + 3];
            }
            *(float4*)&Cm[(long)r * N + c] = o;
        }
    }
}

// ---------------- hi-branch flash attention ----------------
// grid (16 q-tiles, 64 bh).  Br=64 queries, Bc=32 keys per step, hd=64.
// 256 threads: 16x16 grid; S microtile 4x2, O microtile 4x4.
__global__ void __launch_bounds__(256) flash_hi_kernel() {
    __shared__ float Qs[64][68];   // [d][q-row], pre-scaled
    __shared__ float Ks[64][36];   // [d][k-col]
    __shared__ float Vs[32][68];   // [k-col][d]
    __shared__ float Ss[32][68];   // [k-col][q-row]  (P after softmax)
    __shared__ float mrow[64], lrow[64], arow[64];

    int t  = threadIdx.x;
    int qt = blockIdx.x;            // 0..15
    int bh = blockIdx.y;            // 0..63
    int b = bh >> 3, h = bh & 7;
    const float* qkv = g_qkv_hi;

    // load Q tile (transposed, scaled)
    {
        int row = t >> 2;
        int c0  = (t & 3) * 16;
        const float* qg = qkv + (long)(b * 1024 + qt * 64 + row) * 1536 + h * 64 + c0;
#pragma unroll
        for (int u = 0; u < 4; u++) {
            float4 v = *(const float4*)(qg + 4 * u);
            Qs[c0 + 4 * u + 0][row] = v.x * SCALE;
            Qs[c0 + 4 * u + 1][row] = v.y * SCALE;
            Qs[c0 + 4 * u + 2][row] = v.z * SCALE;
            Qs[c0 + 4 * u + 3][row] = v.w * SCALE;
        }
    }
    if (t < 64) { mrow[t] = -1e30f; lrow[t] = 0.f; }

    int tx = t & 15, ty = t >> 4;
    float o[4][4];
#pragma unroll
    for (int i = 0; i < 4; i++)
#pragma unroll
        for (int j = 0; j < 4; j++) o[i][j] = 0.f;

    for (int kt = 0; kt < 32; kt++) {
        __syncthreads();   // protect Ks/Vs/Ss from previous iteration readers
        // load K (transposed) + V (natural) tile: 32 tokens
        {
            int tok = t >> 3;
            int c0  = (t & 7) * 8;
            const float* kg = qkv + (long)(b * 1024 + kt * 32 + tok) * 1536 + 512 + h * 64 + c0;
            const float* vg = kg + 512;
#pragma unroll
            for (int u = 0; u < 2; u++) {
                float4 k4 = *(const float4*)(kg + 4 * u);
                Ks[c0 + 4 * u + 0][tok] = k4.x;
                Ks[c0 + 4 * u + 1][tok] = k4.y;
                Ks[c0 + 4 * u + 2][tok] = k4.z;
                Ks[c0 + 4 * u + 3][tok] = k4.w;
                float4 v4 = *(const float4*)(vg + 4 * u);
                *(float4*)&Vs[tok][c0 + 4 * u] = v4;
            }
        }
        __syncthreads();

        // S = Q K^T  (rows 4ty..+3, cols 2tx..+1)
        float s00 = 0, s01 = 0, s10 = 0, s11 = 0, s20 = 0, s21 = 0, s30 = 0, s31 = 0;
#pragma unroll
        for (int d = 0; d < 64; d++) {
            float4 a  = *(const float4*)&Qs[d][ty * 4];
            float2 bb = *(const float2*)&Ks[d][tx * 2];
            s00 += a.x * bb.x; s01 += a.x * bb.y;
            s10 += a.y * bb.x; s11 += a.y * bb.y;
            s20 += a.z * bb.x; s21 += a.z * bb.y;
            s30 += a.w * bb.x; s31 += a.w * bb.y;
        }
        Ss[tx * 2 + 0][ty * 4 + 0] = s00; Ss[tx * 2 + 1][ty * 4 + 0] = s01;
        Ss[tx * 2 + 0][ty * 4 + 1] = s10; Ss[tx * 2 + 1][ty * 4 + 1] = s11;
        Ss[tx * 2 + 0][ty * 4 + 2] = s20; Ss[tx * 2 + 1][ty * 4 + 2] = s21;
        Ss[tx * 2 + 0][ty * 4 + 3] = s30; Ss[tx * 2 + 1][ty * 4 + 3] = s31;
        __syncthreads();

        // online softmax per row (threads 0..63)
        if (t < 64) {
            float m0 = mrow[t];
            float mx = m0;
#pragma unroll
            for (int c = 0; c < 32; c++) mx = fmaxf(mx, Ss[c][t]);
            float sum = 0.f;
#pragma unroll
            for (int c = 0; c < 32; c++) {
                float e = __expf(Ss[c][t] - mx);
                Ss[c][t] = e;
                sum += e;
            }
            float a = __expf(m0 - mx);
            arow[t] = a; mrow[t] = mx; lrow[t] = lrow[t] * a + sum;
        }
        __syncthreads();

        // rescale O and accumulate P V
        float ai[4];
#pragma unroll
        for (int i = 0; i < 4; i++) ai[i] = arow[ty * 4 + i];
#pragma unroll
        for (int i = 0; i < 4; i++)
#pragma unroll
            for (int j = 0; j < 4; j++) o[i][j] *= ai[i];
#pragma unroll
        for (int c = 0; c < 32; c++) {
            float4 p  = *(const float4*)&Ss[c][ty * 4];
            float4 vv = *(const float4*)&Vs[c][tx * 4];
            o[0][0] += p.x * vv.x; o[0][1] += p.x * vv.y; o[0][2] += p.x * vv.z; o[0][3] += p.x * vv.w;
            o[1][0] += p.y * vv.x; o[1][1] += p.y * vv.y; o[1][2] += p.y * vv.z; o[1][3] += p.y * vv.w;
            o[2][0] += p.z * vv.x; o[2][1] += p.z * vv.y; o[2][2] += p.z * vv.z; o[2][3] += p.z * vv.w;
            o[3][0] += p.w * vv.x; o[3][1] += p.w * vv.y; o[3][2] += p.w * vv.z; o[3][3] += p.w * vv.w;
        }
    }

    // write O / l
#pragma unroll
    for (int i = 0; i < 4; i++) {
        int r = ty * 4 + i;
        float inv = 1.f / lrow[r];
        float4 w4 = make_float4(o[i][0] * inv, o[i][1] * inv, o[i][2] * inv, o[i][3] * inv);
        *(float4*)&g_out_hi[(long)(b * 1024 + qt * 64 + r) * 512 + h * 64 + tx * 4] = w4;
    }
}

// ---------------- lo-branch windowed attention: one warp per (b, w, h) ----------------
__global__ void __launch_bounds__(256) lo_attn_kernel() {
    int gid  = blockIdx.x * blockDim.x + threadIdx.x;
    int warp = gid >> 5;              // 0..65535
    int lane = gid & 31;
    int h = warp & 7;
    int w = (warp >> 3) & 1023;
    int b = warp >> 13;

    const float* base = g_qkv_lo + (long)((b * 1024 + w) * 4) * 1536 + h * 64 + 2 * lane;
    float2 q[4], k[4], v[4];
#pragma unroll
    for (int t = 0; t < 4; t++) {
        q[t] = *(const float2*)(base + (long)t * 1536);
        k[t] = *(const float2*)(base + (long)t * 1536 + 512);
        v[t] = *(const float2*)(base + (long)t * 1536 + 1024);
    }

    float lg[4][4];
#pragma unroll
    for (int ti = 0; ti < 4; ti++)
#pragma unroll
        for (int tj = 0; tj < 4; tj++) {
            float p = q[ti].x * k[tj].x + q[ti].y * k[tj].y;
            p += __shfl_xor_sync(0xffffffffu, p, 16);
            p += __shfl_xor_sync(0xffffffffu, p, 8);
            p += __shfl_xor_sync(0xffffffffu, p, 4);
            p += __shfl_xor_sync(0xffffffffu, p, 2);
            p += __shfl_xor_sync(0xffffffffu, p, 1);
            lg[ti][tj] = p * SCALE;
        }

    int hh = w >> 5, wh = w & 31;
#pragma unroll
    for (int ti = 0; ti < 4; ti++) {
        float mx = fmaxf(fmaxf(lg[ti][0], lg[ti][1]), fmaxf(lg[ti][2], lg[ti][3]));
        float e0 = __expf(lg[ti][0] - mx);
        float e1 = __expf(lg[ti][1] - mx);
        float e2 = __expf(lg[ti][2] - mx);
        float e3 = __expf(lg[ti][3] - mx);
        float is = 1.f / (e0 + e1 + e2 + e3);
        float ox = (e0 * v[0].x + e1 * v[1].x + e2 * v[2].x + e3 * v[3].x) * is;
        float oy = (e0 * v[0].y + e1 * v[1].y + e2 * v[2].y + e3 * v[3].y) * is;
        int pos = (2 * hh + (ti >> 1)) * 64 + 2 * wh + (ti & 1);
        *(float2*)&g_comb[(long)(b * 4096 + pos) * 512 + h * 64 + 2 * lane] =
            make_float2(ox, oy);
    }
}

// ---------------- bilinear upsample 32->64 (half-pixel) + add into comb ----------------
__global__ void __launch_bounds__(128) upsample_add_kernel() {
    int blk = blockIdx.x;           // 32768 = B * 4096
    int b = blk >> 12;
    int p = blk & 4095;
    int y = p >> 6, xq = p & 63;

    float sy = 0.5f * y - 0.25f;
    int   y0 = (int)floorf(sy);
    float fy = sy - (float)y0;
    int   y1 = min(y0 + 1, 31); y0 = max(y0, 0);

    float sx = 0.5f * xq - 0.25f;
    int   x0 = (int)floorf(sx);
    float fx = sx - (float)x0;
    int   x1 = min(x0 + 1, 31); x0 = max(x0, 0);

    float w00 = (1.f - fy) * (1.f - fx), w01 = (1.f - fy) * fx;
    float w10 = fy * (1.f - fx),         w11 = fy * fx;

    int c = threadIdx.x * 4;
    long base = (long)b * 1024 * 512;
    float4 v00 = *(const float4*)&g_out_hi[base + (long)(y0 * 32 + x0) * 512 + c];
    float4 v01 = *(const float4*)&g_out_hi[base + (long)(y0 * 32 + x1) * 512 + c];
    float4 v10 = *(const float4*)&g_out_hi[base + (long)(y1 * 32 + x0) * 512 + c];
    float4 v11 = *(const float4*)&g_out_hi[base + (long)(y1 * 32 + x1) * 512 + c];

    float4* dst = (float4*)&g_comb[(long)(b * 4096 + p) * 512 + c];
    float4 d = *dst;
    d.x += w00 * v00.x + w01 * v01.x + w10 * v10.x + w11 * v11.x;
    d.y += w00 * v00.y + w01 * v01.y + w10 * v10.y + w11 * v11.y;
    d.z += w00 * v00.z + w01 * v01.z + w10 * v10.z + w11 * v11.z;
    d.w += w00 * v00.w + w01 * v01.w + w10 * v10.w + w11 * v11.w;
    *dst = d;
}

// ---------------- launch ----------------
extern "C" void kernel_launch(void* const* d_in, const int* in_sizes, int n_in,
                              void* d_out, int out_size) {
    const float* x     = (const float*)d_in[0];
    const float* Wqkv  = (const float*)d_in[1];
    const float* Wproj = (const float*)d_in[2];
    const float* bproj = (const float*)d_in[3];
    float* out = (float*)d_out;

    float *xhi, *qkvhi, *win, *qkvlo, *comb;
    cudaGetSymbolAddress((void**)&xhi,   g_xhi);
    cudaGetSymbolAddress((void**)&qkvhi, g_qkv_hi);
    cudaGetSymbolAddress((void**)&win,   g_win);
    cudaGetSymbolAddress((void**)&qkvlo, g_qkv_lo);
    cudaGetSymbolAddress((void**)&comb,  g_comb);

    // 1. fused avg-pool + window gather
    prep_kernel<<<16384, 256>>>(x);
    // 2. QKV GEMMs
    sgemm_nt<false><<<dim3(12, 64),  256>>>(xhi, Wqkv, nullptr, qkvhi, 8192,  1536, 512);
    sgemm_nt<false><<<dim3(12, 256), 256>>>(win, Wqkv, nullptr, qkvlo, 32768, 1536, 512);
    // 3. attentions
    flash_hi_kernel<<<dim3(16, 64), 256>>>();
    lo_attn_kernel<<<8192, 256>>>();
    // 4. upsample hi-branch and add
    upsample_add_kernel<<<32768, 128>>>();
    // 5. output projection (+bias)
    sgemm_nt<true><<<dim3(4, 256), 256>>>(comb, Wproj, bproj, out, 32768, 512, 512);
}

// round 3
// speedup vs baseline: 2.0345x; 2.0345x over previous
#include <cuda_runtime.h>
#include <math.h>
#include <stdint.h>

// ---------------- problem constants ----------------
#define B_    8
#define N_    4096      // tokens per batch (64x64)
#define C_    512
#define NH_   8         // heads
#define HD_   64        // head dim
#define SCALE 0.125f    // hd^-0.5

// ---------------- scratch (device globals; no allocation allowed) ----------------
__device__ float g_xhi   [B_*1024*C_];     //  16 MB  pooled tokens
__device__ float g_qkv_hi[B_*1024*3*C_];   //  50 MB
__device__ float g_out_hi[B_*1024*C_];     //  16 MB
__device__ float g_win   [B_*N_*C_];       //  64 MB  gathered window tokens
__device__ float g_qkv_lo[B_*N_*3*C_];     // 201 MB
__device__ float g_comb  [B_*N_*C_];       //  64 MB  out_lo + upsampled out_hi

// ======================= PTX helpers =======================
__device__ __forceinline__ uint32_t smem_u32(const void* p) {
    uint32_t a;
    asm("{ .reg .u64 t; cvta.to.shared.u64 t, %1; cvt.u32.u64 %0, t; }" : "=r"(a) : "l"(p));
    return a;
}
__device__ __forceinline__ float to_tf32(float x) {
    float r;
    asm("cvt.rna.tf32.f32 %0, %1;" : "=f"(r) : "f"(x));
    return r;
}

#define LDSM4(d0, d1, d2, d3, addr)                                            \
    asm volatile("ldmatrix.sync.aligned.m8n8.x4.shared.b16 {%0,%1,%2,%3}, [%4];" \
                 : "=r"(d0), "=r"(d1), "=r"(d2), "=r"(d3) : "r"(addr))

#define MMA_TF32(c, a, b)                                                      \
    asm volatile("mma.sync.aligned.m16n8k8.row.col.f32.tf32.tf32.f32 "         \
                 "{%0,%1,%2,%3}, {%4,%5,%6,%7}, {%8,%9}, {%0,%1,%2,%3};"       \
                 : "+f"((c)[0]), "+f"((c)[1]), "+f"((c)[2]), "+f"((c)[3])      \
                 : "r"((a)[0]), "r"((a)[1]), "r"((a)[2]), "r"((a)[3]),         \
                   "r"((b)[0]), "r"((b)[1]))

// ======================= mma.sync tf32 GEMM =======================
// C[M,N] = A[M,K] * B[N,K]^T (+bias).  Tile 128x128, BK=32, K%32==0.
// 256 threads = 8 warps (2 x 4), warp tile 64x32. Double-buffered SMEM.
#define GEMM_SMEM (1024 + 65536)

template <bool BIAS>
__global__ void __launch_bounds__(256, 1) mma_gemm(
    const float* __restrict__ A, const float* __restrict__ Bm,
    const float* __restrict__ bias, float* __restrict__ Cm,
    int M, int N, int K)
{
    extern __shared__ char dsm[];
    uint32_t sb = (smem_u32(dsm) + 1023u) & ~1023u;
    // buffer b: A tile at sb + b*32768, B tile at sb + b*32768 + 16384

    const int t = threadIdx.x;
    const int bm = blockIdx.y, bn = blockIdx.x;
    const int lane = t & 31, wid = t >> 5;
    const int warp_m = wid & 1, warp_n = wid >> 1;

    // ---- staging geometry: thread covers rows row0+32g, 16B chunk f4 ----
    const int f4 = t & 7;          // which float4 of the 128B row
    const int row0 = t >> 3;       // 0..31
    const float* Ab = A  + (long)(bm * 128 + row0) * K + f4 * 4;
    const float* Bb = Bm + (long)(bn * 128 + row0) * K + f4 * 4;
    uint32_t stOff[4];
#pragma unroll
    for (int g = 0; g < 4; g++) {
        uint32_t off = (row0 + 32 * g) * 128 + f4 * 16;
        stOff[g] = off ^ ((off >> 3) & 0x70);
    }

    // ---- ldmatrix geometry ----
    const int l = lane & 7, g8 = lane >> 3;
    // A: matrices a0(r0-7,k0-3) a1(r8-15,k0-3) a2(r0-7,k4-7) a3(r8-15,k4-7)
    const int aRow = warp_m * 64 + (g8 & 1) * 8 + l;         // + mi*16
    const uint32_t aSw   = (uint32_t)((aRow & 7) << 4);
    const uint32_t aKoff = (uint32_t)((g8 >> 1) * 16);
    // B: x4 covers two n8 tiles: b0(n0-7,k0-3) b1(n0-7,k4-7) b0(n8-15,..) b1
    const int bRow = warp_n * 32 + (g8 >> 1) * 8 + l;        // + j*16
    const uint32_t bSw   = (uint32_t)((bRow & 7) << 4);
    const uint32_t bKoff = (uint32_t)((g8 & 1) * 16);

    float acc[4][4][4];
#pragma unroll
    for (int mi = 0; mi < 4; mi++)
#pragma unroll
        for (int ni = 0; ni < 4; ni++)
#pragma unroll
            for (int q = 0; q < 4; q++) acc[mi][ni][q] = 0.f;

    const int KC = K >> 5;   // chunks of 32
    float4 pa[4], pb[4];
#pragma unroll
    for (int g = 0; g < 4; g++) {
        pa[g] = *(const float4*)(Ab + (long)(g * 32) * K);
        pb[g] = *(const float4*)(Bb + (long)(g * 32) * K);
    }
    {   // store chunk 0 into buffer 0
        uint32_t sA = sb, sB = sb + 16384;
#pragma unroll
        for (int g = 0; g < 4; g++) {
            float ax = to_tf32(pa[g].x), ay = to_tf32(pa[g].y),
                  az = to_tf32(pa[g].z), aw = to_tf32(pa[g].w);
            asm volatile("st.shared.v4.b32 [%0], {%1,%2,%3,%4};"
                         :: "r"(sA + stOff[g]), "f"(ax), "f"(ay), "f"(az), "f"(aw) : "memory");
            float bx = to_tf32(pb[g].x), by = to_tf32(pb[g].y),
                  bz = to_tf32(pb[g].z), bw = to_tf32(pb[g].w);
            asm volatile("st.shared.v4.b32 [%0], {%1,%2,%3,%4};"
                         :: "r"(sB + stOff[g]), "f"(bx), "f"(by), "f"(bz), "f"(bw) : "memory");
        }
    }
    __syncthreads();

    for (int c = 0; c < KC; c++) {
        if (c + 1 < KC) {
            const float* An = Ab + (c + 1) * 32;
            const float* Bn = Bb + (c + 1) * 32;
#pragma unroll
            for (int g = 0; g < 4; g++) {
                pa[g] = *(const float4*)(An + (long)(g * 32) * K);
                pb[g] = *(const float4*)(Bn + (long)(g * 32) * K);
            }
        }
        uint32_t bufA = sb + (c & 1) * 32768;
        uint32_t bufB = bufA + 16384;
#pragma unroll
        for (int kk = 0; kk < 4; kk++) {
            uint32_t aOff = ((uint32_t)(kk * 32) + aKoff) ^ aSw;
            uint32_t bOff = ((uint32_t)(kk * 32) + bKoff) ^ bSw;
            uint32_t af[4][4], bf[4][2];
#pragma unroll
            for (int mi = 0; mi < 4; mi++)
                LDSM4(af[mi][0], af[mi][1], af[mi][2], af[mi][3],
                      bufA + (uint32_t)((aRow + mi * 16) * 128) + aOff);
#pragma unroll
            for (int j = 0; j < 2; j++) {
                uint32_t r0, r1, r2, r3;
                LDSM4(r0, r1, r2, r3,
                      bufB + (uint32_t)((bRow + j * 16) * 128) + bOff);
                bf[2 * j][0] = r0;     bf[2 * j][1] = r1;
                bf[2 * j + 1][0] = r2; bf[2 * j + 1][1] = r3;
            }
#pragma unroll
            for (int mi = 0; mi < 4; mi++)
#pragma unroll
                for (int ni = 0; ni < 4; ni++)
                    MMA_TF32(acc[mi][ni], af[mi], bf[ni]);
        }
        if (c + 1 < KC) {
            uint32_t sA = sb + ((c + 1) & 1) * 32768;
            uint32_t sB = sA + 16384;
#pragma unroll
            for (int g = 0; g < 4; g++) {
                float ax = to_tf32(pa[g].x), ay = to_tf32(pa[g].y),
                      az = to_tf32(pa[g].z), aw = to_tf32(pa[g].w);
                asm volatile("st.shared.v4.b32 [%0], {%1,%2,%3,%4};"
                             :: "r"(sA + stOff[g]), "f"(ax), "f"(ay), "f"(az), "f"(aw) : "memory");
                float bx = to_tf32(pb[g].x), by = to_tf32(pb[g].y),
                      bz = to_tf32(pb[g].z), bw = to_tf32(pb[g].w);
                asm volatile("st.shared.v4.b32 [%0], {%1,%2,%3,%4};"
                             :: "r"(sB + stOff[g]), "f"(bx), "f"(by), "f"(bz), "f"(bw) : "memory");
            }
        }
        __syncthreads();
    }

    // ---- epilogue: write fragments directly ----
    const int qr = lane >> 2, qc = lane & 3;
#pragma unroll
    for (int mi = 0; mi < 4; mi++) {
        int row = bm * 128 + warp_m * 64 + mi * 16 + qr;
#pragma unroll
        for (int ni = 0; ni < 4; ni++) {
            int col = bn * 128 + warp_n * 32 + ni * 8 + qc * 2;
            float bx = 0.f, by = 0.f;
            if (BIAS) { float2 b2 = *(const float2*)&bias[col]; bx = b2.x; by = b2.y; }
            *(float2*)&Cm[(long)row * N + col] =
                make_float2(acc[mi][ni][0] + bx, acc[mi][ni][1] + by);
            *(float2*)&Cm[(long)(row + 8) * N + col] =
                make_float2(acc[mi][ni][2] + bx, acc[mi][ni][3] + by);
        }
    }
}

// ---------------- prep: fused avg-pool + window gather ----------------
__global__ void prep_kernel(const float* __restrict__ x) {
    int id = blockIdx.x * blockDim.x + threadIdx.x;
    int ch = id & 511;
    int w  = (id >> 9) & 1023;
    int b  = id >> 19;
    int hh = w >> 5, wh = w & 31;

    int r0 = (b * 4096 + (2 * hh) * 64 + 2 * wh) * 512 + ch;
    float v00 = x[r0];
    float v01 = x[r0 + 512];
    float v10 = x[r0 + 64 * 512];
    float v11 = x[r0 + 65 * 512];

    g_xhi[(b * 1024 + w) * 512 + ch] = 0.25f * (v00 + v01 + v10 + v11);

    int t = ch >> 7;
    int c = (4 * ch) & 511;
    float4 f4 = make_float4(v00, v01, v10, v11);
    *(float4*)&g_win[(long)((b * 1024 + w) * 4 + t) * 512 + c] = f4;
}

// ---------------- hi-branch flash attention (fp32, unchanged) ----------------
__global__ void __launch_bounds__(256) flash_hi_kernel() {
    __shared__ float Qs[64][68];
    __shared__ float Ks[64][36];
    __shared__ float Vs[32][68];
    __shared__ float Ss[32][68];
    __shared__ float mrow[64], lrow[64], arow[64];

    int t  = threadIdx.x;
    int qt = blockIdx.x;
    int bh = blockIdx.y;
    int b = bh >> 3, h = bh & 7;
    const float* qkv = g_qkv_hi;

    {
        int row = t >> 2;
        int c0  = (t & 3) * 16;
        const float* qg = qkv + (long)(b * 1024 + qt * 64 + row) * 1536 + h * 64 + c0;
#pragma unroll
        for (int u = 0; u < 4; u++) {
            float4 v = *(const float4*)(qg + 4 * u);
            Qs[c0 + 4 * u + 0][row] = v.x * SCALE;
            Qs[c0 + 4 * u + 1][row] = v.y * SCALE;
            Qs[c0 + 4 * u + 2][row] = v.z * SCALE;
            Qs[c0 + 4 * u + 3][row] = v.w * SCALE;
        }
    }
    if (t < 64) { mrow[t] = -1e30f; lrow[t] = 0.f; }

    int tx = t & 15, ty = t >> 4;
    float o[4][4];
#pragma unroll
    for (int i = 0; i < 4; i++)
#pragma unroll
        for (int j = 0; j < 4; j++) o[i][j] = 0.f;

    for (int kt = 0; kt < 32; kt++) {
        __syncthreads();
        {
            int tok = t >> 3;
            int c0  = (t & 7) * 8;
            const float* kg = qkv + (long)(b * 1024 + kt * 32 + tok) * 1536 + 512 + h * 64 + c0;
            const float* vg = kg + 512;
#pragma unroll
            for (int u = 0; u < 2; u++) {
                float4 k4 = *(const float4*)(kg + 4 * u);
                Ks[c0 + 4 * u + 0][tok] = k4.x;
                Ks[c0 + 4 * u + 1][tok] = k4.y;
                Ks[c0 + 4 * u + 2][tok] = k4.z;
                Ks[c0 + 4 * u + 3][tok] = k4.w;
                float4 v4 = *(const float4*)(vg + 4 * u);
                *(float4*)&Vs[tok][c0 + 4 * u] = v4;
            }
        }
        __syncthreads();

        float s00 = 0, s01 = 0, s10 = 0, s11 = 0, s20 = 0, s21 = 0, s30 = 0, s31 = 0;
#pragma unroll
        for (int d = 0; d < 64; d++) {
            float4 a  = *(const float4*)&Qs[d][ty * 4];
            float2 bb = *(const float2*)&Ks[d][tx * 2];
            s00 += a.x * bb.x; s01 += a.x * bb.y;
            s10 += a.y * bb.x; s11 += a.y * bb.y;
            s20 += a.z * bb.x; s21 += a.z * bb.y;
            s30 += a.w * bb.x; s31 += a.w * bb.y;
        }
        Ss[tx * 2 + 0][ty * 4 + 0] = s00; Ss[tx * 2 + 1][ty * 4 + 0] = s01;
        Ss[tx * 2 + 0][ty * 4 + 1] = s10; Ss[tx * 2 + 1][ty * 4 + 1] = s11;
        Ss[tx * 2 + 0][ty * 4 + 2] = s20; Ss[tx * 2 + 1][ty * 4 + 2] = s21;
        Ss[tx * 2 + 0][ty * 4 + 3] = s30; Ss[tx * 2 + 1][ty * 4 + 3] = s31;
        __syncthreads();

        if (t < 64) {
            float m0 = mrow[t];
            float mx = m0;
#pragma unroll
            for (int c = 0; c < 32; c++) mx = fmaxf(mx, Ss[c][t]);
            float sum = 0.f;
#pragma unroll
            for (int c = 0; c < 32; c++) {
                float e = __expf(Ss[c][t] - mx);
                Ss[c][t] = e;
                sum += e;
            }
            float a = __expf(m0 - mx);
            arow[t] = a; mrow[t] = mx; lrow[t] = lrow[t] * a + sum;
        }
        __syncthreads();

        float ai[4];
#pragma unroll
        for (int i = 0; i < 4; i++) ai[i] = arow[ty * 4 + i];
#pragma unroll
        for (int i = 0; i < 4; i++)
#pragma unroll
            for (int j = 0; j < 4; j++) o[i][j] *= ai[i];
#pragma unroll
        for (int c = 0; c < 32; c++) {
            float4 p  = *(const float4*)&Ss[c][ty * 4];
            float4 vv = *(const float4*)&Vs[c][tx * 4];
            o[0][0] += p.x * vv.x; o[0][1] += p.x * vv.y; o[0][2] += p.x * vv.z; o[0][3] += p.x * vv.w;
            o[1][0] += p.y * vv.x; o[1][1] += p.y * vv.y; o[1][2] += p.y * vv.z; o[1][3] += p.y * vv.w;
            o[2][0] += p.z * vv.x; o[2][1] += p.z * vv.y; o[2][2] += p.z * vv.z; o[2][3] += p.z * vv.w;
            o[3][0] += p.w * vv.x; o[3][1] += p.w * vv.y; o[3][2] += p.w * vv.z; o[3][3] += p.w * vv.w;
        }
    }

#pragma unroll
    for (int i = 0; i < 4; i++) {
        int r = ty * 4 + i;
        float inv = 1.f / lrow[r];
        float4 w4 = make_float4(o[i][0] * inv, o[i][1] * inv, o[i][2] * inv, o[i][3] * inv);
        *(float4*)&g_out_hi[(long)(b * 1024 + qt * 64 + r) * 512 + h * 64 + tx * 4] = w4;
    }
}

// ---------------- lo-branch windowed attention ----------------
__global__ void __launch_bounds__(256) lo_attn_kernel() {
    int gid  = blockIdx.x * blockDim.x + threadIdx.x;
    int warp = gid >> 5;
    int lane = gid & 31;
    int h = warp & 7;
    int w = (warp >> 3) & 1023;
    int b = warp >> 13;

    const float* base = g_qkv_lo + (long)((b * 1024 + w) * 4) * 1536 + h * 64 + 2 * lane;
    float2 q[4], k[4], v[4];
#pragma unroll
    for (int t = 0; t < 4; t++) {
        q[t] = *(const float2*)(base + (long)t * 1536);
        k[t] = *(const float2*)(base + (long)t * 1536 + 512);
        v[t] = *(const float2*)(base + (long)t * 1536 + 1024);
    }

    float lg[4][4];
#pragma unroll
    for (int ti = 0; ti < 4; ti++)
#pragma unroll
        for (int tj = 0; tj < 4; tj++) {
            float p = q[ti].x * k[tj].x + q[ti].y * k[tj].y;
            p += __shfl_xor_sync(0xffffffffu, p, 16);
            p += __shfl_xor_sync(0xffffffffu, p, 8);
            p += __shfl_xor_sync(0xffffffffu, p, 4);
            p += __shfl_xor_sync(0xffffffffu, p, 2);
            p += __shfl_xor_sync(0xffffffffu, p, 1);
            lg[ti][tj] = p * SCALE;
        }

    int hh = w >> 5, wh = w & 31;
#pragma unroll
    for (int ti = 0; ti < 4; ti++) {
        float mx = fmaxf(fmaxf(lg[ti][0], lg[ti][1]), fmaxf(lg[ti][2], lg[ti][3]));
        float e0 = __expf(lg[ti][0] - mx);
        float e1 = __expf(lg[ti][1] - mx);
        float e2 = __expf(lg[ti][2] - mx);
        float e3 = __expf(lg[ti][3] - mx);
        float is = 1.f / (e0 + e1 + e2 + e3);
        float ox = (e0 * v[0].x + e1 * v[1].x + e2 * v[2].x + e3 * v[3].x) * is;
        float oy = (e0 * v[0].y + e1 * v[1].y + e2 * v[2].y + e3 * v[3].y) * is;
        int pos = (2 * hh + (ti >> 1)) * 64 + 2 * wh + (ti & 1);
        *(float2*)&g_comb[(long)(b * 4096 + pos) * 512 + h * 64 + 2 * lane] =
            make_float2(ox, oy);
    }
}

// ---------------- bilinear upsample 32->64 + add ----------------
__global__ void __launch_bounds__(128) upsample_add_kernel() {
    int blk = blockIdx.x;
    int b = blk >> 12;
    int p = blk & 4095;
    int y = p >> 6, xq = p & 63;

    float sy = 0.5f * y - 0.25f;
    int   y0 = (int)floorf(sy);
    float fy = sy - (float)y0;
    int   y1 = min(y0 + 1, 31); y0 = max(y0, 0);

    float sx = 0.5f * xq - 0.25f;
    int   x0 = (int)floorf(sx);
    float fx = sx - (float)x0;
    int   x1 = min(x0 + 1, 31); x0 = max(x0, 0);

    float w00 = (1.f - fy) * (1.f - fx), w01 = (1.f - fy) * fx;
    float w10 = fy * (1.f - fx),         w11 = fy * fx;

    int c = threadIdx.x * 4;
    long base = (long)b * 1024 * 512;
    float4 v00 = *(const float4*)&g_out_hi[base + (long)(y0 * 32 + x0) * 512 + c];
    float4 v01 = *(const float4*)&g_out_hi[base + (long)(y0 * 32 + x1) * 512 + c];
    float4 v10 = *(const float4*)&g_out_hi[base + (long)(y1 * 32 + x0) * 512 + c];
    float4 v11 = *(const float4*)&g_out_hi[base + (long)(y1 * 32 + x1) * 512 + c];

    float4* dst = (float4*)&g_comb[(long)(b * 4096 + p) * 512 + c];
    float4 d = *dst;
    d.x += w00 * v00.x + w01 * v01.x + w10 * v10.x + w11 * v11.x;
    d.y += w00 * v00.y + w01 * v01.y + w10 * v10.y + w11 * v11.y;
    d.z += w00 * v00.z + w01 * v01.z + w10 * v10.z + w11 * v11.z;
    d.w += w00 * v00.w + w01 * v01.w + w10 * v10.w + w11 * v11.w;
    *dst = d;
}

// ---------------- launch ----------------
extern "C" void kernel_launch(void* const* d_in, const int* in_sizes, int n_in,
                              void* d_out, int out_size) {
    const float* x     = (const float*)d_in[0];
    const float* Wqkv  = (const float*)d_in[1];
    const float* Wproj = (const float*)d_in[2];
    const float* bproj = (const float*)d_in[3];
    float* out = (float*)d_out;

    float *xhi, *qkvhi, *win, *qkvlo, *comb;
    cudaGetSymbolAddress((void**)&xhi,   g_xhi);
    cudaGetSymbolAddress((void**)&qkvhi, g_qkv_hi);
    cudaGetSymbolAddress((void**)&win,   g_win);
    cudaGetSymbolAddress((void**)&qkvlo, g_qkv_lo);
    cudaGetSymbolAddress((void**)&comb,  g_comb);

    cudaFuncSetAttribute(mma_gemm<false>, cudaFuncAttributeMaxDynamicSharedMemorySize, GEMM_SMEM);
    cudaFuncSetAttribute(mma_gemm<true>,  cudaFuncAttributeMaxDynamicSharedMemorySize, GEMM_SMEM);

    // 1. fused avg-pool + window gather
    prep_kernel<<<16384, 256>>>(x);
    // 2. QKV GEMMs (tf32 mma.sync tensor cores)
    mma_gemm<false><<<dim3(12, 64),  256, GEMM_SMEM>>>(xhi, Wqkv, nullptr, qkvhi, 8192,  1536, 512);
    mma_gemm<false><<<dim3(12, 256), 256, GEMM_SMEM>>>(win, Wqkv, nullptr, qkvlo, 32768, 1536, 512);
    // 3. attentions
    flash_hi_kernel<<<dim3(16, 64), 256>>>();
    lo_attn_kernel<<<8192, 256>>>();
    // 4. upsample hi-branch and add
    upsample_add_kernel<<<32768, 128>>>();
    // 5. output projection (+bias, tf32 mma.sync)
    mma_gemm<true><<<dim3(4, 256), 256, GEMM_SMEM>>>(comb, Wproj, bproj, out, 32768, 512, 512);
}

// round 4
// speedup vs baseline: 2.4929x; 1.2253x over previous
#include <cuda_runtime.h>
#include <math.h>
#include <stdint.h>

// ---------------- problem constants ----------------
#define B_    8
#define N_    4096      // tokens per batch (64x64)
#define C_    512
#define NH_   8         // heads
#define HD_   64        // head dim
#define SCALE 0.125f    // hd^-0.5

// ---------------- scratch (device globals; no allocation allowed) ----------------
__device__ float g_xhi   [B_*1024*C_];     //  16 MB  pooled tokens
__device__ float g_qkv_hi[B_*1024*3*C_];   //  50 MB
__device__ float g_out_hi[B_*1024*C_];     //  16 MB
__device__ float g_win   [B_*N_*C_];       //  64 MB  gathered window tokens
__device__ float g_qkv_lo[B_*N_*3*C_];     // 201 MB
__device__ float g_comb  [B_*N_*C_];       //  64 MB  out_lo + upsampled out_hi

// ======================= PTX helpers =======================
__device__ __forceinline__ uint32_t smem_u32(const void* p) {
    uint32_t a;
    asm("{ .reg .u64 t; cvta.to.shared.u64 t, %1; cvt.u32.u64 %0, t; }" : "=r"(a) : "l"(p));
    return a;
}
__device__ __forceinline__ float to_tf32(float x) {
    float r;
    asm("cvt.rna.tf32.f32 %0, %1;" : "=f"(r) : "f"(x));
    return r;
}

#define LDSM4(d0, d1, d2, d3, addr)                                            \
    asm volatile("ldmatrix.sync.aligned.m8n8.x4.shared.b16 {%0,%1,%2,%3}, [%4];" \
                 : "=r"(d0), "=r"(d1), "=r"(d2), "=r"(d3) : "r"(addr))

#define MMA_TF32(c, a, b)                                                      \
    asm volatile("mma.sync.aligned.m16n8k8.row.col.f32.tf32.tf32.f32 "         \
                 "{%0,%1,%2,%3}, {%4,%5,%6,%7}, {%8,%9}, {%0,%1,%2,%3};"       \
                 : "+f"((c)[0]), "+f"((c)[1]), "+f"((c)[2]), "+f"((c)[3])      \
                 : "r"((a)[0]), "r"((a)[1]), "r"((a)[2]), "r"((a)[3]),         \
                   "r"((b)[0]), "r"((b)[1]))

#define STSV4(addr, x, y, z, w)                                                \
    asm volatile("st.shared.v4.b32 [%0], {%1,%2,%3,%4};"                       \
                 :: "r"(addr), "f"(x), "f"(y), "f"(z), "f"(w) : "memory")
#define STSV2(addr, x, y)                                                      \
    asm volatile("st.shared.v2.b32 [%0], {%1,%2};"                             \
                 :: "r"(addr), "f"(x), "f"(y) : "memory")
#define STSB32(addr, x)                                                        \
    asm volatile("st.shared.b32 [%0], %1;" :: "r"(addr), "f"(x) : "memory")

// ======================= mma.sync tf32 GEMM (from R3, unchanged) =======================
#define GEMM_SMEM (1024 + 65536)

template <bool BIAS>
__global__ void __launch_bounds__(256, 1) mma_gemm(
    const float* __restrict__ A, const float* __restrict__ Bm,
    const float* __restrict__ bias, float* __restrict__ Cm,
    int M, int N, int K)
{
    extern __shared__ char dsm[];
    uint32_t sb = (smem_u32(dsm) + 1023u) & ~1023u;

    const int t = threadIdx.x;
    const int bm = blockIdx.y, bn = blockIdx.x;
    const int lane = t & 31, wid = t >> 5;
    const int warp_m = wid & 1, warp_n = wid >> 1;

    const int f4 = t & 7;
    const int row0 = t >> 3;
    const float* Ab = A  + (long)(bm * 128 + row0) * K + f4 * 4;
    const float* Bb = Bm + (long)(bn * 128 + row0) * K + f4 * 4;
    uint32_t stOff[4];
#pragma unroll
    for (int g = 0; g < 4; g++) {
        uint32_t off = (row0 + 32 * g) * 128 + f4 * 16;
        stOff[g] = off ^ ((off >> 3) & 0x70);
    }

    const int l = lane & 7, g8 = lane >> 3;
    const int aRow = warp_m * 64 + (g8 & 1) * 8 + l;
    const uint32_t aSw   = (uint32_t)((aRow & 7) << 4);
    const uint32_t aKoff = (uint32_t)((g8 >> 1) * 16);
    const int bRow = warp_n * 32 + (g8 >> 1) * 8 + l;
    const uint32_t bSw   = (uint32_t)((bRow & 7) << 4);
    const uint32_t bKoff = (uint32_t)((g8 & 1) * 16);

    float acc[4][4][4];
#pragma unroll
    for (int mi = 0; mi < 4; mi++)
#pragma unroll
        for (int ni = 0; ni < 4; ni++)
#pragma unroll
            for (int q = 0; q < 4; q++) acc[mi][ni][q] = 0.f;

    const int KC = K >> 5;
    float4 pa[4], pb[4];
#pragma unroll
    for (int g = 0; g < 4; g++) {
        pa[g] = *(const float4*)(Ab + (long)(g * 32) * K);
        pb[g] = *(const float4*)(Bb + (long)(g * 32) * K);
    }
    {
        uint32_t sA = sb, sB = sb + 16384;
#pragma unroll
        for (int g = 0; g < 4; g++) {
            STSV4(sA + stOff[g], to_tf32(pa[g].x), to_tf32(pa[g].y), to_tf32(pa[g].z), to_tf32(pa[g].w));
            STSV4(sB + stOff[g], to_tf32(pb[g].x), to_tf32(pb[g].y), to_tf32(pb[g].z), to_tf32(pb[g].w));
        }
    }
    __syncthreads();

    for (int c = 0; c < KC; c++) {
        if (c + 1 < KC) {
            const float* An = Ab + (c + 1) * 32;
            const float* Bn = Bb + (c + 1) * 32;
#pragma unroll
            for (int g = 0; g < 4; g++) {
                pa[g] = *(const float4*)(An + (long)(g * 32) * K);
                pb[g] = *(const float4*)(Bn + (long)(g * 32) * K);
            }
        }
        uint32_t bufA = sb + (c & 1) * 32768;
        uint32_t bufB = bufA + 16384;
#pragma unroll
        for (int kk = 0; kk < 4; kk++) {
            uint32_t aOff = ((uint32_t)(kk * 32) + aKoff) ^ aSw;
            uint32_t bOff = ((uint32_t)(kk * 32) + bKoff) ^ bSw;
            uint32_t af[4][4], bf[4][2];
#pragma unroll
            for (int mi = 0; mi < 4; mi++)
                LDSM4(af[mi][0], af[mi][1], af[mi][2], af[mi][3],
                      bufA + (uint32_t)((aRow + mi * 16) * 128) + aOff);
#pragma unroll
            for (int j = 0; j < 2; j++) {
                uint32_t r0, r1, r2, r3;
                LDSM4(r0, r1, r2, r3,
                      bufB + (uint32_t)((bRow + j * 16) * 128) + bOff);
                bf[2 * j][0] = r0;     bf[2 * j][1] = r1;
                bf[2 * j + 1][0] = r2; bf[2 * j + 1][1] = r3;
            }
#pragma unroll
            for (int mi = 0; mi < 4; mi++)
#pragma unroll
                for (int ni = 0; ni < 4; ni++)
                    MMA_TF32(acc[mi][ni], af[mi], bf[ni]);
        }
        if (c + 1 < KC) {
            uint32_t sA = sb + ((c + 1) & 1) * 32768;
            uint32_t sB = sA + 16384;
#pragma unroll
            for (int g = 0; g < 4; g++) {
                STSV4(sA + stOff[g], to_tf32(pa[g].x), to_tf32(pa[g].y), to_tf32(pa[g].z), to_tf32(pa[g].w));
                STSV4(sB + stOff[g], to_tf32(pb[g].x), to_tf32(pb[g].y), to_tf32(pb[g].z), to_tf32(pb[g].w));
            }
        }
        __syncthreads();
    }

    const int qr = lane >> 2, qc = lane & 3;
#pragma unroll
    for (int mi = 0; mi < 4; mi++) {
        int row = bm * 128 + warp_m * 64 + mi * 16 + qr;
#pragma unroll
        for (int ni = 0; ni < 4; ni++) {
            int col = bn * 128 + warp_n * 32 + ni * 8 + qc * 2;
            float bx = 0.f, by = 0.f;
            if (BIAS) { float2 b2 = *(const float2*)&bias[col]; bx = b2.x; by = b2.y; }
            *(float2*)&Cm[(long)row * N + col] =
                make_float2(acc[mi][ni][0] + bx, acc[mi][ni][1] + by);
            *(float2*)&Cm[(long)(row + 8) * N + col] =
                make_float2(acc[mi][ni][2] + bx, acc[mi][ni][3] + by);
        }
    }
}

// ---------------- prep: fused avg-pool + window gather ----------------
__global__ void prep_kernel(const float* __restrict__ x) {
    int id = blockIdx.x * blockDim.x + threadIdx.x;
    int ch = id & 511;
    int w  = (id >> 9) & 1023;
    int b  = id >> 19;
    int hh = w >> 5, wh = w & 31;

    int r0 = (b * 4096 + (2 * hh) * 64 + 2 * wh) * 512 + ch;
    float v00 = x[r0];
    float v01 = x[r0 + 512];
    float v10 = x[r0 + 64 * 512];
    float v11 = x[r0 + 65 * 512];

    g_xhi[(b * 1024 + w) * 512 + ch] = 0.25f * (v00 + v01 + v10 + v11);

    int t = ch >> 7;
    int c = (4 * ch) & 511;
    float4 f4 = make_float4(v00, v01, v10, v11);
    *(float4*)&g_win[(long)((b * 1024 + w) * 4 + t) * 512 + c] = f4;
}

// ======================= tensor-core hi-branch flash attention =======================
// grid (16 q-tiles, 64 bh), 128 threads = 4 warps; warp w owns q-rows 16w..16w+15.
// KV tiles of 64 tokens, 16 iterations. QK^T uses 3xTF32 split; PV single tf32.
// smem: Q_hi 16K | Q_lo 16K | K_hi 16K | K_lo 16K | V^T 16K | P 16K  (row = 256B, swizzled)
#define FLASH_SMEM (96 * 1024 + 1024)

__global__ void __launch_bounds__(128) flash_hi_tc() {
    extern __shared__ char fsm[];
    uint32_t sb = (smem_u32(fsm) + 1023u) & ~1023u;
    const uint32_t QH = sb, QL = sb + 16384, KH = sb + 32768, KL = sb + 49152,
                   VS = sb + 65536, PS = sb + 81920;

    const int t = threadIdx.x, lane = t & 31, wid = t >> 5;
    const int qt = blockIdx.x, bh = blockIdx.y;
    const int b = bh >> 3, h = bh & 7;

    // ---- load Q (scaled, hi/lo split) ----
    {
        int row = t >> 1, hb = t & 1;
        const float* qg = g_qkv_hi + (long)(b * 1024 + qt * 64 + row) * 1536 + h * 64 + hb * 32;
        uint32_t rbase = (uint32_t)(row * 256);
        uint32_t rsw = (uint32_t)((row & 7) << 4);
#pragma unroll
        for (int i = 0; i < 8; i++) {
            float4 v = *(const float4*)(qg + i * 4);
            v.x *= SCALE; v.y *= SCALE; v.z *= SCALE; v.w *= SCALE;
            float hx = to_tf32(v.x), hy = to_tf32(v.y), hz = to_tf32(v.z), hw = to_tf32(v.w);
            uint32_t off = ((uint32_t)(hb * 128 + i * 16)) ^ rsw;
            STSV4(QH + rbase + off, hx, hy, hz, hw);
            STSV4(QL + rbase + off, to_tf32(v.x - hx), to_tf32(v.y - hy),
                                    to_tf32(v.z - hz), to_tf32(v.w - hw));
        }
    }

    // ---- fragment geometry ----
    const int l7 = lane & 7, g8 = lane >> 3;
    const int aRow = wid * 16 + (g8 & 1) * 8 + l7;       // Q / P rows
    const uint32_t aKsel = (uint32_t)((g8 >> 1) * 16);
    const int bRow = (g8 >> 1) * 8 + l7;                 // + j*16
    const uint32_t bKsel = (uint32_t)((g8 & 1) * 16);
    const uint32_t swl = (uint32_t)(l7 << 4);            // (row&7)<<4 for both aRow and bRow
    const uint32_t aBase = (uint32_t)(aRow * 256);
    const int qr = lane >> 2, qc = lane & 3;

    float oacc[8][4];
#pragma unroll
    for (int ni = 0; ni < 8; ni++)
#pragma unroll
        for (int q = 0; q < 4; q++) oacc[ni][q] = 0.f;
    float m0 = -1e30f, m1 = -1e30f, l0 = 0.f, l1 = 0.f;

    for (int kt = 0; kt < 16; kt++) {
        __syncthreads();   // prior iter finished reading K/V
        // ---- load K (hi/lo) and V (transposed) tiles ----
        {
            int row = t >> 1, hb = t & 1;
            const float* kg = g_qkv_hi + (long)(b * 1024 + kt * 64 + row) * 1536 + 512 + h * 64 + hb * 32;
            const float* vg = kg + 512;
            uint32_t rbase = (uint32_t)(row * 256);
            uint32_t rsw = (uint32_t)((row & 7) << 4);
            uint32_t tokb = (uint32_t)(row * 4);
#pragma unroll
            for (int i = 0; i < 8; i++) {
                float4 kv = *(const float4*)(kg + i * 4);
                float hx = to_tf32(kv.x), hy = to_tf32(kv.y),
                      hz = to_tf32(kv.z), hw = to_tf32(kv.w);
                uint32_t off = ((uint32_t)(hb * 128 + i * 16)) ^ rsw;
                STSV4(KH + rbase + off, hx, hy, hz, hw);
                STSV4(KL + rbase + off, to_tf32(kv.x - hx), to_tf32(kv.y - hy),
                                        to_tf32(kv.z - hz), to_tf32(kv.w - hw));
                float4 vv = *(const float4*)(vg + i * 4);
                int d0 = hb * 32 + i * 4;
                STSB32(VS + (uint32_t)((d0 + 0) * 256) + (tokb ^ (uint32_t)(((d0 + 0) & 7) << 4)), to_tf32(vv.x));
                STSB32(VS + (uint32_t)((d0 + 1) * 256) + (tokb ^ (uint32_t)(((d0 + 1) & 7) << 4)), to_tf32(vv.y));
                STSB32(VS + (uint32_t)((d0 + 2) * 256) + (tokb ^ (uint32_t)(((d0 + 2) & 7) << 4)), to_tf32(vv.z));
                STSB32(VS + (uint32_t)((d0 + 3) * 256) + (tokb ^ (uint32_t)(((d0 + 3) & 7) << 4)), to_tf32(vv.w));
            }
        }
        __syncthreads();

        // ---- S = Q K^T (3xTF32) ----
        float sacc[8][4];
#pragma unroll
        for (int ni = 0; ni < 8; ni++)
#pragma unroll
            for (int q = 0; q < 4; q++) sacc[ni][q] = 0.f;

#pragma unroll
        for (int kk = 0; kk < 8; kk++) {
            uint32_t kb = (uint32_t)(kk * 32);
            uint32_t ah[4], al_[4];
            uint32_t aOff = (kb + aKsel) ^ swl;
            LDSM4(ah[0], ah[1], ah[2], ah[3], QH + aBase + aOff);
            LDSM4(al_[0], al_[1], al_[2], al_[3], QL + aBase + aOff);
            uint32_t bOff = (kb + bKsel) ^ swl;
#pragma unroll
            for (int j = 0; j < 4; j++) {
                uint32_t rb = (uint32_t)((bRow + j * 16) * 256) + bOff;
                uint32_t h0, h1, h2, h3, s0, s1, s2, s3;
                LDSM4(h0, h1, h2, h3, KH + rb);
                LDSM4(s0, s1, s2, s3, KL + rb);
                uint32_t bhv[2], blv[2];
                bhv[0] = h0; bhv[1] = h1; blv[0] = s0; blv[1] = s1;
                MMA_TF32(sacc[2 * j], ah, bhv);
                MMA_TF32(sacc[2 * j], ah, blv);
                MMA_TF32(sacc[2 * j], al_, bhv);
                bhv[0] = h2; bhv[1] = h3; blv[0] = s2; blv[1] = s3;
                MMA_TF32(sacc[2 * j + 1], ah, bhv);
                MMA_TF32(sacc[2 * j + 1], ah, blv);
                MMA_TF32(sacc[2 * j + 1], al_, bhv);
            }
        }

        // ---- online softmax (rows qr, qr+8 of warp band) ----
        float cm0 = -1e30f, cm1 = -1e30f;
#pragma unroll
        for (int ni = 0; ni < 8; ni++) {
            cm0 = fmaxf(cm0, fmaxf(sacc[ni][0], sacc[ni][1]));
            cm1 = fmaxf(cm1, fmaxf(sacc[ni][2], sacc[ni][3]));
        }
        cm0 = fmaxf(cm0, __shfl_xor_sync(0xffffffffu, cm0, 1));
        cm0 = fmaxf(cm0, __shfl_xor_sync(0xffffffffu, cm0, 2));
        cm1 = fmaxf(cm1, __shfl_xor_sync(0xffffffffu, cm1, 1));
        cm1 = fmaxf(cm1, __shfl_xor_sync(0xffffffffu, cm1, 2));

        float nm0 = fmaxf(m0, cm0), nm1 = fmaxf(m1, cm1);
        float a0 = __expf(m0 - nm0), a1 = __expf(m1 - nm1);
        float rs0 = 0.f, rs1 = 0.f;
        const uint32_t pr0 = PS + (uint32_t)((wid * 16 + qr) * 256);
        const uint32_t pr1 = PS + (uint32_t)((wid * 16 + qr + 8) * 256);
        const uint32_t sw0 = (uint32_t)((qr & 7) << 4);
        const uint32_t sw1 = (uint32_t)(((qr + 8) & 7) << 4);
#pragma unroll
        for (int ni = 0; ni < 8; ni++) {
            float p0 = __expf(sacc[ni][0] - nm0);
            float p1 = __expf(sacc[ni][1] - nm0);
            float p2 = __expf(sacc[ni][2] - nm1);
            float p3 = __expf(sacc[ni][3] - nm1);
            float q0 = to_tf32(p0), q1 = to_tf32(p1), q2 = to_tf32(p2), q3 = to_tf32(p3);
            rs0 += q0 + q1; rs1 += q2 + q3;
            uint32_t cb = (uint32_t)(ni * 32 + qc * 8);
            STSV2(pr0 + (cb ^ sw0), q0, q1);
            STSV2(pr1 + (cb ^ sw1), q2, q3);
        }
        rs0 += __shfl_xor_sync(0xffffffffu, rs0, 1);
        rs0 += __shfl_xor_sync(0xffffffffu, rs0, 2);
        rs1 += __shfl_xor_sync(0xffffffffu, rs1, 1);
        rs1 += __shfl_xor_sync(0xffffffffu, rs1, 2);
        m0 = nm0; m1 = nm1;
        l0 = l0 * a0 + rs0; l1 = l1 * a1 + rs1;
#pragma unroll
        for (int ni = 0; ni < 8; ni++) {
            oacc[ni][0] *= a0; oacc[ni][1] *= a0;
            oacc[ni][2] *= a1; oacc[ni][3] *= a1;
        }
        __syncwarp();

        // ---- O += P V ----
#pragma unroll
        for (int kk = 0; kk < 8; kk++) {
            uint32_t kb = (uint32_t)(kk * 32);
            uint32_t ap[4];
            LDSM4(ap[0], ap[1], ap[2], ap[3], PS + aBase + ((kb + aKsel) ^ swl));
            uint32_t bOff = (kb + bKsel) ^ swl;
#pragma unroll
            for (int j = 0; j < 4; j++) {
                uint32_t r0, r1, r2, r3;
                LDSM4(r0, r1, r2, r3, VS + (uint32_t)((bRow + j * 16) * 256) + bOff);
                uint32_t bv[2];
                bv[0] = r0; bv[1] = r1;
                MMA_TF32(oacc[2 * j], ap, bv);
                bv[0] = r2; bv[1] = r3;
                MMA_TF32(oacc[2 * j + 1], ap, bv);
            }
        }
    }

    // ---- normalize and store ----
    float inv0 = 1.f / l0, inv1 = 1.f / l1;
    long r0g = (long)(b * 1024 + qt * 64 + wid * 16 + qr) * 512 + h * 64;
    long r1g = r0g + 8 * 512;
#pragma unroll
    for (int ni = 0; ni < 8; ni++) {
        int col = ni * 8 + qc * 2;
        *(float2*)&g_out_hi[r0g + col] = make_float2(oacc[ni][0] * inv0, oacc[ni][1] * inv0);
        *(float2*)&g_out_hi[r1g + col] = make_float2(oacc[ni][2] * inv1, oacc[ni][3] * inv1);
    }
}

// ---------------- lo-branch windowed attention ----------------
__global__ void __launch_bounds__(256) lo_attn_kernel() {
    int gid  = blockIdx.x * blockDim.x + threadIdx.x;
    int warp = gid >> 5;
    int lane = gid & 31;
    int h = warp & 7;
    int w = (warp >> 3) & 1023;
    int b = warp >> 13;

    const float* base = g_qkv_lo + (long)((b * 1024 + w) * 4) * 1536 + h * 64 + 2 * lane;
    float2 q[4], k[4], v[4];
#pragma unroll
    for (int t = 0; t < 4; t++) {
        q[t] = *(const float2*)(base + (long)t * 1536);
        k[t] = *(const float2*)(base + (long)t * 1536 + 512);
        v[t] = *(const float2*)(base + (long)t * 1536 + 1024);
    }

    float lg[4][4];
#pragma unroll
    for (int ti = 0; ti < 4; ti++)
#pragma unroll
        for (int tj = 0; tj < 4; tj++) {
            float p = q[ti].x * k[tj].x + q[ti].y * k[tj].y;
            p += __shfl_xor_sync(0xffffffffu, p, 16);
            p += __shfl_xor_sync(0xffffffffu, p, 8);
            p += __shfl_xor_sync(0xffffffffu, p, 4);
            p += __shfl_xor_sync(0xffffffffu, p, 2);
            p += __shfl_xor_sync(0xffffffffu, p, 1);
            lg[ti][tj] = p * SCALE;
        }

    int hh = w >> 5, wh = w & 31;
#pragma unroll
    for (int ti = 0; ti < 4; ti++) {
        float mx = fmaxf(fmaxf(lg[ti][0], lg[ti][1]), fmaxf(lg[ti][2], lg[ti][3]));
        float e0 = __expf(lg[ti][0] - mx);
        float e1 = __expf(lg[ti][1] - mx);
        float e2 = __expf(lg[ti][2] - mx);
        float e3 = __expf(lg[ti][3] - mx);
        float is = 1.f / (e0 + e1 + e2 + e3);
        float ox = (e0 * v[0].x + e1 * v[1].x + e2 * v[2].x + e3 * v[3].x) * is;
        float oy = (e0 * v[0].y + e1 * v[1].y + e2 * v[2].y + e3 * v[3].y) * is;
        int pos = (2 * hh + (ti >> 1)) * 64 + 2 * wh + (ti & 1);
        *(float2*)&g_comb[(long)(b * 4096 + pos) * 512 + h * 64 + 2 * lane] =
            make_float2(ox, oy);
    }
}

// ---------------- bilinear upsample 32->64 + add ----------------
__global__ void __launch_bounds__(128) upsample_add_kernel() {
    int blk = blockIdx.x;
    int b = blk >> 12;
    int p = blk & 4095;
    int y = p >> 6, xq = p & 63;

    float sy = 0.5f * y - 0.25f;
    int   y0 = (int)floorf(sy);
    float fy = sy - (float)y0;
    int   y1 = min(y0 + 1, 31); y0 = max(y0, 0);

    float sx = 0.5f * xq - 0.25f;
    int   x0 = (int)floorf(sx);
    float fx = sx - (float)x0;
    int   x1 = min(x0 + 1, 31); x0 = max(x0, 0);

    float w00 = (1.f - fy) * (1.f - fx), w01 = (1.f - fy) * fx;
    float w10 = fy * (1.f - fx),         w11 = fy * fx;

    int c = threadIdx.x * 4;
    long base = (long)b * 1024 * 512;
    float4 v00 = *(const float4*)&g_out_hi[base + (long)(y0 * 32 + x0) * 512 + c];
    float4 v01 = *(const float4*)&g_out_hi[base + (long)(y0 * 32 + x1) * 512 + c];
    float4 v10 = *(const float4*)&g_out_hi[base + (long)(y1 * 32 + x0) * 512 + c];
    float4 v11 = *(const float4*)&g_out_hi[base + (long)(y1 * 32 + x1) * 512 + c];

    float4* dst = (float4*)&g_comb[(long)(b * 4096 + p) * 512 + c];
    float4 d = *dst;
    d.x += w00 * v00.x + w01 * v01.x + w10 * v10.x + w11 * v11.x;
    d.y += w00 * v00.y + w01 * v01.y + w10 * v10.y + w11 * v11.y;
    d.z += w00 * v00.z + w01 * v01.z + w10 * v10.z + w11 * v11.z;
    d.w += w00 * v00.w + w01 * v01.w + w10 * v10.w + w11 * v11.w;
    *dst = d;
}

// ---------------- launch ----------------
extern "C" void kernel_launch(void* const* d_in, const int* in_sizes, int n_in,
                              void* d_out, int out_size) {
    const float* x     = (const float*)d_in[0];
    const float* Wqkv  = (const float*)d_in[1];
    const float* Wproj = (const float*)d_in[2];
    const float* bproj = (const float*)d_in[3];
    float* out = (float*)d_out;

    float *xhi, *qkvhi, *win, *qkvlo, *comb;
    cudaGetSymbolAddress((void**)&xhi,   g_xhi);
    cudaGetSymbolAddress((void**)&qkvhi, g_qkv_hi);
    cudaGetSymbolAddress((void**)&win,   g_win);
    cudaGetSymbolAddress((void**)&qkvlo, g_qkv_lo);
    cudaGetSymbolAddress((void**)&comb,  g_comb);

    cudaFuncSetAttribute(mma_gemm<false>, cudaFuncAttributeMaxDynamicSharedMemorySize, GEMM_SMEM);
    cudaFuncSetAttribute(mma_gemm<true>,  cudaFuncAttributeMaxDynamicSharedMemorySize, GEMM_SMEM);
    cudaFuncSetAttribute(flash_hi_tc,     cudaFuncAttributeMaxDynamicSharedMemorySize, FLASH_SMEM);

    // 1. fused avg-pool + window gather
    prep_kernel<<<16384, 256>>>(x);
    // 2. QKV GEMMs (tf32 mma.sync tensor cores)
    mma_gemm<false><<<dim3(12, 64),  256, GEMM_SMEM>>>(xhi, Wqkv, nullptr, qkvhi, 8192,  1536, 512);
    mma_gemm<false><<<dim3(12, 256), 256, GEMM_SMEM>>>(win, Wqkv, nullptr, qkvlo, 32768, 1536, 512);
    // 3. attentions
    flash_hi_tc<<<dim3(16, 64), 128, FLASH_SMEM>>>();
    lo_attn_kernel<<<8192, 256>>>();
    // 4. upsample hi-branch and add
    upsample_add_kernel<<<32768, 128>>>();
    // 5. output projection (+bias, tf32 mma.sync)
    mma_gemm<true><<<dim3(4, 256), 256, GEMM_SMEM>>>(comb, Wproj, bproj, out, 32768, 512, 512);
}

// round 5
// speedup vs baseline: 2.5976x; 1.0420x over previous
#include <cuda_runtime.h>
#include <math.h>
#include <stdint.h>

// ---------------- problem constants ----------------
#define B_    8
#define N_    4096      // tokens per batch (64x64)
#define C_    512
#define NH_   8         // heads
#define HD_   64        // head dim
#define SCALE 0.125f    // hd^-0.5

// ---------------- scratch (device globals; no allocation allowed) ----------------
__device__ float g_xhi   [B_*1024*C_];     //  16 MB  pooled tokens
__device__ float g_qkv_hi[B_*1024*3*C_];   //  50 MB
__device__ float g_out_hi[B_*1024*C_];     //  16 MB
__device__ float g_win   [B_*N_*C_];       //  64 MB  gathered window tokens
__device__ float g_qkv_lo[B_*N_*3*C_];     // 201 MB
__device__ float g_comb  [B_*N_*C_];       //  64 MB  out_lo + upsampled out_hi

// ======================= PTX helpers =======================
__device__ __forceinline__ uint32_t smem_u32(const void* p) {
    uint32_t a;
    asm("{ .reg .u64 t; cvta.to.shared.u64 t, %1; cvt.u32.u64 %0, t; }" : "=r"(a) : "l"(p));
    return a;
}
__device__ __forceinline__ float to_tf32(float x) {
    float r;
    asm("cvt.rna.tf32.f32 %0, %1;" : "=f"(r) : "f"(x));
    return r;
}

#define LDSM4(d0, d1, d2, d3, addr)                                            \
    asm volatile("ldmatrix.sync.aligned.m8n8.x4.shared.b16 {%0,%1,%2,%3}, [%4];" \
                 : "=r"(d0), "=r"(d1), "=r"(d2), "=r"(d3) : "r"(addr))

#define MMA_TF32(c, a, b)                                                      \
    asm volatile("mma.sync.aligned.m16n8k8.row.col.f32.tf32.tf32.f32 "         \
                 "{%0,%1,%2,%3}, {%4,%5,%6,%7}, {%8,%9}, {%0,%1,%2,%3};"       \
                 : "+f"((c)[0]), "+f"((c)[1]), "+f"((c)[2]), "+f"((c)[3])      \
                 : "r"((a)[0]), "r"((a)[1]), "r"((a)[2]), "r"((a)[3]),         \
                   "r"((b)[0]), "r"((b)[1]))

#define STSV4(addr, x, y, z, w)                                                \
    asm volatile("st.shared.v4.b32 [%0], {%1,%2,%3,%4};"                       \
                 :: "r"(addr), "f"(x), "f"(y), "f"(z), "f"(w) : "memory")
#define STSV2(addr, x, y)                                                      \
    asm volatile("st.shared.v2.b32 [%0], {%1,%2};"                             \
                 :: "r"(addr), "f"(x), "f"(y) : "memory")
#define STSB32(addr, x)                                                        \
    asm volatile("st.shared.b32 [%0], %1;" :: "r"(addr), "f"(x) : "memory")

// ======================= mma.sync tf32 GEMM (unchanged) =======================
#define GEMM_SMEM (1024 + 65536)

template <bool BIAS>
__global__ void __launch_bounds__(256, 1) mma_gemm(
    const float* __restrict__ A, const float* __restrict__ Bm,
    const float* __restrict__ bias, float* __restrict__ Cm,
    int M, int N, int K)
{
    extern __shared__ char dsm[];
    uint32_t sb = (smem_u32(dsm) + 1023u) & ~1023u;

    const int t = threadIdx.x;
    const int bm = blockIdx.y, bn = blockIdx.x;
    const int lane = t & 31, wid = t >> 5;
    const int warp_m = wid & 1, warp_n = wid >> 1;

    const int f4 = t & 7;
    const int row0 = t >> 3;
    const float* Ab = A  + (long)(bm * 128 + row0) * K + f4 * 4;
    const float* Bb = Bm + (long)(bn * 128 + row0) * K + f4 * 4;
    uint32_t stOff[4];
#pragma unroll
    for (int g = 0; g < 4; g++) {
        uint32_t off = (row0 + 32 * g) * 128 + f4 * 16;
        stOff[g] = off ^ ((off >> 3) & 0x70);
    }

    const int l = lane & 7, g8 = lane >> 3;
    const int aRow = warp_m * 64 + (g8 & 1) * 8 + l;
    const uint32_t aSw   = (uint32_t)((aRow & 7) << 4);
    const uint32_t aKoff = (uint32_t)((g8 >> 1) * 16);
    const int bRow = warp_n * 32 + (g8 >> 1) * 8 + l;
    const uint32_t bSw   = (uint32_t)((bRow & 7) << 4);
    const uint32_t bKoff = (uint32_t)((g8 & 1) * 16);

    float acc[4][4][4];
#pragma unroll
    for (int mi = 0; mi < 4; mi++)
#pragma unroll
        for (int ni = 0; ni < 4; ni++)
#pragma unroll
            for (int q = 0; q < 4; q++) acc[mi][ni][q] = 0.f;

    const int KC = K >> 5;
    float4 pa[4], pb[4];
#pragma unroll
    for (int g = 0; g < 4; g++) {
        pa[g] = *(const float4*)(Ab + (long)(g * 32) * K);
        pb[g] = *(const float4*)(Bb + (long)(g * 32) * K);
    }
    {
        uint32_t sA = sb, sB = sb + 16384;
#pragma unroll
        for (int g = 0; g < 4; g++) {
            STSV4(sA + stOff[g], to_tf32(pa[g].x), to_tf32(pa[g].y), to_tf32(pa[g].z), to_tf32(pa[g].w));
            STSV4(sB + stOff[g], to_tf32(pb[g].x), to_tf32(pb[g].y), to_tf32(pb[g].z), to_tf32(pb[g].w));
        }
    }
    __syncthreads();

    for (int c = 0; c < KC; c++) {
        if (c + 1 < KC) {
            const float* An = Ab + (c + 1) * 32;
            const float* Bn = Bb + (c + 1) * 32;
#pragma unroll
            for (int g = 0; g < 4; g++) {
                pa[g] = *(const float4*)(An + (long)(g * 32) * K);
                pb[g] = *(const float4*)(Bn + (long)(g * 32) * K);
            }
        }
        uint32_t bufA = sb + (c & 1) * 32768;
        uint32_t bufB = bufA + 16384;
#pragma unroll
        for (int kk = 0; kk < 4; kk++) {
            uint32_t aOff = ((uint32_t)(kk * 32) + aKoff) ^ aSw;
            uint32_t bOff = ((uint32_t)(kk * 32) + bKoff) ^ bSw;
            uint32_t af[4][4], bf[4][2];
#pragma unroll
            for (int mi = 0; mi < 4; mi++)
                LDSM4(af[mi][0], af[mi][1], af[mi][2], af[mi][3],
                      bufA + (uint32_t)((aRow + mi * 16) * 128) + aOff);
#pragma unroll
            for (int j = 0; j < 2; j++) {
                uint32_t r0, r1, r2, r3;
                LDSM4(r0, r1, r2, r3,
                      bufB + (uint32_t)((bRow + j * 16) * 128) + bOff);
                bf[2 * j][0] = r0;     bf[2 * j][1] = r1;
                bf[2 * j + 1][0] = r2; bf[2 * j + 1][1] = r3;
            }
#pragma unroll
            for (int mi = 0; mi < 4; mi++)
#pragma unroll
                for (int ni = 0; ni < 4; ni++)
                    MMA_TF32(acc[mi][ni], af[mi], bf[ni]);
        }
        if (c + 1 < KC) {
            uint32_t sA = sb + ((c + 1) & 1) * 32768;
            uint32_t sB = sA + 16384;
#pragma unroll
            for (int g = 0; g < 4; g++) {
                STSV4(sA + stOff[g], to_tf32(pa[g].x), to_tf32(pa[g].y), to_tf32(pa[g].z), to_tf32(pa[g].w));
                STSV4(sB + stOff[g], to_tf32(pb[g].x), to_tf32(pb[g].y), to_tf32(pb[g].z), to_tf32(pb[g].w));
            }
        }
        __syncthreads();
    }

    const int qr = lane >> 2, qc = lane & 3;
#pragma unroll
    for (int mi = 0; mi < 4; mi++) {
        int row = bm * 128 + warp_m * 64 + mi * 16 + qr;
#pragma unroll
        for (int ni = 0; ni < 4; ni++) {
            int col = bn * 128 + warp_n * 32 + ni * 8 + qc * 2;
            float bx = 0.f, by = 0.f;
            if (BIAS) { float2 b2 = *(const float2*)&bias[col]; bx = b2.x; by = b2.y; }
            *(float2*)&Cm[(long)row * N + col] =
                make_float2(acc[mi][ni][0] + bx, acc[mi][ni][1] + by);
            *(float2*)&Cm[(long)(row + 8) * N + col] =
                make_float2(acc[mi][ni][2] + bx, acc[mi][ni][3] + by);
        }
    }
}

// ---------------- prep: fused avg-pool + window gather ----------------
__global__ void prep_kernel(const float* __restrict__ x) {
    int id = blockIdx.x * blockDim.x + threadIdx.x;
    int ch = id & 511;
    int w  = (id >> 9) & 1023;
    int b  = id >> 19;
    int hh = w >> 5, wh = w & 31;

    int r0 = (b * 4096 + (2 * hh) * 64 + 2 * wh) * 512 + ch;
    float v00 = x[r0];
    float v01 = x[r0 + 512];
    float v10 = x[r0 + 64 * 512];
    float v11 = x[r0 + 65 * 512];

    g_xhi[(b * 1024 + w) * 512 + ch] = 0.25f * (v00 + v01 + v10 + v11);

    int t = ch >> 7;
    int c = (4 * ch) & 511;
    float4 f4 = make_float4(v00, v01, v10, v11);
    *(float4*)&g_win[(long)((b * 1024 + w) * 4 + t) * 512 + c] = f4;
}

// ======================= tensor-core hi-branch flash attention v2 =======================
// grid (8 q-tiles, 64 bh), 256 threads = 8 warps; warp w owns q-rows 16w..16w+15 (Br=128).
// KV tiles of 64 tokens, 16 iterations. QK^T 3xTF32 with Q fragments CACHED IN REGISTERS.
// smem: KH 16K | KL 16K | V^T 16K | P 32K  (Q staged through KH..KL region before loop)
#define FLASH_SMEM (80 * 1024 + 1024)

__global__ void __launch_bounds__(256, 1) flash_hi_tc() {
    extern __shared__ char fsm[];
    uint32_t sb = (smem_u32(fsm) + 1023u) & ~1023u;
    const uint32_t KH = sb, KL = sb + 16384, VS = sb + 32768, PS = sb + 49152;

    const int t = threadIdx.x, lane = t & 31, wid = t >> 5;
    const int qt = blockIdx.x, bh = blockIdx.y;
    const int b = bh >> 3, h = bh & 7;

    // ---- fragment geometry ----
    const int l7 = lane & 7, g8 = lane >> 3;
    const int aRow = wid * 16 + (g8 & 1) * 8 + l7;       // q / P rows (0..127)
    const uint32_t aKsel = (uint32_t)((g8 >> 1) * 16);
    const int bRow = (g8 >> 1) * 8 + l7;                 // + j*16
    const uint32_t bKsel = (uint32_t)((g8 & 1) * 16);
    const uint32_t swl = (uint32_t)(l7 << 4);
    const uint32_t aBase = (uint32_t)(aRow * 256);
    const int qr = lane >> 2, qc = lane & 3;

    // ---- load Q fragments into registers (hi pass, then lo pass) ----
    uint32_t qh[8][4], ql[8][4];
    {
        int row = t >> 1, hb = t & 1;
        const float* qg = g_qkv_hi + (long)(b * 1024 + qt * 128 + row) * 1536 + h * 64 + hb * 32;
        uint32_t rbase = (uint32_t)(row * 256);
        uint32_t rsw = (uint32_t)((row & 7) << 4);
        // hi pass: stage into KH..KL (32KB = 128 rows x 256B)
#pragma unroll
        for (int i = 0; i < 8; i++) {
            float4 v = *(const float4*)(qg + i * 4);
            v.x *= SCALE; v.y *= SCALE; v.z *= SCALE; v.w *= SCALE;
            uint32_t off = ((uint32_t)(hb * 128 + i * 16)) ^ rsw;
            STSV4(KH + rbase + off, to_tf32(v.x), to_tf32(v.y), to_tf32(v.z), to_tf32(v.w));
        }
        __syncthreads();
#pragma unroll
        for (int kk = 0; kk < 8; kk++)
            LDSM4(qh[kk][0], qh[kk][1], qh[kk][2], qh[kk][3],
                  KH + aBase + (((uint32_t)(kk * 32) + aKsel) ^ swl));
        __syncthreads();
        // lo pass
#pragma unroll
        for (int i = 0; i < 8; i++) {
            float4 v = *(const float4*)(qg + i * 4);
            v.x *= SCALE; v.y *= SCALE; v.z *= SCALE; v.w *= SCALE;
            float hx = to_tf32(v.x), hy = to_tf32(v.y), hz = to_tf32(v.z), hw = to_tf32(v.w);
            uint32_t off = ((uint32_t)(hb * 128 + i * 16)) ^ rsw;
            STSV4(KH + rbase + off, to_tf32(v.x - hx), to_tf32(v.y - hy),
                                    to_tf32(v.z - hz), to_tf32(v.w - hw));
        }
        __syncthreads();
#pragma unroll
        for (int kk = 0; kk < 8; kk++)
            LDSM4(ql[kk][0], ql[kk][1], ql[kk][2], ql[kk][3],
                  KH + aBase + (((uint32_t)(kk * 32) + aKsel) ^ swl));
    }

    float oacc[8][4];
#pragma unroll
    for (int ni = 0; ni < 8; ni++)
#pragma unroll
        for (int q = 0; q < 4; q++) oacc[ni][q] = 0.f;
    float m0 = -1e30f, m1 = -1e30f, l0 = 0.f, l1 = 0.f;

    for (int kt = 0; kt < 16; kt++) {
        __syncthreads();   // prior readers done (incl. Q-lo LDSM on first iter)
        // ---- stage K (hi/lo) and V (transposed): 256 threads, 64 tokens ----
        {
            int row = t >> 2, q4 = t & 3;
            const float* kg = g_qkv_hi + (long)(b * 1024 + kt * 64 + row) * 1536 + 512 + h * 64 + q4 * 16;
            const float* vg = kg + 512;
            uint32_t rbase = (uint32_t)(row * 256);
            uint32_t rsw = (uint32_t)((row & 7) << 4);
            uint32_t tokb = (uint32_t)(row * 4);
#pragma unroll
            for (int i = 0; i < 4; i++) {
                float4 kv = *(const float4*)(kg + i * 4);
                float hx = to_tf32(kv.x), hy = to_tf32(kv.y),
                      hz = to_tf32(kv.z), hw = to_tf32(kv.w);
                uint32_t off = ((uint32_t)(q4 * 64 + i * 16)) ^ rsw;
                STSV4(KH + rbase + off, hx, hy, hz, hw);
                STSV4(KL + rbase + off, to_tf32(kv.x - hx), to_tf32(kv.y - hy),
                                        to_tf32(kv.z - hz), to_tf32(kv.w - hw));
                float4 vv = *(const float4*)(vg + i * 4);
                int d0 = q4 * 16 + i * 4;
                STSB32(VS + (uint32_t)((d0 + 0) * 256) + (tokb ^ (uint32_t)(((d0 + 0) & 7) << 4)), to_tf32(vv.x));
                STSB32(VS + (uint32_t)((d0 + 1) * 256) + (tokb ^ (uint32_t)(((d0 + 1) & 7) << 4)), to_tf32(vv.y));
                STSB32(VS + (uint32_t)((d0 + 2) * 256) + (tokb ^ (uint32_t)(((d0 + 2) & 7) << 4)), to_tf32(vv.z));
                STSB32(VS + (uint32_t)((d0 + 3) * 256) + (tokb ^ (uint32_t)(((d0 + 3) & 7) << 4)), to_tf32(vv.w));
            }
        }
        __syncthreads();

        // ---- S = Q K^T (3xTF32, Q from registers) ----
        float sacc[8][4];
#pragma unroll
        for (int ni = 0; ni < 8; ni++)
#pragma unroll
            for (int q = 0; q < 4; q++) sacc[ni][q] = 0.f;

#pragma unroll
        for (int kk = 0; kk < 8; kk++) {
            uint32_t bOff = ((uint32_t)(kk * 32) + bKsel) ^ swl;
#pragma unroll
            for (int j = 0; j < 4; j++) {
                uint32_t rb = (uint32_t)((bRow + j * 16) * 256) + bOff;
                uint32_t h0, h1, h2, h3, s0, s1, s2, s3;
                LDSM4(h0, h1, h2, h3, KH + rb);
                LDSM4(s0, s1, s2, s3, KL + rb);
                uint32_t bhv[2], blv[2];
                bhv[0] = h0; bhv[1] = h1; blv[0] = s0; blv[1] = s1;
                MMA_TF32(sacc[2 * j], qh[kk], bhv);
                MMA_TF32(sacc[2 * j], qh[kk], blv);
                MMA_TF32(sacc[2 * j], ql[kk], bhv);
                bhv[0] = h2; bhv[1] = h3; blv[0] = s2; blv[1] = s3;
                MMA_TF32(sacc[2 * j + 1], qh[kk], bhv);
                MMA_TF32(sacc[2 * j + 1], qh[kk], blv);
                MMA_TF32(sacc[2 * j + 1], ql[kk], bhv);
            }
        }

        // ---- online softmax (rows qr, qr+8 of warp band) ----
        float cm0 = -1e30f, cm1 = -1e30f;
#pragma unroll
        for (int ni = 0; ni < 8; ni++) {
            cm0 = fmaxf(cm0, fmaxf(sacc[ni][0], sacc[ni][1]));
            cm1 = fmaxf(cm1, fmaxf(sacc[ni][2], sacc[ni][3]));
        }
        cm0 = fmaxf(cm0, __shfl_xor_sync(0xffffffffu, cm0, 1));
        cm0 = fmaxf(cm0, __shfl_xor_sync(0xffffffffu, cm0, 2));
        cm1 = fmaxf(cm1, __shfl_xor_sync(0xffffffffu, cm1, 1));
        cm1 = fmaxf(cm1, __shfl_xor_sync(0xffffffffu, cm1, 2));

        float nm0 = fmaxf(m0, cm0), nm1 = fmaxf(m1, cm1);
        float a0 = __expf(m0 - nm0), a1 = __expf(m1 - nm1);
        float rs0 = 0.f, rs1 = 0.f;
        const uint32_t pr0 = PS + (uint32_t)((wid * 16 + qr) * 256);
        const uint32_t pr1 = PS + (uint32_t)((wid * 16 + qr + 8) * 256);
        const uint32_t sw0 = (uint32_t)((qr & 7) << 4);
        const uint32_t sw1 = (uint32_t)(((qr + 8) & 7) << 4);
#pragma unroll
        for (int ni = 0; ni < 8; ni++) {
            float p0 = __expf(sacc[ni][0] - nm0);
            float p1 = __expf(sacc[ni][1] - nm0);
            float p2 = __expf(sacc[ni][2] - nm1);
            float p3 = __expf(sacc[ni][3] - nm1);
            float q0 = to_tf32(p0), q1 = to_tf32(p1), q2 = to_tf32(p2), q3 = to_tf32(p3);
            rs0 += q0 + q1; rs1 += q2 + q3;
            uint32_t cb = (uint32_t)(ni * 32 + qc * 8);
            STSV2(pr0 + (cb ^ sw0), q0, q1);
            STSV2(pr1 + (cb ^ sw1), q2, q3);
        }
        rs0 += __shfl_xor_sync(0xffffffffu, rs0, 1);
        rs0 += __shfl_xor_sync(0xffffffffu, rs0, 2);
        rs1 += __shfl_xor_sync(0xffffffffu, rs1, 1);
        rs1 += __shfl_xor_sync(0xffffffffu, rs1, 2);
        m0 = nm0; m1 = nm1;
        l0 = l0 * a0 + rs0; l1 = l1 * a1 + rs1;
#pragma unroll
        for (int ni = 0; ni < 8; ni++) {
            oacc[ni][0] *= a0; oacc[ni][1] *= a0;
            oacc[ni][2] *= a1; oacc[ni][3] *= a1;
        }
        __syncwarp();   // P rows are warp-private: warp-level ordering suffices

        // ---- O += P V ----
#pragma unroll
        for (int kk = 0; kk < 8; kk++) {
            uint32_t kb = (uint32_t)(kk * 32);
            uint32_t ap[4];
            LDSM4(ap[0], ap[1], ap[2], ap[3], PS + aBase + ((kb + aKsel) ^ swl));
            uint32_t bOff = (kb + bKsel) ^ swl;
#pragma unroll
            for (int j = 0; j < 4; j++) {
                uint32_t r0, r1, r2, r3;
                LDSM4(r0, r1, r2, r3, VS + (uint32_t)((bRow + j * 16) * 256) + bOff);
                uint32_t bv[2];
                bv[0] = r0; bv[1] = r1;
                MMA_TF32(oacc[2 * j], ap, bv);
                bv[0] = r2; bv[1] = r3;
                MMA_TF32(oacc[2 * j + 1], ap, bv);
            }
        }
    }

    // ---- normalize and store ----
    float inv0 = 1.f / l0, inv1 = 1.f / l1;
    long r0g = (long)(b * 1024 + qt * 128 + wid * 16 + qr) * 512 + h * 64;
    long r1g = r0g + 8 * 512;
#pragma unroll
    for (int ni = 0; ni < 8; ni++) {
        int col = ni * 8 + qc * 2;
        *(float2*)&g_out_hi[r0g + col] = make_float2(oacc[ni][0] * inv0, oacc[ni][1] * inv0);
        *(float2*)&g_out_hi[r1g + col] = make_float2(oacc[ni][2] * inv1, oacc[ni][3] * inv1);
    }
}

// ---------------- lo-branch windowed attention + fused hi upsample-add ----------------
__global__ void __launch_bounds__(256) lo_attn_kernel() {
    int gid  = blockIdx.x * blockDim.x + threadIdx.x;
    int warp = gid >> 5;
    int lane = gid & 31;
    int h = warp & 7;
    int w = (warp >> 3) & 1023;
    int b = warp >> 13;

    const float* base = g_qkv_lo + (long)((b * 1024 + w) * 4) * 1536 + h * 64 + 2 * lane;
    float2 q[4], k[4], v[4];
#pragma unroll
    for (int t = 0; t < 4; t++) {
        q[t] = *(const float2*)(base + (long)t * 1536);
        k[t] = *(const float2*)(base + (long)t * 1536 + 512);
        v[t] = *(const float2*)(base + (long)t * 1536 + 1024);
    }

    float lg[4][4];
#pragma unroll
    for (int ti = 0; ti < 4; ti++)
#pragma unroll
        for (int tj = 0; tj < 4; tj++) {
            float p = q[ti].x * k[tj].x + q[ti].y * k[tj].y;
            p += __shfl_xor_sync(0xffffffffu, p, 16);
            p += __shfl_xor_sync(0xffffffffu, p, 8);
            p += __shfl_xor_sync(0xffffffffu, p, 4);
            p += __shfl_xor_sync(0xffffffffu, p, 2);
            p += __shfl_xor_sync(0xffffffffu, p, 1);
            lg[ti][tj] = p * SCALE;
        }

    int hh = w >> 5, wh = w & 31;
    long hibase = (long)b * 1024 * 512;
    int ccol = h * 64 + 2 * lane;
#pragma unroll
    for (int ti = 0; ti < 4; ti++) {
        float mx = fmaxf(fmaxf(lg[ti][0], lg[ti][1]), fmaxf(lg[ti][2], lg[ti][3]));
        float e0 = __expf(lg[ti][0] - mx);
        float e1 = __expf(lg[ti][1] - mx);
        float e2 = __expf(lg[ti][2] - mx);
        float e3 = __expf(lg[ti][3] - mx);
        float is = 1.f / (e0 + e1 + e2 + e3);
        float ox = (e0 * v[0].x + e1 * v[1].x + e2 * v[2].x + e3 * v[3].x) * is;
        float oy = (e0 * v[0].y + e1 * v[1].y + e2 * v[2].y + e3 * v[3].y) * is;

        // fused bilinear upsample of hi branch (half-pixel, 32->64)
        int y  = 2 * hh + (ti >> 1);
        int xq = 2 * wh + (ti & 1);
        float sy = 0.5f * y - 0.25f;
        int   y0 = (int)floorf(sy);
        float fy = sy - (float)y0;
        int   y1 = min(y0 + 1, 31); y0 = max(y0, 0);
        float sx = 0.5f * xq - 0.25f;
        int   x0 = (int)floorf(sx);
        float fx = sx - (float)x0;
        int   x1 = min(x0 + 1, 31); x0 = max(x0, 0);
        float w00 = (1.f - fy) * (1.f - fx), w01 = (1.f - fy) * fx;
        float w10 = fy * (1.f - fx),         w11 = fy * fx;

        float2 v00 = *(const float2*)&g_out_hi[hibase + (long)(y0 * 32 + x0) * 512 + ccol];
        float2 v01 = *(const float2*)&g_out_hi[hibase + (long)(y0 * 32 + x1) * 512 + ccol];
        float2 v10 = *(const float2*)&g_out_hi[hibase + (long)(y1 * 32 + x0) * 512 + ccol];
        float2 v11 = *(const float2*)&g_out_hi[hibase + (long)(y1 * 32 + x1) * 512 + ccol];
        float hx = w00 * v00.x + w01 * v01.x + w10 * v10.x + w11 * v11.x;
        float hy = w00 * v00.y + w01 * v01.y + w10 * v10.y + w11 * v11.y;

        int pos = y * 64 + xq;
        *(float2*)&g_comb[(long)(b * 4096 + pos) * 512 + ccol] =
            make_float2(ox + hx, oy + hy);
    }
}

// ---------------- launch ----------------
extern "C" void kernel_launch(void* const* d_in, const int* in_sizes, int n_in,
                              void* d_out, int out_size) {
    const float* x     = (const float*)d_in[0];
    const float* Wqkv  = (const float*)d_in[1];
    const float* Wproj = (const float*)d_in[2];
    const float* bproj = (const float*)d_in[3];
    float* out = (float*)d_out;

    float *xhi, *qkvhi, *win, *qkvlo, *comb;
    cudaGetSymbolAddress((void**)&xhi,   g_xhi);
    cudaGetSymbolAddress((void**)&qkvhi, g_qkv_hi);
    cudaGetSymbolAddress((void**)&win,   g_win);
    cudaGetSymbolAddress((void**)&qkvlo, g_qkv_lo);
    cudaGetSymbolAddress((void**)&comb,  g_comb);

    cudaFuncSetAttribute(mma_gemm<false>, cudaFuncAttributeMaxDynamicSharedMemorySize, GEMM_SMEM);
    cudaFuncSetAttribute(mma_gemm<true>,  cudaFuncAttributeMaxDynamicSharedMemorySize, GEMM_SMEM);
    cudaFuncSetAttribute(flash_hi_tc,     cudaFuncAttributeMaxDynamicSharedMemorySize, FLASH_SMEM);

    // 1. fused avg-pool + window gather
    prep_kernel<<<16384, 256>>>(x);
    // 2. QKV GEMMs (tf32 mma.sync tensor cores)
    mma_gemm<false><<<dim3(12, 64),  256, GEMM_SMEM>>>(xhi, Wqkv, nullptr, qkvhi, 8192,  1536, 512);
    mma_gemm<false><<<dim3(12, 256), 256, GEMM_SMEM>>>(win, Wqkv, nullptr, qkvlo, 32768, 1536, 512);
    // 3. hi attention (tensor core flash), then lo attention fused with upsample-add
    flash_hi_tc<<<dim3(8, 64), 256, FLASH_SMEM>>>();
    lo_attn_kernel<<<8192, 256>>>();
    // 4. output projection (+bias, tf32 mma.sync)
    mma_gemm<true><<<dim3(4, 256), 256, GEMM_SMEM>>>(comb, Wproj, bproj, out, 32768, 512, 512);
}

// round 6
// speedup vs baseline: 2.6143x; 1.0064x over previous
#include <cuda_runtime.h>
#include <math.h>
#include <stdint.h>

// ---------------- problem constants ----------------
#define B_    8
#define N_    4096      // tokens per batch (64x64)
#define C_    512
#define NH_   8         // heads
#define HD_   64        // head dim
#define SCALE 0.125f    // hd^-0.5

// ---------------- scratch (device globals; no allocation allowed) ----------------
__device__ float g_xhi   [B_*1024*C_];     //  16 MB  pooled tokens
__device__ float g_qkv_hi[B_*1024*3*C_];   //  50 MB
__device__ float g_out_hi[B_*1024*C_];     //  16 MB
__device__ float g_win   [B_*N_*C_];       //  64 MB  gathered window tokens
__device__ float g_qkv_lo[B_*N_*3*C_];     // 201 MB
__device__ float g_comb  [B_*N_*C_];       //  64 MB  out_lo + upsampled out_hi

// ======================= PTX helpers =======================
__device__ __forceinline__ uint32_t smem_u32(const void* p) {
    uint32_t a;
    asm("{ .reg .u64 t; cvta.to.shared.u64 t, %1; cvt.u32.u64 %0, t; }" : "=r"(a) : "l"(p));
    return a;
}
__device__ __forceinline__ float to_tf32(float x) {
    float r;
    asm("cvt.rna.tf32.f32 %0, %1;" : "=f"(r) : "f"(x));
    return r;
}

#define LDSM4(d0, d1, d2, d3, addr)                                            \
    asm volatile("ldmatrix.sync.aligned.m8n8.x4.shared.b16 {%0,%1,%2,%3}, [%4];" \
                 : "=r"(d0), "=r"(d1), "=r"(d2), "=r"(d3) : "r"(addr))

#define MMA_TF32(c, a, b)                                                      \
    asm volatile("mma.sync.aligned.m16n8k8.row.col.f32.tf32.tf32.f32 "         \
                 "{%0,%1,%2,%3}, {%4,%5,%6,%7}, {%8,%9}, {%0,%1,%2,%3};"       \
                 : "+f"((c)[0]), "+f"((c)[1]), "+f"((c)[2]), "+f"((c)[3])      \
                 : "r"((a)[0]), "r"((a)[1]), "r"((a)[2]), "r"((a)[3]),         \
                   "r"((b)[0]), "r"((b)[1]))

#define STSV4(addr, x, y, z, w)                                                \
    asm volatile("st.shared.v4.b32 [%0], {%1,%2,%3,%4};"                       \
                 :: "r"(addr), "f"(x), "f"(y), "f"(z), "f"(w) : "memory")
#define STSV2(addr, x, y)                                                      \
    asm volatile("st.shared.v2.b32 [%0], {%1,%2};"                             \
                 :: "r"(addr), "f"(x), "f"(y) : "memory")
#define STSB32(addr, x)                                                        \
    asm volatile("st.shared.b32 [%0], %1;" :: "r"(addr), "f"(x) : "memory")
#define LDSV4(x, y, z, w, addr)                                                \
    asm volatile("ld.shared.v4.b32 {%0,%1,%2,%3}, [%4];"                       \
                 : "=f"(x), "=f"(y), "=f"(z), "=f"(w) : "r"(addr))
#define CP_ASYNC16(dst, src)                                                   \
    asm volatile("cp.async.cg.shared.global [%0], [%1], 16;"                   \
                 :: "r"(dst), "l"(src) : "memory")
#define CP_COMMIT()  asm volatile("cp.async.commit_group;" ::: "memory")
#define CP_WAIT0()   asm volatile("cp.async.wait_group 0;" ::: "memory")

// ======================= mma.sync tf32 GEMM (unchanged) =======================
#define GEMM_SMEM (1024 + 65536)

template <bool BIAS>
__global__ void __launch_bounds__(256, 1) mma_gemm(
    const float* __restrict__ A, const float* __restrict__ Bm,
    const float* __restrict__ bias, float* __restrict__ Cm,
    int M, int N, int K)
{
    extern __shared__ char dsm[];
    uint32_t sb = (smem_u32(dsm) + 1023u) & ~1023u;

    const int t = threadIdx.x;
    const int bm = blockIdx.y, bn = blockIdx.x;
    const int lane = t & 31, wid = t >> 5;
    const int warp_m = wid & 1, warp_n = wid >> 1;

    const int f4 = t & 7;
    const int row0 = t >> 3;
    const float* Ab = A  + (long)(bm * 128 + row0) * K + f4 * 4;
    const float* Bb = Bm + (long)(bn * 128 + row0) * K + f4 * 4;
    uint32_t stOff[4];
#pragma unroll
    for (int g = 0; g < 4; g++) {
        uint32_t off = (row0 + 32 * g) * 128 + f4 * 16;
        stOff[g] = off ^ ((off >> 3) & 0x70);
    }

    const int l = lane & 7, g8 = lane >> 3;
    const int aRow = warp_m * 64 + (g8 & 1) * 8 + l;
    const uint32_t aSw   = (uint32_t)((aRow & 7) << 4);
    const uint32_t aKoff = (uint32_t)((g8 >> 1) * 16);
    const int bRow = warp_n * 32 + (g8 >> 1) * 8 + l;
    const uint32_t bSw   = (uint32_t)((bRow & 7) << 4);
    const uint32_t bKoff = (uint32_t)((g8 & 1) * 16);

    float acc[4][4][4];
#pragma unroll
    for (int mi = 0; mi < 4; mi++)
#pragma unroll
        for (int ni = 0; ni < 4; ni++)
#pragma unroll
            for (int q = 0; q < 4; q++) acc[mi][ni][q] = 0.f;

    const int KC = K >> 5;
    float4 pa[4], pb[4];
#pragma unroll
    for (int g = 0; g < 4; g++) {
        pa[g] = *(const float4*)(Ab + (long)(g * 32) * K);
        pb[g] = *(const float4*)(Bb + (long)(g * 32) * K);
    }
    {
        uint32_t sA = sb, sB = sb + 16384;
#pragma unroll
        for (int g = 0; g < 4; g++) {
            STSV4(sA + stOff[g], to_tf32(pa[g].x), to_tf32(pa[g].y), to_tf32(pa[g].z), to_tf32(pa[g].w));
            STSV4(sB + stOff[g], to_tf32(pb[g].x), to_tf32(pb[g].y), to_tf32(pb[g].z), to_tf32(pb[g].w));
        }
    }
    __syncthreads();

    for (int c = 0; c < KC; c++) {
        if (c + 1 < KC) {
            const float* An = Ab + (c + 1) * 32;
            const float* Bn = Bb + (c + 1) * 32;
#pragma unroll
            for (int g = 0; g < 4; g++) {
                pa[g] = *(const float4*)(An + (long)(g * 32) * K);
                pb[g] = *(const float4*)(Bn + (long)(g * 32) * K);
            }
        }
        uint32_t bufA = sb + (c & 1) * 32768;
        uint32_t bufB = bufA + 16384;
#pragma unroll
        for (int kk = 0; kk < 4; kk++) {
            uint32_t aOff = ((uint32_t)(kk * 32) + aKoff) ^ aSw;
            uint32_t bOff = ((uint32_t)(kk * 32) + bKoff) ^ bSw;
            uint32_t af[4][4], bf[4][2];
#pragma unroll
            for (int mi = 0; mi < 4; mi++)
                LDSM4(af[mi][0], af[mi][1], af[mi][2], af[mi][3],
                      bufA + (uint32_t)((aRow + mi * 16) * 128) + aOff);
#pragma unroll
            for (int j = 0; j < 2; j++) {
                uint32_t r0, r1, r2, r3;
                LDSM4(r0, r1, r2, r3,
                      bufB + (uint32_t)((bRow + j * 16) * 128) + bOff);
                bf[2 * j][0] = r0;     bf[2 * j][1] = r1;
                bf[2 * j + 1][0] = r2; bf[2 * j + 1][1] = r3;
            }
#pragma unroll
            for (int mi = 0; mi < 4; mi++)
#pragma unroll
                for (int ni = 0; ni < 4; ni++)
                    MMA_TF32(acc[mi][ni], af[mi], bf[ni]);
        }
        if (c + 1 < KC) {
            uint32_t sA = sb + ((c + 1) & 1) * 32768;
            uint32_t sB = sA + 16384;
#pragma unroll
            for (int g = 0; g < 4; g++) {
                STSV4(sA + stOff[g], to_tf32(pa[g].x), to_tf32(pa[g].y), to_tf32(pa[g].z), to_tf32(pa[g].w));
                STSV4(sB + stOff[g], to_tf32(pb[g].x), to_tf32(pb[g].y), to_tf32(pb[g].z), to_tf32(pb[g].w));
            }
        }
        __syncthreads();
    }

    const int qr = lane >> 2, qc = lane & 3;
#pragma unroll
    for (int mi = 0; mi < 4; mi++) {
        int row = bm * 128 + warp_m * 64 + mi * 16 + qr;
#pragma unroll
        for (int ni = 0; ni < 4; ni++) {
            int col = bn * 128 + warp_n * 32 + ni * 8 + qc * 2;
            float bx = 0.f, by = 0.f;
            if (BIAS) { float2 b2 = *(const float2*)&bias[col]; bx = b2.x; by = b2.y; }
            *(float2*)&Cm[(long)row * N + col] =
                make_float2(acc[mi][ni][0] + bx, acc[mi][ni][1] + by);
            *(float2*)&Cm[(long)(row + 8) * N + col] =
                make_float2(acc[mi][ni][2] + bx, acc[mi][ni][3] + by);
        }
    }
}

// ---------------- prep: fused avg-pool + window gather ----------------
__global__ void prep_kernel(const float* __restrict__ x) {
    int id = blockIdx.x * blockDim.x + threadIdx.x;
    int ch = id & 511;
    int w  = (id >> 9) & 1023;
    int b  = id >> 19;
    int hh = w >> 5, wh = w & 31;

    int r0 = (b * 4096 + (2 * hh) * 64 + 2 * wh) * 512 + ch;
    float v00 = x[r0];
    float v01 = x[r0 + 512];
    float v10 = x[r0 + 64 * 512];
    float v11 = x[r0 + 65 * 512];

    g_xhi[(b * 1024 + w) * 512 + ch] = 0.25f * (v00 + v01 + v10 + v11);

    int t = ch >> 7;
    int c = (4 * ch) & 511;
    float4 f4 = make_float4(v00, v01, v10, v11);
    *(float4*)&g_win[(long)((b * 1024 + w) * 4 + t) * 512 + c] = f4;
}

// ======================= tensor-core hi-branch flash attention v3 =======================
// grid (8 q-tiles, 64 bh), 256 threads = 8 warps; warp w owns q-rows 16w..16w+15 (Br=128).
// KV tiles of 64 tokens, 16 iterations, cp.async pipelined raw staging.
// smem: KH 16K | KL 16K | V^T 16K | P 32K | rawK 17408 | rawV 17408
#define RAWK_OFF 81920
#define RAWV_OFF (81920 + 17408)
#define FLASH_SMEM (81920 + 2 * 17408 + 1024)

__global__ void __launch_bounds__(256, 1) flash_hi_tc() {
    extern __shared__ char fsm[];
    uint32_t sb = (smem_u32(fsm) + 1023u) & ~1023u;
    const uint32_t KH = sb, KL = sb + 16384, VS = sb + 32768, PS = sb + 49152;
    const uint32_t RK = sb + RAWK_OFF, RV = sb + RAWV_OFF;

    const int t = threadIdx.x, lane = t & 31, wid = t >> 5;
    const int qt = blockIdx.x, bh = blockIdx.y;
    const int b = bh >> 3, h = bh & 7;

    // staging geometry
    const int krow = t >> 2, kq4 = t & 3;           // K: 64 rows x 4 chunks
    const int vtok = t & 63, vdb = (t >> 6) * 16;   // V: 64 toks x 16-d blocks
    const uint32_t rkd = RK + (uint32_t)(krow * 272 + kq4 * 64);
    const uint32_t rvd = RV + (uint32_t)(vtok * 272 + vdb * 4);
    const float* kv_base = g_qkv_hi + (long)(b * 1024) * 1536 + 512 + h * 64;

    // issue tile 0 copy
    {
        const float* kg = kv_base + (long)krow * 1536 + kq4 * 16;
        const float* vg = kv_base + (long)vtok * 1536 + 512 + vdb;
#pragma unroll
        for (int i = 0; i < 4; i++) {
            CP_ASYNC16(rkd + i * 16, kg + i * 4);
            CP_ASYNC16(rvd + i * 16, vg + i * 4);
        }
        CP_COMMIT();
    }

    // ---- fragment geometry ----
    const int l7 = lane & 7, g8 = lane >> 3;
    const int aRow = wid * 16 + (g8 & 1) * 8 + l7;
    const uint32_t aKsel = (uint32_t)((g8 >> 1) * 16);
    const int bRow = (g8 >> 1) * 8 + l7;
    const uint32_t bKsel = (uint32_t)((g8 & 1) * 16);
    const uint32_t swl = (uint32_t)(l7 << 4);
    const uint32_t aBase = (uint32_t)(aRow * 256);
    const int qr = lane >> 2, qc = lane & 3;

    // ---- load Q fragments into registers (hi pass, then lo pass; KH..KL as scratch) ----
    uint32_t qh[8][4], ql[8][4];
    {
        int row = t >> 1, hb = t & 1;
        const float* qg = g_qkv_hi + (long)(b * 1024 + qt * 128 + row) * 1536 + h * 64 + hb * 32;
        uint32_t rbase = (uint32_t)(row * 256);
        uint32_t rsw = (uint32_t)((row & 7) << 4);
#pragma unroll
        for (int i = 0; i < 8; i++) {
            float4 v = *(const float4*)(qg + i * 4);
            v.x *= SCALE; v.y *= SCALE; v.z *= SCALE; v.w *= SCALE;
            uint32_t off = ((uint32_t)(hb * 128 + i * 16)) ^ rsw;
            STSV4(KH + rbase + off, to_tf32(v.x), to_tf32(v.y), to_tf32(v.z), to_tf32(v.w));
        }
        __syncthreads();
#pragma unroll
        for (int kk = 0; kk < 8; kk++)
            LDSM4(qh[kk][0], qh[kk][1], qh[kk][2], qh[kk][3],
                  KH + aBase + (((uint32_t)(kk * 32) + aKsel) ^ swl));
        __syncthreads();
#pragma unroll
        for (int i = 0; i < 8; i++) {
            float4 v = *(const float4*)(qg + i * 4);
            v.x *= SCALE; v.y *= SCALE; v.z *= SCALE; v.w *= SCALE;
            float hx = to_tf32(v.x), hy = to_tf32(v.y), hz = to_tf32(v.z), hw = to_tf32(v.w);
            uint32_t off = ((uint32_t)(hb * 128 + i * 16)) ^ rsw;
            STSV4(KH + rbase + off, to_tf32(v.x - hx), to_tf32(v.y - hy),
                                    to_tf32(v.z - hz), to_tf32(v.w - hw));
        }
        __syncthreads();
#pragma unroll
        for (int kk = 0; kk < 8; kk++)
            LDSM4(ql[kk][0], ql[kk][1], ql[kk][2], ql[kk][3],
                  KH + aBase + (((uint32_t)(kk * 32) + aKsel) ^ swl));
    }

    float oacc[8][4];
#pragma unroll
    for (int ni = 0; ni < 8; ni++)
#pragma unroll
        for (int q = 0; q < 4; q++) oacc[ni][q] = 0.f;
    float m0 = -1e30f, m1 = -1e30f, l0 = 0.f, l1 = 0.f;

    for (int kt = 0; kt < 16; kt++) {
        CP_WAIT0();
        __syncthreads();   // raw tile kt visible to all; prior readers of KH/KL/VS done

        // ---- convert raw -> KH/KL (hi/lo split) ----
        {
            uint32_t rbase = (uint32_t)(krow * 256);
            uint32_t rsw = (uint32_t)((krow & 7) << 4);
#pragma unroll
            for (int i = 0; i < 4; i++) {
                float x_, y_, z_, w_;
                LDSV4(x_, y_, z_, w_, rkd + i * 16);
                float hx = to_tf32(x_), hy = to_tf32(y_), hz = to_tf32(z_), hw = to_tf32(w_);
                uint32_t off = ((uint32_t)(kq4 * 64 + i * 16)) ^ rsw;
                STSV4(KH + rbase + off, hx, hy, hz, hw);
                STSV4(KL + rbase + off, to_tf32(x_ - hx), to_tf32(y_ - hy),
                                        to_tf32(z_ - hz), to_tf32(w_ - hw));
            }
        }
        // ---- convert raw V -> V^T (conflict-free: lane owns a distinct token) ----
        {
            uint32_t tokb = (uint32_t)(vtok * 4);
#pragma unroll
            for (int i = 0; i < 4; i++) {
                float x_, y_, z_, w_;
                LDSV4(x_, y_, z_, w_, rvd + i * 16);
                int d0 = vdb + i * 4;
                STSB32(VS + (uint32_t)((d0 + 0) * 256) + (tokb ^ (uint32_t)(((d0 + 0) & 7) << 4)), to_tf32(x_));
                STSB32(VS + (uint32_t)((d0 + 1) * 256) + (tokb ^ (uint32_t)(((d0 + 1) & 7) << 4)), to_tf32(y_));
                STSB32(VS + (uint32_t)((d0 + 2) * 256) + (tokb ^ (uint32_t)(((d0 + 2) & 7) << 4)), to_tf32(z_));
                STSB32(VS + (uint32_t)((d0 + 3) * 256) + (tokb ^ (uint32_t)(((d0 + 3) & 7) << 4)), to_tf32(w_));
            }
        }
        // ---- issue copy for tile kt+1 (lands during compute) ----
        if (kt + 1 < 16) {
            const float* kg = kv_base + (long)((kt + 1) * 64 + krow) * 1536 + kq4 * 16;
            const float* vg = kv_base + (long)((kt + 1) * 64 + vtok) * 1536 + 512 + vdb;
#pragma unroll
            for (int i = 0; i < 4; i++) {
                CP_ASYNC16(rkd + i * 16, kg + i * 4);
                CP_ASYNC16(rvd + i * 16, vg + i * 4);
            }
            CP_COMMIT();
        }
        __syncthreads();

        // ---- S = Q K^T (3xTF32, Q from registers, interleaved targets) ----
        float sacc[8][4];
#pragma unroll
        for (int ni = 0; ni < 8; ni++)
#pragma unroll
            for (int q = 0; q < 4; q++) sacc[ni][q] = 0.f;

#pragma unroll
        for (int kk = 0; kk < 8; kk++) {
            uint32_t bOff = ((uint32_t)(kk * 32) + bKsel) ^ swl;
#pragma unroll
            for (int j = 0; j < 4; j++) {
                uint32_t rb = (uint32_t)((bRow + j * 16) * 256) + bOff;
                uint32_t h0, h1, h2, h3, s0, s1, s2, s3;
                LDSM4(h0, h1, h2, h3, KH + rb);
                LDSM4(s0, s1, s2, s3, KL + rb);
                uint32_t bh0[2] = {h0, h1}, bh1[2] = {h2, h3};
                uint32_t bl0[2] = {s0, s1}, bl1[2] = {s2, s3};
                MMA_TF32(sacc[2 * j],     qh[kk], bh0);
                MMA_TF32(sacc[2 * j + 1], qh[kk], bh1);
                MMA_TF32(sacc[2 * j],     qh[kk], bl0);
                MMA_TF32(sacc[2 * j + 1], qh[kk], bl1);
                MMA_TF32(sacc[2 * j],     ql[kk], bh0);
                MMA_TF32(sacc[2 * j + 1], ql[kk], bh1);
            }
        }

        // ---- online softmax (rows qr, qr+8 of warp band) ----
        float cm0 = -1e30f, cm1 = -1e30f;
#pragma unroll
        for (int ni = 0; ni < 8; ni++) {
            cm0 = fmaxf(cm0, fmaxf(sacc[ni][0], sacc[ni][1]));
            cm1 = fmaxf(cm1, fmaxf(sacc[ni][2], sacc[ni][3]));
        }
        cm0 = fmaxf(cm0, __shfl_xor_sync(0xffffffffu, cm0, 1));
        cm0 = fmaxf(cm0, __shfl_xor_sync(0xffffffffu, cm0, 2));
        cm1 = fmaxf(cm1, __shfl_xor_sync(0xffffffffu, cm1, 1));
        cm1 = fmaxf(cm1, __shfl_xor_sync(0xffffffffu, cm1, 2));

        float nm0 = fmaxf(m0, cm0), nm1 = fmaxf(m1, cm1);
        float a0 = __expf(m0 - nm0), a1 = __expf(m1 - nm1);
        float rs0 = 0.f, rs1 = 0.f;
        const uint32_t pr0 = PS + (uint32_t)((wid * 16 + qr) * 256);
        const uint32_t pr1 = PS + (uint32_t)((wid * 16 + qr + 8) * 256);
        const uint32_t sw0 = (uint32_t)((qr & 7) << 4);
        const uint32_t sw1 = (uint32_t)(((qr + 8) & 7) << 4);
#pragma unroll
        for (int ni = 0; ni < 8; ni++) {
            float p0 = __expf(sacc[ni][0] - nm0);
            float p1 = __expf(sacc[ni][1] - nm0);
            float p2 = __expf(sacc[ni][2] - nm1);
            float p3 = __expf(sacc[ni][3] - nm1);
            float q0 = to_tf32(p0), q1 = to_tf32(p1), q2 = to_tf32(p2), q3 = to_tf32(p3);
            rs0 += q0 + q1; rs1 += q2 + q3;
            uint32_t cb = (uint32_t)(ni * 32 + qc * 8);
            STSV2(pr0 + (cb ^ sw0), q0, q1);
            STSV2(pr1 + (cb ^ sw1), q2, q3);
        }
        rs0 += __shfl_xor_sync(0xffffffffu, rs0, 1);
        rs0 += __shfl_xor_sync(0xffffffffu, rs0, 2);
        rs1 += __shfl_xor_sync(0xffffffffu, rs1, 1);
        rs1 += __shfl_xor_sync(0xffffffffu, rs1, 2);
        m0 = nm0; m1 = nm1;
        l0 = l0 * a0 + rs0; l1 = l1 * a1 + rs1;
#pragma unroll
        for (int ni = 0; ni < 8; ni++) {
            oacc[ni][0] *= a0; oacc[ni][1] *= a0;
            oacc[ni][2] *= a1; oacc[ni][3] *= a1;
        }
        __syncwarp();   // P rows are warp-private

        // ---- O += P V ----
#pragma unroll
        for (int kk = 0; kk < 8; kk++) {
            uint32_t kb = (uint32_t)(kk * 32);
            uint32_t ap[4];
            LDSM4(ap[0], ap[1], ap[2], ap[3], PS + aBase + ((kb + aKsel) ^ swl));
            uint32_t bOff = (kb + bKsel) ^ swl;
#pragma unroll
            for (int j = 0; j < 4; j++) {
                uint32_t r0, r1, r2, r3;
                LDSM4(r0, r1, r2, r3, VS + (uint32_t)((bRow + j * 16) * 256) + bOff);
                uint32_t bv0[2] = {r0, r1}, bv1[2] = {r2, r3};
                MMA_TF32(oacc[2 * j],     ap, bv0);
                MMA_TF32(oacc[2 * j + 1], ap, bv1);
            }
        }
    }

    // ---- normalize and store ----
    float inv0 = 1.f / l0, inv1 = 1.f / l1;
    long r0g = (long)(b * 1024 + qt * 128 + wid * 16 + qr) * 512 + h * 64;
    long r1g = r0g + 8 * 512;
#pragma unroll
    for (int ni = 0; ni < 8; ni++) {
        int col = ni * 8 + qc * 2;
        *(float2*)&g_out_hi[r0g + col] = make_float2(oacc[ni][0] * inv0, oacc[ni][1] * inv0);
        *(float2*)&g_out_hi[r1g + col] = make_float2(oacc[ni][2] * inv1, oacc[ni][3] * inv1);
    }
}

// ---------------- lo-branch windowed attention + fused hi upsample-add ----------------
__global__ void __launch_bounds__(256) lo_attn_kernel() {
    int gid  = blockIdx.x * blockDim.x + threadIdx.x;
    int warp = gid >> 5;
    int lane = gid & 31;
    int h = warp & 7;
    int w = (warp >> 3) & 1023;
    int b = warp >> 13;

    const float* base = g_qkv_lo + (long)((b * 1024 + w) * 4) * 1536 + h * 64 + 2 * lane;
    float2 q[4], k[4], v[4];
#pragma unroll
    for (int t = 0; t < 4; t++) {
        q[t] = *(const float2*)(base + (long)t * 1536);
        k[t] = *(const float2*)(base + (long)t * 1536 + 512);
        v[t] = *(const float2*)(base + (long)t * 1536 + 1024);
    }

    float lg[4][4];
#pragma unroll
    for (int ti = 0; ti < 4; ti++)
#pragma unroll
        for (int tj = 0; tj < 4; tj++) {
            float p = q[ti].x * k[tj].x + q[ti].y * k[tj].y;
            p += __shfl_xor_sync(0xffffffffu, p, 16);
            p += __shfl_xor_sync(0xffffffffu, p, 8);
            p += __shfl_xor_sync(0xffffffffu, p, 4);
            p += __shfl_xor_sync(0xffffffffu, p, 2);
            p += __shfl_xor_sync(0xffffffffu, p, 1);
            lg[ti][tj] = p * SCALE;
        }

    int hh = w >> 5, wh = w & 31;
    long hibase = (long)b * 1024 * 512;
    int ccol = h * 64 + 2 * lane;
#pragma unroll
    for (int ti = 0; ti < 4; ti++) {
        float mx = fmaxf(fmaxf(lg[ti][0], lg[ti][1]), fmaxf(lg[ti][2], lg[ti][3]));
        float e0 = __expf(lg[ti][0] - mx);
        float e1 = __expf(lg[ti][1] - mx);
        float e2 = __expf(lg[ti][2] - mx);
        float e3 = __expf(lg[ti][3] - mx);
        float is = 1.f / (e0 + e1 + e2 + e3);
        float ox = (e0 * v[0].x + e1 * v[1].x + e2 * v[2].x + e3 * v[3].x) * is;
        float oy = (e0 * v[0].y + e1 * v[1].y + e2 * v[2].y + e3 * v[3].y) * is;

        // fused bilinear upsample of hi branch (half-pixel, 32->64)
        int y  = 2 * hh + (ti >> 1);
        int xq = 2 * wh + (ti & 1);
        float sy = 0.5f * y - 0.25f;
        int   y0 = (int)floorf(sy);
        float fy = sy - (float)y0;
        int   y1 = min(y0 + 1, 31); y0 = max(y0, 0);
        float sx = 0.5f * xq - 0.25f;
        int   x0 = (int)floorf(sx);
        float fx = sx - (float)x0;
        int   x1 = min(x0 + 1, 31); x0 = max(x0, 0);
        float w00 = (1.f - fy) * (1.f - fx), w01 = (1.f - fy) * fx;
        float w10 = fy * (1.f - fx),         w11 = fy * fx;

        float2 v00 = *(const float2*)&g_out_hi[hibase + (long)(y0 * 32 + x0) * 512 + ccol];
        float2 v01 = *(const float2*)&g_out_hi[hibase + (long)(y0 * 32 + x1) * 512 + ccol];
        float2 v10 = *(const float2*)&g_out_hi[hibase + (long)(y1 * 32 + x0) * 512 + ccol];
        float2 v11 = *(const float2*)&g_out_hi[hibase + (long)(y1 * 32 + x1) * 512 + ccol];
        float hx = w00 * v00.x + w01 * v01.x + w10 * v10.x + w11 * v11.x;
        float hy = w00 * v00.y + w01 * v01.y + w10 * v10.y + w11 * v11.y;

        int pos = y * 64 + xq;
        *(float2*)&g_comb[(long)(b * 4096 + pos) * 512 + ccol] =
            make_float2(ox + hx, oy + hy);
    }
}

// ---------------- launch ----------------
extern "C" void kernel_launch(void* const* d_in, const int* in_sizes, int n_in,
                              void* d_out, int out_size) {
    const float* x     = (const float*)d_in[0];
    const float* Wqkv  = (const float*)d_in[1];
    const float* Wproj = (const float*)d_in[2];
    const float* bproj = (const float*)d_in[3];
    float* out = (float*)d_out;

    float *xhi, *qkvhi, *win, *qkvlo, *comb;
    cudaGetSymbolAddress((void**)&xhi,   g_xhi);
    cudaGetSymbolAddress((void**)&qkvhi, g_qkv_hi);
    cudaGetSymbolAddress((void**)&win,   g_win);
    cudaGetSymbolAddress((void**)&qkvlo, g_qkv_lo);
    cudaGetSymbolAddress((void**)&comb,  g_comb);

    cudaFuncSetAttribute(mma_gemm<false>, cudaFuncAttributeMaxDynamicSharedMemorySize, GEMM_SMEM);
    cudaFuncSetAttribute(mma_gemm<true>,  cudaFuncAttributeMaxDynamicSharedMemorySize, GEMM_SMEM);
    cudaFuncSetAttribute(flash_hi_tc,     cudaFuncAttributeMaxDynamicSharedMemorySize, FLASH_SMEM);

    // 1. fused avg-pool + window gather
    prep_kernel<<<16384, 256>>>(x);
    // 2. QKV GEMMs (tf32 mma.sync tensor cores)
    mma_gemm<false><<<dim3(12, 64),  256, GEMM_SMEM>>>(xhi, Wqkv, nullptr, qkvhi, 8192,  1536, 512);
    mma_gemm<false><<<dim3(12, 256), 256, GEMM_SMEM>>>(win, Wqkv, nullptr, qkvlo, 32768, 1536, 512);
    // 3. hi attention (tensor core flash), then lo attention fused with upsample-add
    flash_hi_tc<<<dim3(8, 64), 256, FLASH_SMEM>>>();
    lo_attn_kernel<<<8192, 256>>>();
    // 4. output projection (+bias, tf32 mma.sync)
    mma_gemm<true><<<dim3(4, 256), 256, GEMM_SMEM>>>(comb, Wproj, bproj, out, 32768, 512, 512);
}

// round 7
// speedup vs baseline: 2.8400x; 1.0864x over previous
#include <cuda_runtime.h>
#include <math.h>
#include <stdint.h>

// ---------------- problem constants ----------------
#define B_    8
#define N_    4096      // tokens per batch (64x64)
#define C_    512
#define NH_   8         // heads
#define HD_   64        // head dim
#define SCALE 0.125f    // hd^-0.5

// ---------------- scratch (device globals; no allocation allowed) ----------------
__device__ float g_xhi   [B_*1024*C_];     //  16 MB  pooled tokens
__device__ float g_qkv_hi[B_*1024*3*C_];   //  50 MB
__device__ float g_out_hi[B_*1024*C_];     //  16 MB
__device__ float g_win   [B_*N_*C_];       //  64 MB  gathered window tokens
__device__ float g_qkv_lo[B_*N_*3*C_];     // 201 MB
__device__ float g_comb  [B_*N_*C_];       //  64 MB  out_lo + upsampled out_hi

// ======================= PTX helpers =======================
__device__ __forceinline__ uint32_t smem_u32(const void* p) {
    uint32_t a;
    asm("{ .reg .u64 t; cvta.to.shared.u64 t, %1; cvt.u32.u64 %0, t; }" : "=r"(a) : "l"(p));
    return a;
}
__device__ __forceinline__ float to_tf32(float x) {
    float r;
    asm("cvt.rna.tf32.f32 %0, %1;" : "=f"(r) : "f"(x));
    return r;
}

#define LDSM4(d0, d1, d2, d3, addr)                                            \
    asm volatile("ldmatrix.sync.aligned.m8n8.x4.shared.b16 {%0,%1,%2,%3}, [%4];" \
                 : "=r"(d0), "=r"(d1), "=r"(d2), "=r"(d3) : "r"(addr))

#define MMA_TF32(c, a, b)                                                      \
    asm volatile("mma.sync.aligned.m16n8k8.row.col.f32.tf32.tf32.f32 "         \
                 "{%0,%1,%2,%3}, {%4,%5,%6,%7}, {%8,%9}, {%0,%1,%2,%3};"       \
                 : "+f"((c)[0]), "+f"((c)[1]), "+f"((c)[2]), "+f"((c)[3])      \
                 : "r"((a)[0]), "r"((a)[1]), "r"((a)[2]), "r"((a)[3]),         \
                   "r"((b)[0]), "r"((b)[1]))

#define STSV4(addr, x, y, z, w)                                                \
    asm volatile("st.shared.v4.b32 [%0], {%1,%2,%3,%4};"                       \
                 :: "r"(addr), "f"(x), "f"(y), "f"(z), "f"(w) : "memory")
#define STSV2(addr, x, y)                                                      \
    asm volatile("st.shared.v2.b32 [%0], {%1,%2};"                             \
                 :: "r"(addr), "f"(x), "f"(y) : "memory")
#define STSB32(addr, x)                                                        \
    asm volatile("st.shared.b32 [%0], %1;" :: "r"(addr), "f"(x) : "memory")
#define LDSV4(x, y, z, w, addr)                                                \
    asm volatile("ld.shared.v4.b32 {%0,%1,%2,%3}, [%4];"                       \
                 : "=f"(x), "=f"(y), "=f"(z), "=f"(w) : "r"(addr))
#define CP_ASYNC16(dst, src)                                                   \
    asm volatile("cp.async.cg.shared.global [%0], [%1], 16;"                   \
                 :: "r"(dst), "l"(src) : "memory")
#define CP_COMMIT()  asm volatile("cp.async.commit_group;" ::: "memory")
#define CP_WAIT0()   asm volatile("cp.async.wait_group 0;" ::: "memory")

// ======================= mma.sync tf32 GEMM (unchanged) =======================
#define GEMM_SMEM (1024 + 65536)

template <bool BIAS>
__global__ void __launch_bounds__(256, 1) mma_gemm(
    const float* __restrict__ A, const float* __restrict__ Bm,
    const float* __restrict__ bias, float* __restrict__ Cm,
    int M, int N, int K)
{
    extern __shared__ char dsm[];
    uint32_t sb = (smem_u32(dsm) + 1023u) & ~1023u;

    const int t = threadIdx.x;
    const int bm = blockIdx.y, bn = blockIdx.x;
    const int lane = t & 31, wid = t >> 5;
    const int warp_m = wid & 1, warp_n = wid >> 1;

    const int f4 = t & 7;
    const int row0 = t >> 3;
    const float* Ab = A  + (long)(bm * 128 + row0) * K + f4 * 4;
    const float* Bb = Bm + (long)(bn * 128 + row0) * K + f4 * 4;
    uint32_t stOff[4];
#pragma unroll
    for (int g = 0; g < 4; g++) {
        uint32_t off = (row0 + 32 * g) * 128 + f4 * 16;
        stOff[g] = off ^ ((off >> 3) & 0x70);
    }

    const int l = lane & 7, g8 = lane >> 3;
    const int aRow = warp_m * 64 + (g8 & 1) * 8 + l;
    const uint32_t aSw   = (uint32_t)((aRow & 7) << 4);
    const uint32_t aKoff = (uint32_t)((g8 >> 1) * 16);
    const int bRow = warp_n * 32 + (g8 >> 1) * 8 + l;
    const uint32_t bSw   = (uint32_t)((bRow & 7) << 4);
    const uint32_t bKoff = (uint32_t)((g8 & 1) * 16);

    float acc[4][4][4];
#pragma unroll
    for (int mi = 0; mi < 4; mi++)
#pragma unroll
        for (int ni = 0; ni < 4; ni++)
#pragma unroll
            for (int q = 0; q < 4; q++) acc[mi][ni][q] = 0.f;

    const int KC = K >> 5;
    float4 pa[4], pb[4];
#pragma unroll
    for (int g = 0; g < 4; g++) {
        pa[g] = *(const float4*)(Ab + (long)(g * 32) * K);
        pb[g] = *(const float4*)(Bb + (long)(g * 32) * K);
    }
    {
        uint32_t sA = sb, sB = sb + 16384;
#pragma unroll
        for (int g = 0; g < 4; g++) {
            STSV4(sA + stOff[g], to_tf32(pa[g].x), to_tf32(pa[g].y), to_tf32(pa[g].z), to_tf32(pa[g].w));
            STSV4(sB + stOff[g], to_tf32(pb[g].x), to_tf32(pb[g].y), to_tf32(pb[g].z), to_tf32(pb[g].w));
        }
    }
    __syncthreads();

    for (int c = 0; c < KC; c++) {
        if (c + 1 < KC) {
            const float* An = Ab + (c + 1) * 32;
            const float* Bn = Bb + (c + 1) * 32;
#pragma unroll
            for (int g = 0; g < 4; g++) {
                pa[g] = *(const float4*)(An + (long)(g * 32) * K);
                pb[g] = *(const float4*)(Bn + (long)(g * 32) * K);
            }
        }
        uint32_t bufA = sb + (c & 1) * 32768;
        uint32_t bufB = bufA + 16384;
#pragma unroll
        for (int kk = 0; kk < 4; kk++) {
            uint32_t aOff = ((uint32_t)(kk * 32) + aKoff) ^ aSw;
            uint32_t bOff = ((uint32_t)(kk * 32) + bKoff) ^ bSw;
            uint32_t af[4][4], bf[4][2];
#pragma unroll
            for (int mi = 0; mi < 4; mi++)
                LDSM4(af[mi][0], af[mi][1], af[mi][2], af[mi][3],
                      bufA + (uint32_t)((aRow + mi * 16) * 128) + aOff);
#pragma unroll
            for (int j = 0; j < 2; j++) {
                uint32_t r0, r1, r2, r3;
                LDSM4(r0, r1, r2, r3,
                      bufB + (uint32_t)((bRow + j * 16) * 128) + bOff);
                bf[2 * j][0] = r0;     bf[2 * j][1] = r1;
                bf[2 * j + 1][0] = r2; bf[2 * j + 1][1] = r3;
            }
#pragma unroll
            for (int mi = 0; mi < 4; mi++)
#pragma unroll
                for (int ni = 0; ni < 4; ni++)
                    MMA_TF32(acc[mi][ni], af[mi], bf[ni]);
        }
        if (c + 1 < KC) {
            uint32_t sA = sb + ((c + 1) & 1) * 32768;
            uint32_t sB = sA + 16384;
#pragma unroll
            for (int g = 0; g < 4; g++) {
                STSV4(sA + stOff[g], to_tf32(pa[g].x), to_tf32(pa[g].y), to_tf32(pa[g].z), to_tf32(pa[g].w));
                STSV4(sB + stOff[g], to_tf32(pb[g].x), to_tf32(pb[g].y), to_tf32(pb[g].z), to_tf32(pb[g].w));
            }
        }
        __syncthreads();
    }

    const int qr = lane >> 2, qc = lane & 3;
#pragma unroll
    for (int mi = 0; mi < 4; mi++) {
        int row = bm * 128 + warp_m * 64 + mi * 16 + qr;
#pragma unroll
        for (int ni = 0; ni < 4; ni++) {
            int col = bn * 128 + warp_n * 32 + ni * 8 + qc * 2;
            float bx = 0.f, by = 0.f;
            if (BIAS) { float2 b2 = *(const float2*)&bias[col]; bx = b2.x; by = b2.y; }
            *(float2*)&Cm[(long)row * N + col] =
                make_float2(acc[mi][ni][0] + bx, acc[mi][ni][1] + by);
            *(float2*)&Cm[(long)(row + 8) * N + col] =
                make_float2(acc[mi][ni][2] + bx, acc[mi][ni][3] + by);
        }
    }
}

// ---------------- prep: fused avg-pool + window gather ----------------
__global__ void prep_kernel(const float* __restrict__ x) {
    int id = blockIdx.x * blockDim.x + threadIdx.x;
    int ch = id & 511;
    int w  = (id >> 9) & 1023;
    int b  = id >> 19;
    int hh = w >> 5, wh = w & 31;

    int r0 = (b * 4096 + (2 * hh) * 64 + 2 * wh) * 512 + ch;
    float v00 = x[r0];
    float v01 = x[r0 + 512];
    float v10 = x[r0 + 64 * 512];
    float v11 = x[r0 + 65 * 512];

    g_xhi[(b * 1024 + w) * 512 + ch] = 0.25f * (v00 + v01 + v10 + v11);

    int t = ch >> 7;
    int c = (4 * ch) & 511;
    float4 f4 = make_float4(v00, v01, v10, v11);
    *(float4*)&g_win[(long)((b * 1024 + w) * 4 + t) * 512 + c] = f4;
}

// ======================= tensor-core hi-branch flash attention v4 =======================
// grid (8 q-tiles, 64 bh), 256 threads = 8 warps; warp w owns q-rows 16w..16w+15 (Br=128).
// KV tiles of 64 tokens, 16 iterations, cp.async pipelined raw staging.
// Single-pass tf32 QK (Q/K already carry tf32 GEMM error; extra rounding negligible).
// smem: KH 16K | V^T 16K | P 32K | rawK 17408 | rawV 17408
#define RAWK_OFF 65536
#define RAWV_OFF (65536 + 17408)
#define FLASH_SMEM (65536 + 2 * 17408 + 1024)

__global__ void __launch_bounds__(256, 1) flash_hi_tc() {
    extern __shared__ char fsm[];
    uint32_t sb = (smem_u32(fsm) + 1023u) & ~1023u;
    const uint32_t KH = sb, VS = sb + 16384, PS = sb + 32768;
    const uint32_t RK = sb + RAWK_OFF, RV = sb + RAWV_OFF;

    const int t = threadIdx.x, lane = t & 31, wid = t >> 5;
    const int qt = blockIdx.x, bh = blockIdx.y;
    const int b = bh >> 3, h = bh & 7;

    // staging geometry
    const int krow = t >> 2, kq4 = t & 3;           // K: 64 rows x 4 chunks
    const int vtok = t & 63, vdb = (t >> 6) * 16;   // V: 64 toks x 16-d blocks
    const uint32_t rkd = RK + (uint32_t)(krow * 272 + kq4 * 64);
    const uint32_t rvd = RV + (uint32_t)(vtok * 272 + vdb * 4);
    const float* kv_base = g_qkv_hi + (long)(b * 1024) * 1536 + 512 + h * 64;

    // issue tile 0 copy
    {
        const float* kg = kv_base + (long)krow * 1536 + kq4 * 16;
        const float* vg = kv_base + (long)vtok * 1536 + 512 + vdb;
#pragma unroll
        for (int i = 0; i < 4; i++) {
            CP_ASYNC16(rkd + i * 16, kg + i * 4);
            CP_ASYNC16(rvd + i * 16, vg + i * 4);
        }
        CP_COMMIT();
    }

    // ---- fragment geometry ----
    const int l7 = lane & 7, g8 = lane >> 3;
    const int aRow = wid * 16 + (g8 & 1) * 8 + l7;
    const uint32_t aKsel = (uint32_t)((g8 >> 1) * 16);
    const int bRow = (g8 >> 1) * 8 + l7;
    const uint32_t bKsel = (uint32_t)((g8 & 1) * 16);
    const uint32_t swl = (uint32_t)(l7 << 4);
    const uint32_t aBase = (uint32_t)(aRow * 256);
    const int qr = lane >> 2, qc = lane & 3;

    // ---- load Q fragments into registers (single tf32 pass; KH+VS as 32K scratch) ----
    uint32_t qh[8][4];
    {
        int row = t >> 1, hb = t & 1;
        const float* qg = g_qkv_hi + (long)(b * 1024 + qt * 128 + row) * 1536 + h * 64 + hb * 32;
        uint32_t rbase = (uint32_t)(row * 256);
        uint32_t rsw = (uint32_t)((row & 7) << 4);
#pragma unroll
        for (int i = 0; i < 8; i++) {
            float4 v = *(const float4*)(qg + i * 4);
            v.x *= SCALE; v.y *= SCALE; v.z *= SCALE; v.w *= SCALE;
            uint32_t off = ((uint32_t)(hb * 128 + i * 16)) ^ rsw;
            STSV4(KH + rbase + off, to_tf32(v.x), to_tf32(v.y), to_tf32(v.z), to_tf32(v.w));
        }
        __syncthreads();
#pragma unroll
        for (int kk = 0; kk < 8; kk++)
            LDSM4(qh[kk][0], qh[kk][1], qh[kk][2], qh[kk][3],
                  KH + aBase + (((uint32_t)(kk * 32) + aKsel) ^ swl));
    }

    float oacc[8][4];
#pragma unroll
    for (int ni = 0; ni < 8; ni++)
#pragma unroll
        for (int q = 0; q < 4; q++) oacc[ni][q] = 0.f;
    float m0 = -1e30f, m1 = -1e30f, l0 = 0.f, l1 = 0.f;

    for (int kt = 0; kt < 16; kt++) {
        CP_WAIT0();
        __syncthreads();   // raw tile kt visible; prior readers of KH/VS done (incl. Q LDSM)

        // ---- convert raw K -> KH ----
        {
            uint32_t rbase = (uint32_t)(krow * 256);
            uint32_t rsw = (uint32_t)((krow & 7) << 4);
#pragma unroll
            for (int i = 0; i < 4; i++) {
                float x_, y_, z_, w_;
                LDSV4(x_, y_, z_, w_, rkd + i * 16);
                uint32_t off = ((uint32_t)(kq4 * 64 + i * 16)) ^ rsw;
                STSV4(KH + rbase + off, to_tf32(x_), to_tf32(y_), to_tf32(z_), to_tf32(w_));
            }
        }
        // ---- convert raw V -> V^T (conflict-free: lane owns a distinct token) ----
        {
            uint32_t tokb = (uint32_t)(vtok * 4);
#pragma unroll
            for (int i = 0; i < 4; i++) {
                float x_, y_, z_, w_;
                LDSV4(x_, y_, z_, w_, rvd + i * 16);
                int d0 = vdb + i * 4;
                STSB32(VS + (uint32_t)((d0 + 0) * 256) + (tokb ^ (uint32_t)(((d0 + 0) & 7) << 4)), to_tf32(x_));
                STSB32(VS + (uint32_t)((d0 + 1) * 256) + (tokb ^ (uint32_t)(((d0 + 1) & 7) << 4)), to_tf32(y_));
                STSB32(VS + (uint32_t)((d0 + 2) * 256) + (tokb ^ (uint32_t)(((d0 + 2) & 7) << 4)), to_tf32(z_));
                STSB32(VS + (uint32_t)((d0 + 3) * 256) + (tokb ^ (uint32_t)(((d0 + 3) & 7) << 4)), to_tf32(w_));
            }
        }
        // ---- issue copy for tile kt+1 ----
        if (kt + 1 < 16) {
            const float* kg = kv_base + (long)((kt + 1) * 64 + krow) * 1536 + kq4 * 16;
            const float* vg = kv_base + (long)((kt + 1) * 64 + vtok) * 1536 + 512 + vdb;
#pragma unroll
            for (int i = 0; i < 4; i++) {
                CP_ASYNC16(rkd + i * 16, kg + i * 4);
                CP_ASYNC16(rvd + i * 16, vg + i * 4);
            }
            CP_COMMIT();
        }
        __syncthreads();

        // ---- S = Q K^T (single tf32, Q from registers) ----
        float sacc[8][4];
#pragma unroll
        for (int ni = 0; ni < 8; ni++)
#pragma unroll
            for (int q = 0; q < 4; q++) sacc[ni][q] = 0.f;

#pragma unroll
        for (int kk = 0; kk < 8; kk++) {
            uint32_t bOff = ((uint32_t)(kk * 32) + bKsel) ^ swl;
#pragma unroll
            for (int j = 0; j < 4; j++) {
                uint32_t r0, r1, r2, r3;
                LDSM4(r0, r1, r2, r3, KH + (uint32_t)((bRow + j * 16) * 256) + bOff);
                uint32_t bh0[2] = {r0, r1}, bh1[2] = {r2, r3};
                MMA_TF32(sacc[2 * j],     qh[kk], bh0);
                MMA_TF32(sacc[2 * j + 1], qh[kk], bh1);
            }
        }

        // ---- online softmax (rows qr, qr+8 of warp band) ----
        float cm0 = -1e30f, cm1 = -1e30f;
#pragma unroll
        for (int ni = 0; ni < 8; ni++) {
            cm0 = fmaxf(cm0, fmaxf(sacc[ni][0], sacc[ni][1]));
            cm1 = fmaxf(cm1, fmaxf(sacc[ni][2], sacc[ni][3]));
        }
        cm0 = fmaxf(cm0, __shfl_xor_sync(0xffffffffu, cm0, 1));
        cm0 = fmaxf(cm0, __shfl_xor_sync(0xffffffffu, cm0, 2));
        cm1 = fmaxf(cm1, __shfl_xor_sync(0xffffffffu, cm1, 1));
        cm1 = fmaxf(cm1, __shfl_xor_sync(0xffffffffu, cm1, 2));

        float nm0 = fmaxf(m0, cm0), nm1 = fmaxf(m1, cm1);
        float a0 = __expf(m0 - nm0), a1 = __expf(m1 - nm1);
        float rs0 = 0.f, rs1 = 0.f;
        const uint32_t pr0 = PS + (uint32_t)((wid * 16 + qr) * 256);
        const uint32_t pr1 = PS + (uint32_t)((wid * 16 + qr + 8) * 256);
        const uint32_t sw0 = (uint32_t)((qr & 7) << 4);
        const uint32_t sw1 = (uint32_t)(((qr + 8) & 7) << 4);
#pragma unroll
        for (int ni = 0; ni < 8; ni++) {
            float p0 = __expf(sacc[ni][0] - nm0);
            float p1 = __expf(sacc[ni][1] - nm0);
            float p2 = __expf(sacc[ni][2] - nm1);
            float p3 = __expf(sacc[ni][3] - nm1);
            float q0 = to_tf32(p0), q1 = to_tf32(p1), q2 = to_tf32(p2), q3 = to_tf32(p3);
            rs0 += q0 + q1; rs1 += q2 + q3;
            uint32_t cb = (uint32_t)(ni * 32 + qc * 8);
            STSV2(pr0 + (cb ^ sw0), q0, q1);
            STSV2(pr1 + (cb ^ sw1), q2, q3);
        }
        rs0 += __shfl_xor_sync(0xffffffffu, rs0, 1);
        rs0 += __shfl_xor_sync(0xffffffffu, rs0, 2);
        rs1 += __shfl_xor_sync(0xffffffffu, rs1, 1);
        rs1 += __shfl_xor_sync(0xffffffffu, rs1, 2);
        m0 = nm0; m1 = nm1;
        l0 = l0 * a0 + rs0; l1 = l1 * a1 + rs1;
#pragma unroll
        for (int ni = 0; ni < 8; ni++) {
            oacc[ni][0] *= a0; oacc[ni][1] *= a0;
            oacc[ni][2] *= a1; oacc[ni][3] *= a1;
        }
        __syncwarp();   // P rows are warp-private

        // ---- O += P V ----
#pragma unroll
        for (int kk = 0; kk < 8; kk++) {
            uint32_t kb = (uint32_t)(kk * 32);
            uint32_t ap[4];
            LDSM4(ap[0], ap[1], ap[2], ap[3], PS + aBase + ((kb + aKsel) ^ swl));
            uint32_t bOff = (kb + bKsel) ^ swl;
#pragma unroll
            for (int j = 0; j < 4; j++) {
                uint32_t r0, r1, r2, r3;
                LDSM4(r0, r1, r2, r3, VS + (uint32_t)((bRow + j * 16) * 256) + bOff);
                uint32_t bv0[2] = {r0, r1}, bv1[2] = {r2, r3};
                MMA_TF32(oacc[2 * j],     ap, bv0);
                MMA_TF32(oacc[2 * j + 1], ap, bv1);
            }
        }
    }

    // ---- normalize and store ----
    float inv0 = 1.f / l0, inv1 = 1.f / l1;
    long r0g = (long)(b * 1024 + qt * 128 + wid * 16 + qr) * 512 + h * 64;
    long r1g = r0g + 8 * 512;
#pragma unroll
    for (int ni = 0; ni < 8; ni++) {
        int col = ni * 8 + qc * 2;
        *(float2*)&g_out_hi[r0g + col] = make_float2(oacc[ni][0] * inv0, oacc[ni][1] * inv0);
        *(float2*)&g_out_hi[r1g + col] = make_float2(oacc[ni][2] * inv1, oacc[ni][3] * inv1);
    }
}

// ---------------- lo-branch windowed attention + fused hi upsample-add ----------------
__global__ void __launch_bounds__(256) lo_attn_kernel() {
    int gid  = blockIdx.x * blockDim.x + threadIdx.x;
    int warp = gid >> 5;
    int lane = gid & 31;
    int h = warp & 7;
    int w = (warp >> 3) & 1023;
    int b = warp >> 13;

    const float* base = g_qkv_lo + (long)((b * 1024 + w) * 4) * 1536 + h * 64 + 2 * lane;
    float2 q[4], k[4], v[4];
#pragma unroll
    for (int t = 0; t < 4; t++) {
        q[t] = *(const float2*)(base + (long)t * 1536);
        k[t] = *(const float2*)(base + (long)t * 1536 + 512);
        v[t] = *(const float2*)(base + (long)t * 1536 + 1024);
    }

    float lg[4][4];
#pragma unroll
    for (int ti = 0; ti < 4; ti++)
#pragma unroll
        for (int tj = 0; tj < 4; tj++) {
            float p = q[ti].x * k[tj].x + q[ti].y * k[tj].y;
            p += __shfl_xor_sync(0xffffffffu, p, 16);
            p += __shfl_xor_sync(0xffffffffu, p, 8);
            p += __shfl_xor_sync(0xffffffffu, p, 4);
            p += __shfl_xor_sync(0xffffffffu, p, 2);
            p += __shfl_xor_sync(0xffffffffu, p, 1);
            lg[ti][tj] = p * SCALE;
        }

    int hh = w >> 5, wh = w & 31;
    long hibase = (long)b * 1024 * 512;
    int ccol = h * 64 + 2 * lane;
#pragma unroll
    for (int ti = 0; ti < 4; ti++) {
        float mx = fmaxf(fmaxf(lg[ti][0], lg[ti][1]), fmaxf(lg[ti][2], lg[ti][3]));
        float e0 = __expf(lg[ti][0] - mx);
        float e1 = __expf(lg[ti][1] - mx);
        float e2 = __expf(lg[ti][2] - mx);
        float e3 = __expf(lg[ti][3] - mx);
        float is = 1.f / (e0 + e1 + e2 + e3);
        float ox = (e0 * v[0].x + e1 * v[1].x + e2 * v[2].x + e3 * v[3].x) * is;
        float oy = (e0 * v[0].y + e1 * v[1].y + e2 * v[2].y + e3 * v[3].y) * is;

        // fused bilinear upsample of hi branch (half-pixel, 32->64)
        int y  = 2 * hh + (ti >> 1);
        int xq = 2 * wh + (ti & 1);
        float sy = 0.5f * y - 0.25f;
        int   y0 = (int)floorf(sy);
        float fy = sy - (float)y0;
        int   y1 = min(y0 + 1, 31); y0 = max(y0, 0);
        float sx = 0.5f * xq - 0.25f;
        int   x0 = (int)floorf(sx);
        float fx = sx - (float)x0;
        int   x1 = min(x0 + 1, 31); x0 = max(x0, 0);
        float w00 = (1.f - fy) * (1.f - fx), w01 = (1.f - fy) * fx;
        float w10 = fy * (1.f - fx),         w11 = fy * fx;

        float2 v00 = *(const float2*)&g_out_hi[hibase + (long)(y0 * 32 + x0) * 512 + ccol];
        float2 v01 = *(const float2*)&g_out_hi[hibase + (long)(y0 * 32 + x1) * 512 + ccol];
        float2 v10 = *(const float2*)&g_out_hi[hibase + (long)(y1 * 32 + x0) * 512 + ccol];
        float2 v11 = *(const float2*)&g_out_hi[hibase + (long)(y1 * 32 + x1) * 512 + ccol];
        float hx = w00 * v00.x + w01 * v01.x + w10 * v10.x + w11 * v11.x;
        float hy = w00 * v00.y + w01 * v01.y + w10 * v10.y + w11 * v11.y;

        int pos = y * 64 + xq;
        *(float2*)&g_comb[(long)(b * 4096 + pos) * 512 + ccol] =
            make_float2(ox + hx, oy + hy);
    }
}

// ---------------- launch ----------------
extern "C" void kernel_launch(void* const* d_in, const int* in_sizes, int n_in,
                              void* d_out, int out_size) {
    const float* x     = (const float*)d_in[0];
    const float* Wqkv  = (const float*)d_in[1];
    const float* Wproj = (const float*)d_in[2];
    const float* bproj = (const float*)d_in[3];
    float* out = (float*)d_out;

    float *xhi, *qkvhi, *win, *qkvlo, *comb;
    cudaGetSymbolAddress((void**)&xhi,   g_xhi);
    cudaGetSymbolAddress((void**)&qkvhi, g_qkv_hi);
    cudaGetSymbolAddress((void**)&win,   g_win);
    cudaGetSymbolAddress((void**)&qkvlo, g_qkv_lo);
    cudaGetSymbolAddress((void**)&comb,  g_comb);

    cudaFuncSetAttribute(mma_gemm<false>, cudaFuncAttributeMaxDynamicSharedMemorySize, GEMM_SMEM);
    cudaFuncSetAttribute(mma_gemm<true>,  cudaFuncAttributeMaxDynamicSharedMemorySize, GEMM_SMEM);
    cudaFuncSetAttribute(flash_hi_tc,     cudaFuncAttributeMaxDynamicSharedMemorySize, FLASH_SMEM);

    // 1. fused avg-pool + window gather
    prep_kernel<<<16384, 256>>>(x);
    // 2. QKV GEMMs (tf32 mma.sync tensor cores)
    mma_gemm<false><<<dim3(12, 64),  256, GEMM_SMEM>>>(xhi, Wqkv, nullptr, qkvhi, 8192,  1536, 512);
    mma_gemm<false><<<dim3(12, 256), 256, GEMM_SMEM>>>(win, Wqkv, nullptr, qkvlo, 32768, 1536, 512);
    // 3. hi attention (tensor core flash), then lo attention fused with upsample-add
    flash_hi_tc<<<dim3(8, 64), 256, FLASH_SMEM>>>();
    lo_attn_kernel<<<8192, 256>>>();
    // 4. output projection (+bias, tf32 mma.sync)
    mma_gemm<true><<<dim3(4, 256), 256, GEMM_SMEM>>>(comb, Wproj, bproj, out, 32768, 512, 512);
}

// round 8
// speedup vs baseline: 3.5180x; 1.2387x over previous
#include <cuda_runtime.h>
#include <math.h>
#include <stdint.h>

// ---------------- problem constants ----------------
#define B_    8
#define N_    4096      // tokens per batch (64x64)
#define C_    512
#define NH_   8         // heads
#define HD_   64        // head dim
#define SCALE 0.125f    // hd^-0.5

// ---------------- scratch (device globals; no allocation allowed) ----------------
__device__ float g_xhi   [B_*1024*C_];     //  16 MB  pooled tokens (tf32-rounded)
__device__ float g_qkv_hi[B_*1024*3*C_];   //  50 MB
__device__ float g_out_hi[B_*1024*C_];     //  16 MB
__device__ float g_win   [B_*N_*C_];       //  64 MB  window tokens (tf32-rounded)
__device__ float g_qkv_lo[B_*N_*3*C_];     // 201 MB
__device__ float g_comb  [B_*N_*C_];       //  64 MB  combined (tf32-rounded)
__device__ float g_wq_r  [3*C_*C_];        //   3 MB  Wqkv tf32-rounded
__device__ float g_wp_r  [C_*C_];          //   1 MB  Wproj tf32-rounded

// ======================= PTX helpers =======================
__device__ __forceinline__ uint32_t smem_u32(const void* p) {
    uint32_t a;
    asm("{ .reg .u64 t; cvta.to.shared.u64 t, %1; cvt.u32.u64 %0, t; }" : "=r"(a) : "l"(p));
    return a;
}
__device__ __forceinline__ float to_tf32(float x) {
    float r;
    asm("cvt.rna.tf32.f32 %0, %1;" : "=f"(r) : "f"(x));
    return r;
}

#define LDSM4(d0, d1, d2, d3, addr)                                            \
    asm volatile("ldmatrix.sync.aligned.m8n8.x4.shared.b16 {%0,%1,%2,%3}, [%4];" \
                 : "=r"(d0), "=r"(d1), "=r"(d2), "=r"(d3) : "r"(addr))

#define MMA_TF32(c, a, b)                                                      \
    asm volatile("mma.sync.aligned.m16n8k8.row.col.f32.tf32.tf32.f32 "         \
                 "{%0,%1,%2,%3}, {%4,%5,%6,%7}, {%8,%9}, {%0,%1,%2,%3};"       \
                 : "+f"((c)[0]), "+f"((c)[1]), "+f"((c)[2]), "+f"((c)[3])      \
                 : "r"((a)[0]), "r"((a)[1]), "r"((a)[2]), "r"((a)[3]),         \
                   "r"((b)[0]), "r"((b)[1]))

#define STSV4(addr, x, y, z, w)                                                \
    asm volatile("st.shared.v4.b32 [%0], {%1,%2,%3,%4};"                       \
                 :: "r"(addr), "f"(x), "f"(y), "f"(z), "f"(w) : "memory")
#define STSV2(addr, x, y)                                                      \
    asm volatile("st.shared.v2.b32 [%0], {%1,%2};"                             \
                 :: "r"(addr), "f"(x), "f"(y) : "memory")
#define STSB32(addr, x)                                                        \
    asm volatile("st.shared.b32 [%0], %1;" :: "r"(addr), "f"(x) : "memory")
#define LDSV4(x, y, z, w, addr)                                                \
    asm volatile("ld.shared.v4.b32 {%0,%1,%2,%3}, [%4];"                       \
                 : "=f"(x), "=f"(y), "=f"(z), "=f"(w) : "r"(addr))
#define CP_ASYNC16(dst, src)                                                   \
    asm volatile("cp.async.cg.shared.global [%0], [%1], 16;"                   \
                 :: "r"(dst), "l"(src) : "memory")
#define CP_COMMIT()  asm volatile("cp.async.commit_group;" ::: "memory")
#define CP_WAIT0()   asm volatile("cp.async.wait_group 0;" ::: "memory")
#define CP_WAIT1()   asm volatile("cp.async.wait_group 1;" ::: "memory")

// ======================= mma.sync tf32 GEMM v2 =======================
// C[M,N] = A[M,K] * B[N,K]^T (+bias). Inputs MUST be pre-rounded to tf32.
// Tile 128x128, BK=32; cp.async 2-stage pipeline; 2 blocks/SM.
#define GEMM_SMEM (1024 + 65536)

template <bool BIAS>
__global__ void __launch_bounds__(256, 2) mma_gemm(
    const float* __restrict__ A, const float* __restrict__ Bm,
    const float* __restrict__ bias, float* __restrict__ Cm,
    int M, int N, int K)
{
    extern __shared__ char dsm[];
    uint32_t sb = (smem_u32(dsm) + 1023u) & ~1023u;
    // stage s: A at sb + s*32768, B at +16384

    const int t = threadIdx.x;
    const int bm = blockIdx.y, bn = blockIdx.x;
    const int lane = t & 31, wid = t >> 5;
    const int warp_m = wid & 1, warp_n = wid >> 1;

    const int f4 = t & 7;
    const int row0 = t >> 3;
    const float* Ap = A  + (long)(bm * 128 + row0) * K + f4 * 4;
    const float* Bp = Bm + (long)(bn * 128 + row0) * K + f4 * 4;
    uint32_t stOff[4];
#pragma unroll
    for (int g = 0; g < 4; g++) {
        uint32_t off = (row0 + 32 * g) * 128 + f4 * 16;
        stOff[g] = off ^ ((off >> 3) & 0x70);
    }

    const int l = lane & 7, g8 = lane >> 3;
    const int aRow = warp_m * 64 + (g8 & 1) * 8 + l;
    const uint32_t aSw   = (uint32_t)((aRow & 7) << 4);
    const uint32_t aKoff = (uint32_t)((g8 >> 1) * 16);
    const int bRow = warp_n * 32 + (g8 >> 1) * 8 + l;
    const uint32_t bSw   = (uint32_t)((bRow & 7) << 4);
    const uint32_t bKoff = (uint32_t)((g8 & 1) * 16);

    float acc[4][4][4];
#pragma unroll
    for (int mi = 0; mi < 4; mi++)
#pragma unroll
        for (int ni = 0; ni < 4; ni++)
#pragma unroll
            for (int q = 0; q < 4; q++) acc[mi][ni][q] = 0.f;

    const int KC = K >> 5;
    {   // prologue: copy chunk 0 -> stage 0
        uint32_t sA = sb, sB = sb + 16384;
#pragma unroll
        for (int g = 0; g < 4; g++) {
            CP_ASYNC16(sA + stOff[g], Ap + (long)(g * 32) * K);
            CP_ASYNC16(sB + stOff[g], Bp + (long)(g * 32) * K);
        }
        CP_COMMIT();
    }

    for (int c = 0; c < KC; c++) {
        if (c + 1 < KC) {
            uint32_t sA = sb + ((c + 1) & 1) * 32768, sB = sA + 16384;
            const float* An = Ap + (c + 1) * 32;
            const float* Bn = Bp + (c + 1) * 32;
#pragma unroll
            for (int g = 0; g < 4; g++) {
                CP_ASYNC16(sA + stOff[g], An + (long)(g * 32) * K);
                CP_ASYNC16(sB + stOff[g], Bn + (long)(g * 32) * K);
            }
            CP_COMMIT();
            CP_WAIT1();   // chunk c complete; chunk c+1 in flight
        } else {
            CP_WAIT0();
        }
        __syncthreads();

        uint32_t bufA = sb + (c & 1) * 32768;
        uint32_t bufB = bufA + 16384;
#pragma unroll
        for (int kk = 0; kk < 4; kk++) {
            uint32_t aOff = ((uint32_t)(kk * 32) + aKoff) ^ aSw;
            uint32_t bOff = ((uint32_t)(kk * 32) + bKoff) ^ bSw;
            uint32_t af[4][4], bf[4][2];
#pragma unroll
            for (int mi = 0; mi < 4; mi++)
                LDSM4(af[mi][0], af[mi][1], af[mi][2], af[mi][3],
                      bufA + (uint32_t)((aRow + mi * 16) * 128) + aOff);
#pragma unroll
            for (int j = 0; j < 2; j++) {
                uint32_t r0, r1, r2, r3;
                LDSM4(r0, r1, r2, r3,
                      bufB + (uint32_t)((bRow + j * 16) * 128) + bOff);
                bf[2 * j][0] = r0;     bf[2 * j][1] = r1;
                bf[2 * j + 1][0] = r2; bf[2 * j + 1][1] = r3;
            }
#pragma unroll
            for (int mi = 0; mi < 4; mi++)
#pragma unroll
                for (int ni = 0; ni < 4; ni++)
                    MMA_TF32(acc[mi][ni], af[mi], bf[ni]);
        }
        __syncthreads();   // all warps done with buf c before chunk c+2 overwrites it
    }

    const int qr = lane >> 2, qc = lane & 3;
#pragma unroll
    for (int mi = 0; mi < 4; mi++) {
        int row = bm * 128 + warp_m * 64 + mi * 16 + qr;
#pragma unroll
        for (int ni = 0; ni < 4; ni++) {
            int col = bn * 128 + warp_n * 32 + ni * 8 + qc * 2;
            float bx = 0.f, by = 0.f;
            if (BIAS) { float2 b2 = *(const float2*)&bias[col]; bx = b2.x; by = b2.y; }
            *(float2*)&Cm[(long)row * N + col] =
                make_float2(acc[mi][ni][0] + bx, acc[mi][ni][1] + by);
            *(float2*)&Cm[(long)(row + 8) * N + col] =
                make_float2(acc[mi][ni][2] + bx, acc[mi][ni][3] + by);
        }
    }
}

// ---------------- weight rounding (Wqkv + Wproj -> tf32) ----------------
__global__ void round_w_kernel(const float* __restrict__ wq, const float* __restrict__ wp) {
    int i = blockIdx.x * blockDim.x + threadIdx.x;   // 262144 float4 slots
    if (i < 196608) {
        float4 v = ((const float4*)wq)[i];
        ((float4*)g_wq_r)[i] = make_float4(to_tf32(v.x), to_tf32(v.y), to_tf32(v.z), to_tf32(v.w));
    } else {
        float4 v = ((const float4*)wp)[i - 196608];
        ((float4*)g_wp_r)[i - 196608] = make_float4(to_tf32(v.x), to_tf32(v.y), to_tf32(v.z), to_tf32(v.w));
    }
}

// ---------------- prep: fused avg-pool + window gather (tf32-rounded outputs) ----------------
__global__ void prep_kernel(const float* __restrict__ x) {
    int id = blockIdx.x * blockDim.x + threadIdx.x;
    int ch = id & 511;
    int w  = (id >> 9) & 1023;
    int b  = id >> 19;
    int hh = w >> 5, wh = w & 31;

    int r0 = (b * 4096 + (2 * hh) * 64 + 2 * wh) * 512 + ch;
    float v00 = x[r0];
    float v01 = x[r0 + 512];
    float v10 = x[r0 + 64 * 512];
    float v11 = x[r0 + 65 * 512];

    g_xhi[(b * 1024 + w) * 512 + ch] = to_tf32(0.25f * (v00 + v01 + v10 + v11));

    int t = ch >> 7;
    int c = (4 * ch) & 511;
    float4 f4 = make_float4(to_tf32(v00), to_tf32(v01), to_tf32(v10), to_tf32(v11));
    *(float4*)&g_win[(long)((b * 1024 + w) * 4 + t) * 512 + c] = f4;
}

// ======================= tensor-core hi-branch flash attention v4 (unchanged) =======================
#define RAWK_OFF 65536
#define RAWV_OFF (65536 + 17408)
#define FLASH_SMEM (65536 + 2 * 17408 + 1024)

__global__ void __launch_bounds__(256, 1) flash_hi_tc() {
    extern __shared__ char fsm[];
    uint32_t sb = (smem_u32(fsm) + 1023u) & ~1023u;
    const uint32_t KH = sb, VS = sb + 16384, PS = sb + 32768;
    const uint32_t RK = sb + RAWK_OFF, RV = sb + RAWV_OFF;

    const int t = threadIdx.x, lane = t & 31, wid = t >> 5;
    const int qt = blockIdx.x, bh = blockIdx.y;
    const int b = bh >> 3, h = bh & 7;

    const int krow = t >> 2, kq4 = t & 3;
    const int vtok = t & 63, vdb = (t >> 6) * 16;
    const uint32_t rkd = RK + (uint32_t)(krow * 272 + kq4 * 64);
    const uint32_t rvd = RV + (uint32_t)(vtok * 272 + vdb * 4);
    const float* kv_base = g_qkv_hi + (long)(b * 1024) * 1536 + 512 + h * 64;

    {
        const float* kg = kv_base + (long)krow * 1536 + kq4 * 16;
        const float* vg = kv_base + (long)vtok * 1536 + 512 + vdb;
#pragma unroll
        for (int i = 0; i < 4; i++) {
            CP_ASYNC16(rkd + i * 16, kg + i * 4);
            CP_ASYNC16(rvd + i * 16, vg + i * 4);
        }
        CP_COMMIT();
    }

    const int l7 = lane & 7, g8 = lane >> 3;
    const int aRow = wid * 16 + (g8 & 1) * 8 + l7;
    const uint32_t aKsel = (uint32_t)((g8 >> 1) * 16);
    const int bRow = (g8 >> 1) * 8 + l7;
    const uint32_t bKsel = (uint32_t)((g8 & 1) * 16);
    const uint32_t swl = (uint32_t)(l7 << 4);
    const uint32_t aBase = (uint32_t)(aRow * 256);
    const int qr = lane >> 2, qc = lane & 3;

    uint32_t qh[8][4];
    {
        int row = t >> 1, hb = t & 1;
        const float* qg = g_qkv_hi + (long)(b * 1024 + qt * 128 + row) * 1536 + h * 64 + hb * 32;
        uint32_t rbase = (uint32_t)(row * 256);
        uint32_t rsw = (uint32_t)((row & 7) << 4);
#pragma unroll
        for (int i = 0; i < 8; i++) {
            float4 v = *(const float4*)(qg + i * 4);
            v.x *= SCALE; v.y *= SCALE; v.z *= SCALE; v.w *= SCALE;
            uint32_t off = ((uint32_t)(hb * 128 + i * 16)) ^ rsw;
            STSV4(KH + rbase + off, to_tf32(v.x), to_tf32(v.y), to_tf32(v.z), to_tf32(v.w));
        }
        __syncthreads();
#pragma unroll
        for (int kk = 0; kk < 8; kk++)
            LDSM4(qh[kk][0], qh[kk][1], qh[kk][2], qh[kk][3],
                  KH + aBase + (((uint32_t)(kk * 32) + aKsel) ^ swl));
    }

    float oacc[8][4];
#pragma unroll
    for (int ni = 0; ni < 8; ni++)
#pragma unroll
        for (int q = 0; q < 4; q++) oacc[ni][q] = 0.f;
    float m0 = -1e30f, m1 = -1e30f, l0 = 0.f, l1 = 0.f;

    for (int kt = 0; kt < 16; kt++) {
        CP_WAIT0();
        __syncthreads();

        {
            uint32_t rbase = (uint32_t)(krow * 256);
            uint32_t rsw = (uint32_t)((krow & 7) << 4);
#pragma unroll
            for (int i = 0; i < 4; i++) {
                float x_, y_, z_, w_;
                LDSV4(x_, y_, z_, w_, rkd + i * 16);
                uint32_t off = ((uint32_t)(kq4 * 64 + i * 16)) ^ rsw;
                STSV4(KH + rbase + off, to_tf32(x_), to_tf32(y_), to_tf32(z_), to_tf32(w_));
            }
        }
        {
            uint32_t tokb = (uint32_t)(vtok * 4);
#pragma unroll
            for (int i = 0; i < 4; i++) {
                float x_, y_, z_, w_;
                LDSV4(x_, y_, z_, w_, rvd + i * 16);
                int d0 = vdb + i * 4;
                STSB32(VS + (uint32_t)((d0 + 0) * 256) + (tokb ^ (uint32_t)(((d0 + 0) & 7) << 4)), to_tf32(x_));
                STSB32(VS + (uint32_t)((d0 + 1) * 256) + (tokb ^ (uint32_t)(((d0 + 1) & 7) << 4)), to_tf32(y_));
                STSB32(VS + (uint32_t)((d0 + 2) * 256) + (tokb ^ (uint32_t)(((d0 + 2) & 7) << 4)), to_tf32(z_));
                STSB32(VS + (uint32_t)((d0 + 3) * 256) + (tokb ^ (uint32_t)(((d0 + 3) & 7) << 4)), to_tf32(w_));
            }
        }
        if (kt + 1 < 16) {
            const float* kg = kv_base + (long)((kt + 1) * 64 + krow) * 1536 + kq4 * 16;
            const float* vg = kv_base + (long)((kt + 1) * 64 + vtok) * 1536 + 512 + vdb;
#pragma unroll
            for (int i = 0; i < 4; i++) {
                CP_ASYNC16(rkd + i * 16, kg + i * 4);
                CP_ASYNC16(rvd + i * 16, vg + i * 4);
            }
            CP_COMMIT();
        }
        __syncthreads();

        float sacc[8][4];
#pragma unroll
        for (int ni = 0; ni < 8; ni++)
#pragma unroll
            for (int q = 0; q < 4; q++) sacc[ni][q] = 0.f;

#pragma unroll
        for (int kk = 0; kk < 8; kk++) {
            uint32_t bOff = ((uint32_t)(kk * 32) + bKsel) ^ swl;
#pragma unroll
            for (int j = 0; j < 4; j++) {
                uint32_t r0, r1, r2, r3;
                LDSM4(r0, r1, r2, r3, KH + (uint32_t)((bRow + j * 16) * 256) + bOff);
                uint32_t bh0[2] = {r0, r1}, bh1[2] = {r2, r3};
                MMA_TF32(sacc[2 * j],     qh[kk], bh0);
                MMA_TF32(sacc[2 * j + 1], qh[kk], bh1);
            }
        }

        float cm0 = -1e30f, cm1 = -1e30f;
#pragma unroll
        for (int ni = 0; ni < 8; ni++) {
            cm0 = fmaxf(cm0, fmaxf(sacc[ni][0], sacc[ni][1]));
            cm1 = fmaxf(cm1, fmaxf(sacc[ni][2], sacc[ni][3]));
        }
        cm0 = fmaxf(cm0, __shfl_xor_sync(0xffffffffu, cm0, 1));
        cm0 = fmaxf(cm0, __shfl_xor_sync(0xffffffffu, cm0, 2));
        cm1 = fmaxf(cm1, __shfl_xor_sync(0xffffffffu, cm1, 1));
        cm1 = fmaxf(cm1, __shfl_xor_sync(0xffffffffu, cm1, 2));

        float nm0 = fmaxf(m0, cm0), nm1 = fmaxf(m1, cm1);
        float a0 = __expf(m0 - nm0), a1 = __expf(m1 - nm1);
        float rs0 = 0.f, rs1 = 0.f;
        const uint32_t pr0 = PS + (uint32_t)((wid * 16 + qr) * 256);
        const uint32_t pr1 = PS + (uint32_t)((wid * 16 + qr + 8) * 256);
        const uint32_t sw0 = (uint32_t)((qr & 7) << 4);
        const uint32_t sw1 = (uint32_t)(((qr + 8) & 7) << 4);
#pragma unroll
        for (int ni = 0; ni < 8; ni++) {
            float p0 = __expf(sacc[ni][0] - nm0);
            float p1 = __expf(sacc[ni][1] - nm0);
            float p2 = __expf(sacc[ni][2] - nm1);
            float p3 = __expf(sacc[ni][3] - nm1);
            float q0 = to_tf32(p0), q1 = to_tf32(p1), q2 = to_tf32(p2), q3 = to_tf32(p3);
            rs0 += q0 + q1; rs1 += q2 + q3;
            uint32_t cb = (uint32_t)(ni * 32 + qc * 8);
            STSV2(pr0 + (cb ^ sw0), q0, q1);
            STSV2(pr1 + (cb ^ sw1), q2, q3);
        }
        rs0 += __shfl_xor_sync(0xffffffffu, rs0, 1);
        rs0 += __shfl_xor_sync(0xffffffffu, rs0, 2);
        rs1 += __shfl_xor_sync(0xffffffffu, rs1, 1);
        rs1 += __shfl_xor_sync(0xffffffffu, rs1, 2);
        m0 = nm0; m1 = nm1;
        l0 = l0 * a0 + rs0; l1 = l1 * a1 + rs1;
#pragma unroll
        for (int ni = 0; ni < 8; ni++) {
            oacc[ni][0] *= a0; oacc[ni][1] *= a0;
            oacc[ni][2] *= a1; oacc[ni][3] *= a1;
        }
        __syncwarp();

#pragma unroll
        for (int kk = 0; kk < 8; kk++) {
            uint32_t kb = (uint32_t)(kk * 32);
            uint32_t ap[4];
            LDSM4(ap[0], ap[1], ap[2], ap[3], PS + aBase + ((kb + aKsel) ^ swl));
            uint32_t bOff = (kb + bKsel) ^ swl;
#pragma unroll
            for (int j = 0; j < 4; j++) {
                uint32_t r0, r1, r2, r3;
                LDSM4(r0, r1, r2, r3, VS + (uint32_t)((bRow + j * 16) * 256) + bOff);
                uint32_t bv0[2] = {r0, r1}, bv1[2] = {r2, r3};
                MMA_TF32(oacc[2 * j],     ap, bv0);
                MMA_TF32(oacc[2 * j + 1], ap, bv1);
            }
        }
    }

    float inv0 = 1.f / l0, inv1 = 1.f / l1;
    long r0g = (long)(b * 1024 + qt * 128 + wid * 16 + qr) * 512 + h * 64;
    long r1g = r0g + 8 * 512;
#pragma unroll
    for (int ni = 0; ni < 8; ni++) {
        int col = ni * 8 + qc * 2;
        *(float2*)&g_out_hi[r0g + col] = make_float2(oacc[ni][0] * inv0, oacc[ni][1] * inv0);
        *(float2*)&g_out_hi[r1g + col] = make_float2(oacc[ni][2] * inv1, oacc[ni][3] * inv1);
    }
}

// ---------------- lo-branch windowed attention + fused hi upsample-add (tf32-rounded out) ----------------
__global__ void __launch_bounds__(256) lo_attn_kernel() {
    int gid  = blockIdx.x * blockDim.x + threadIdx.x;
    int warp = gid >> 5;
    int lane = gid & 31;
    int h = warp & 7;
    int w = (warp >> 3) & 1023;
    int b = warp >> 13;

    const float* base = g_qkv_lo + (long)((b * 1024 + w) * 4) * 1536 + h * 64 + 2 * lane;
    float2 q[4], k[4], v[4];
#pragma unroll
    for (int t = 0; t < 4; t++) {
        q[t] = *(const float2*)(base + (long)t * 1536);
        k[t] = *(const float2*)(base + (long)t * 1536 + 512);
        v[t] = *(const float2*)(base + (long)t * 1536 + 1024);
    }

    float lg[4][4];
#pragma unroll
    for (int ti = 0; ti < 4; ti++)
#pragma unroll
        for (int tj = 0; tj < 4; tj++) {
            float p = q[ti].x * k[tj].x + q[ti].y * k[tj].y;
            p += __shfl_xor_sync(0xffffffffu, p, 16);
            p += __shfl_xor_sync(0xffffffffu, p, 8);
            p += __shfl_xor_sync(0xffffffffu, p, 4);
            p += __shfl_xor_sync(0xffffffffu, p, 2);
            p += __shfl_xor_sync(0xffffffffu, p, 1);
            lg[ti][tj] = p * SCALE;
        }

    int hh = w >> 5, wh = w & 31;
    long hibase = (long)b * 1024 * 512;
    int ccol = h * 64 + 2 * lane;
#pragma unroll
    for (int ti = 0; ti < 4; ti++) {
        float mx = fmaxf(fmaxf(lg[ti][0], lg[ti][1]), fmaxf(lg[ti][2], lg[ti][3]));
        float e0 = __expf(lg[ti][0] - mx);
        float e1 = __expf(lg[ti][1] - mx);
        float e2 = __expf(lg[ti][2] - mx);
        float e3 = __expf(lg[ti][3] - mx);
        float is = 1.f / (e0 + e1 + e2 + e3);
        float ox = (e0 * v[0].x + e1 * v[1].x + e2 * v[2].x + e3 * v[3].x) * is;
        float oy = (e0 * v[0].y + e1 * v[1].y + e2 * v[2].y + e3 * v[3].y) * is;

        int y  = 2 * hh + (ti >> 1);
        int xq = 2 * wh + (ti & 1);
        float sy = 0.5f * y - 0.25f;
        int   y0 = (int)floorf(sy);
        float fy = sy - (float)y0;
        int   y1 = min(y0 + 1, 31); y0 = max(y0, 0);
        float sx = 0.5f * xq - 0.25f;
        int   x0 = (int)floorf(sx);
        float fx = sx - (float)x0;
        int   x1 = min(x0 + 1, 31); x0 = max(x0, 0);
        float w00 = (1.f - fy) * (1.f - fx), w01 = (1.f - fy) * fx;
        float w10 = fy * (1.f - fx),         w11 = fy * fx;

        float2 v00 = *(const float2*)&g_out_hi[hibase + (long)(y0 * 32 + x0) * 512 + ccol];
        float2 v01 = *(const float2*)&g_out_hi[hibase + (long)(y0 * 32 + x1) * 512 + ccol];
        float2 v10 = *(const float2*)&g_out_hi[hibase + (long)(y1 * 32 + x0) * 512 + ccol];
        float2 v11 = *(const float2*)&g_out_hi[hibase + (long)(y1 * 32 + x1) * 512 + ccol];
        float hx = w00 * v00.x + w01 * v01.x + w10 * v10.x + w11 * v11.x;
        float hy = w00 * v00.y + w01 * v01.y + w10 * v10.y + w11 * v11.y;

        int pos = y * 64 + xq;
        *(float2*)&g_comb[(long)(b * 4096 + pos) * 512 + ccol] =
            make_float2(to_tf32(ox + hx), to_tf32(oy + hy));
    }
}

// ---------------- launch ----------------
extern "C" void kernel_launch(void* const* d_in, const int* in_sizes, int n_in,
                              void* d_out, int out_size) {
    const float* x     = (const float*)d_in[0];
    const float* Wqkv  = (const float*)d_in[1];
    const float* Wproj = (const float*)d_in[2];
    const float* bproj = (const float*)d_in[3];
    float* out = (float*)d_out;

    float *xhi, *qkvhi, *win, *qkvlo, *comb, *wqr, *wpr;
    cudaGetSymbolAddress((void**)&xhi,   g_xhi);
    cudaGetSymbolAddress((void**)&qkvhi, g_qkv_hi);
    cudaGetSymbolAddress((void**)&win,   g_win);
    cudaGetSymbolAddress((void**)&qkvlo, g_qkv_lo);
    cudaGetSymbolAddress((void**)&comb,  g_comb);
    cudaGetSymbolAddress((void**)&wqr,   g_wq_r);
    cudaGetSymbolAddress((void**)&wpr,   g_wp_r);

    cudaFuncSetAttribute(mma_gemm<false>, cudaFuncAttributeMaxDynamicSharedMemorySize, GEMM_SMEM);
    cudaFuncSetAttribute(mma_gemm<true>,  cudaFuncAttributeMaxDynamicSharedMemorySize, GEMM_SMEM);
    cudaFuncSetAttribute(flash_hi_tc,     cudaFuncAttributeMaxDynamicSharedMemorySize, FLASH_SMEM);

    // 0. round weights to tf32
    round_w_kernel<<<1024, 256>>>(Wqkv, Wproj);
    // 1. fused avg-pool + window gather (tf32-rounded)
    prep_kernel<<<16384, 256>>>(x);
    // 2. QKV GEMMs (tf32 mma.sync, cp.async pipeline, 2 blocks/SM)
    mma_gemm<false><<<dim3(12, 64),  256, GEMM_SMEM>>>(xhi, wqr, nullptr, qkvhi, 8192,  1536, 512);
    mma_gemm<false><<<dim3(12, 256), 256, GEMM_SMEM>>>(win, wqr, nullptr, qkvlo, 32768, 1536, 512);
    // 3. hi attention (tensor core flash), then lo attention fused with upsample-add
    flash_hi_tc<<<dim3(8, 64), 256, FLASH_SMEM>>>();
    lo_attn_kernel<<<8192, 256>>>();
    // 4. output projection (+bias)
    mma_gemm<true><<<dim3(4, 256), 256, GEMM_SMEM>>>(comb, wpr, bproj, out, 32768, 512, 512);
}

// round 9
// speedup vs baseline: 3.5909x; 1.0207x over previous
#include <cuda_runtime.h>
#include <math.h>
#include <stdint.h>

// ---------------- problem constants ----------------
#define B_    8
#define N_    4096      // tokens per batch (64x64)
#define C_    512
#define NH_   8         // heads
#define HD_   64        // head dim
#define SCALE 0.125f    // hd^-0.5

// ---------------- scratch (device globals; no allocation allowed) ----------------
__device__ float g_xhi   [B_*1024*C_];     //  16 MB  pooled tokens (tf32-rounded)
__device__ float g_qkv_hi[B_*1024*3*C_];   //  50 MB
__device__ float g_out_hi[B_*1024*C_];     //  16 MB
__device__ float g_win   [B_*N_*C_];       //  64 MB  window tokens (tf32-rounded)
__device__ float g_qkv_lo[B_*N_*3*C_];     // 201 MB
__device__ float g_comb  [B_*N_*C_];       //  64 MB  combined (tf32-rounded)
__device__ float g_wq_r  [3*C_*C_];        //   3 MB  Wqkv tf32-rounded
__device__ float g_wp_r  [C_*C_];          //   1 MB  Wproj tf32-rounded

// ======================= PTX helpers =======================
__device__ __forceinline__ uint32_t smem_u32(const void* p) {
    uint32_t a;
    asm("{ .reg .u64 t; cvta.to.shared.u64 t, %1; cvt.u32.u64 %0, t; }" : "=r"(a) : "l"(p));
    return a;
}
__device__ __forceinline__ float to_tf32(float x) {
    float r;
    asm("cvt.rna.tf32.f32 %0, %1;" : "=f"(r) : "f"(x));
    return r;
}

#define LDSM4(d0, d1, d2, d3, addr)                                            \
    asm volatile("ldmatrix.sync.aligned.m8n8.x4.shared.b16 {%0,%1,%2,%3}, [%4];" \
                 : "=r"(d0), "=r"(d1), "=r"(d2), "=r"(d3) : "r"(addr))

#define MMA_TF32(c, a, b)                                                      \
    asm volatile("mma.sync.aligned.m16n8k8.row.col.f32.tf32.tf32.f32 "         \
                 "{%0,%1,%2,%3}, {%4,%5,%6,%7}, {%8,%9}, {%0,%1,%2,%3};"       \
                 : "+f"((c)[0]), "+f"((c)[1]), "+f"((c)[2]), "+f"((c)[3])      \
                 : "r"((a)[0]), "r"((a)[1]), "r"((a)[2]), "r"((a)[3]),         \
                   "r"((b)[0]), "r"((b)[1]))

#define STSV4(addr, x, y, z, w)                                                \
    asm volatile("st.shared.v4.b32 [%0], {%1,%2,%3,%4};"                       \
                 :: "r"(addr), "f"(x), "f"(y), "f"(z), "f"(w) : "memory")
#define STSV2(addr, x, y)                                                      \
    asm volatile("st.shared.v2.b32 [%0], {%1,%2};"                             \
                 :: "r"(addr), "f"(x), "f"(y) : "memory")
#define STSB32(addr, x)                                                        \
    asm volatile("st.shared.b32 [%0], %1;" :: "r"(addr), "f"(x) : "memory")
#define LDSV4(x, y, z, w, addr)                                                \
    asm volatile("ld.shared.v4.b32 {%0,%1,%2,%3}, [%4];"                       \
                 : "=f"(x), "=f"(y), "=f"(z), "=f"(w) : "r"(addr))
#define CP_ASYNC16(dst, src)                                                   \
    asm volatile("cp.async.cg.shared.global [%0], [%1], 16;"                   \
                 :: "r"(dst), "l"(src) : "memory")
#define CP_COMMIT()  asm volatile("cp.async.commit_group;" ::: "memory")
#define CP_WAIT0()   asm volatile("cp.async.wait_group 0;" ::: "memory")
#define CP_WAIT1()   asm volatile("cp.async.wait_group 1;" ::: "memory")

// ======================= mma.sync tf32 GEMM v2 (unchanged) =======================
#define GEMM_SMEM (1024 + 65536)

template <bool BIAS>
__global__ void __launch_bounds__(256, 2) mma_gemm(
    const float* __restrict__ A, const float* __restrict__ Bm,
    const float* __restrict__ bias, float* __restrict__ Cm,
    int M, int N, int K)
{
    extern __shared__ char dsm[];
    uint32_t sb = (smem_u32(dsm) + 1023u) & ~1023u;

    const int t = threadIdx.x;
    const int bm = blockIdx.y, bn = blockIdx.x;
    const int lane = t & 31, wid = t >> 5;
    const int warp_m = wid & 1, warp_n = wid >> 1;

    const int f4 = t & 7;
    const int row0 = t >> 3;
    const float* Ap = A  + (long)(bm * 128 + row0) * K + f4 * 4;
    const float* Bp = Bm + (long)(bn * 128 + row0) * K + f4 * 4;
    uint32_t stOff[4];
#pragma unroll
    for (int g = 0; g < 4; g++) {
        uint32_t off = (row0 + 32 * g) * 128 + f4 * 16;
        stOff[g] = off ^ ((off >> 3) & 0x70);
    }

    const int l = lane & 7, g8 = lane >> 3;
    const int aRow = warp_m * 64 + (g8 & 1) * 8 + l;
    const uint32_t aSw   = (uint32_t)((aRow & 7) << 4);
    const uint32_t aKoff = (uint32_t)((g8 >> 1) * 16);
    const int bRow = warp_n * 32 + (g8 >> 1) * 8 + l;
    const uint32_t bSw   = (uint32_t)((bRow & 7) << 4);
    const uint32_t bKoff = (uint32_t)((g8 & 1) * 16);

    float acc[4][4][4];
#pragma unroll
    for (int mi = 0; mi < 4; mi++)
#pragma unroll
        for (int ni = 0; ni < 4; ni++)
#pragma unroll
            for (int q = 0; q < 4; q++) acc[mi][ni][q] = 0.f;

    const int KC = K >> 5;
    {
        uint32_t sA = sb, sB = sb + 16384;
#pragma unroll
        for (int g = 0; g < 4; g++) {
            CP_ASYNC16(sA + stOff[g], Ap + (long)(g * 32) * K);
            CP_ASYNC16(sB + stOff[g], Bp + (long)(g * 32) * K);
        }
        CP_COMMIT();
    }

    for (int c = 0; c < KC; c++) {
        if (c + 1 < KC) {
            uint32_t sA = sb + ((c + 1) & 1) * 32768, sB = sA + 16384;
            const float* An = Ap + (c + 1) * 32;
            const float* Bn = Bp + (c + 1) * 32;
#pragma unroll
            for (int g = 0; g < 4; g++) {
                CP_ASYNC16(sA + stOff[g], An + (long)(g * 32) * K);
                CP_ASYNC16(sB + stOff[g], Bn + (long)(g * 32) * K);
            }
            CP_COMMIT();
            CP_WAIT1();
        } else {
            CP_WAIT0();
        }
        __syncthreads();

        uint32_t bufA = sb + (c & 1) * 32768;
        uint32_t bufB = bufA + 16384;
#pragma unroll
        for (int kk = 0; kk < 4; kk++) {
            uint32_t aOff = ((uint32_t)(kk * 32) + aKoff) ^ aSw;
            uint32_t bOff = ((uint32_t)(kk * 32) + bKoff) ^ bSw;
            uint32_t af[4][4], bf[4][2];
#pragma unroll
            for (int mi = 0; mi < 4; mi++)
                LDSM4(af[mi][0], af[mi][1], af[mi][2], af[mi][3],
                      bufA + (uint32_t)((aRow + mi * 16) * 128) + aOff);
#pragma unroll
            for (int j = 0; j < 2; j++) {
                uint32_t r0, r1, r2, r3;
                LDSM4(r0, r1, r2, r3,
                      bufB + (uint32_t)((bRow + j * 16) * 128) + bOff);
                bf[2 * j][0] = r0;     bf[2 * j][1] = r1;
                bf[2 * j + 1][0] = r2; bf[2 * j + 1][1] = r3;
            }
#pragma unroll
            for (int mi = 0; mi < 4; mi++)
#pragma unroll
                for (int ni = 0; ni < 4; ni++)
                    MMA_TF32(acc[mi][ni], af[mi], bf[ni]);
        }
        __syncthreads();
    }

    const int qr = lane >> 2, qc = lane & 3;
#pragma unroll
    for (int mi = 0; mi < 4; mi++) {
        int row = bm * 128 + warp_m * 64 + mi * 16 + qr;
#pragma unroll
        for (int ni = 0; ni < 4; ni++) {
            int col = bn * 128 + warp_n * 32 + ni * 8 + qc * 2;
            float bx = 0.f, by = 0.f;
            if (BIAS) { float2 b2 = *(const float2*)&bias[col]; bx = b2.x; by = b2.y; }
            *(float2*)&Cm[(long)row * N + col] =
                make_float2(acc[mi][ni][0] + bx, acc[mi][ni][1] + by);
            *(float2*)&Cm[(long)(row + 8) * N + col] =
                make_float2(acc[mi][ni][2] + bx, acc[mi][ni][3] + by);
        }
    }
}

// ---------------- weight rounding (Wqkv + Wproj -> tf32) ----------------
__global__ void round_w_kernel(const float* __restrict__ wq, const float* __restrict__ wp) {
    int i = blockIdx.x * blockDim.x + threadIdx.x;
    if (i < 196608) {
        float4 v = ((const float4*)wq)[i];
        ((float4*)g_wq_r)[i] = make_float4(to_tf32(v.x), to_tf32(v.y), to_tf32(v.z), to_tf32(v.w));
    } else {
        float4 v = ((const float4*)wp)[i - 196608];
        ((float4*)g_wp_r)[i - 196608] = make_float4(to_tf32(v.x), to_tf32(v.y), to_tf32(v.z), to_tf32(v.w));
    }
}

// ---------------- prep: fused avg-pool + window gather (tf32-rounded outputs) ----------------
__global__ void prep_kernel(const float* __restrict__ x) {
    int id = blockIdx.x * blockDim.x + threadIdx.x;
    int ch = id & 511;
    int w  = (id >> 9) & 1023;
    int b  = id >> 19;
    int hh = w >> 5, wh = w & 31;

    int r0 = (b * 4096 + (2 * hh) * 64 + 2 * wh) * 512 + ch;
    float v00 = x[r0];
    float v01 = x[r0 + 512];
    float v10 = x[r0 + 64 * 512];
    float v11 = x[r0 + 65 * 512];

    g_xhi[(b * 1024 + w) * 512 + ch] = to_tf32(0.25f * (v00 + v01 + v10 + v11));

    int t = ch >> 7;
    int c = (4 * ch) & 511;
    float4 f4 = make_float4(to_tf32(v00), to_tf32(v01), to_tf32(v10), to_tf32(v11));
    *(float4*)&g_win[(long)((b * 1024 + w) * 4 + t) * 512 + c] = f4;
}

// ======================= tensor-core hi-branch flash attention v4 (unchanged) =======================
#define RAWK_OFF 65536
#define RAWV_OFF (65536 + 17408)
#define FLASH_SMEM (65536 + 2 * 17408 + 1024)

__global__ void __launch_bounds__(256, 1) flash_hi_tc() {
    extern __shared__ char fsm[];
    uint32_t sb = (smem_u32(fsm) + 1023u) & ~1023u;
    const uint32_t KH = sb, VS = sb + 16384, PS = sb + 32768;
    const uint32_t RK = sb + RAWK_OFF, RV = sb + RAWV_OFF;

    const int t = threadIdx.x, lane = t & 31, wid = t >> 5;
    const int qt = blockIdx.x, bh = blockIdx.y;
    const int b = bh >> 3, h = bh & 7;

    const int krow = t >> 2, kq4 = t & 3;
    const int vtok = t & 63, vdb = (t >> 6) * 16;
    const uint32_t rkd = RK + (uint32_t)(krow * 272 + kq4 * 64);
    const uint32_t rvd = RV + (uint32_t)(vtok * 272 + vdb * 4);
    const float* kv_base = g_qkv_hi + (long)(b * 1024) * 1536 + 512 + h * 64;

    {
        const float* kg = kv_base + (long)krow * 1536 + kq4 * 16;
        const float* vg = kv_base + (long)vtok * 1536 + 512 + vdb;
#pragma unroll
        for (int i = 0; i < 4; i++) {
            CP_ASYNC16(rkd + i * 16, kg + i * 4);
            CP_ASYNC16(rvd + i * 16, vg + i * 4);
        }
        CP_COMMIT();
    }

    const int l7 = lane & 7, g8 = lane >> 3;
    const int aRow = wid * 16 + (g8 & 1) * 8 + l7;
    const uint32_t aKsel = (uint32_t)((g8 >> 1) * 16);
    const int bRow = (g8 >> 1) * 8 + l7;
    const uint32_t bKsel = (uint32_t)((g8 & 1) * 16);
    const uint32_t swl = (uint32_t)(l7 << 4);
    const uint32_t aBase = (uint32_t)(aRow * 256);
    const int qr = lane >> 2, qc = lane & 3;

    uint32_t qh[8][4];
    {
        int row = t >> 1, hb = t & 1;
        const float* qg = g_qkv_hi + (long)(b * 1024 + qt * 128 + row) * 1536 + h * 64 + hb * 32;
        uint32_t rbase = (uint32_t)(row * 256);
        uint32_t rsw = (uint32_t)((row & 7) << 4);
#pragma unroll
        for (int i = 0; i < 8; i++) {
            float4 v = *(const float4*)(qg + i * 4);
            v.x *= SCALE; v.y *= SCALE; v.z *= SCALE; v.w *= SCALE;
            uint32_t off = ((uint32_t)(hb * 128 + i * 16)) ^ rsw;
            STSV4(KH + rbase + off, to_tf32(v.x), to_tf32(v.y), to_tf32(v.z), to_tf32(v.w));
        }
        __syncthreads();
#pragma unroll
        for (int kk = 0; kk < 8; kk++)
            LDSM4(qh[kk][0], qh[kk][1], qh[kk][2], qh[kk][3],
                  KH + aBase + (((uint32_t)(kk * 32) + aKsel) ^ swl));
    }

    float oacc[8][4];
#pragma unroll
    for (int ni = 0; ni < 8; ni++)
#pragma unroll
        for (int q = 0; q < 4; q++) oacc[ni][q] = 0.f;
    float m0 = -1e30f, m1 = -1e30f, l0 = 0.f, l1 = 0.f;

    for (int kt = 0; kt < 16; kt++) {
        CP_WAIT0();
        __syncthreads();

        {
            uint32_t rbase = (uint32_t)(krow * 256);
            uint32_t rsw = (uint32_t)((krow & 7) << 4);
#pragma unroll
            for (int i = 0; i < 4; i++) {
                float x_, y_, z_, w_;
                LDSV4(x_, y_, z_, w_, rkd + i * 16);
                uint32_t off = ((uint32_t)(kq4 * 64 + i * 16)) ^ rsw;
                STSV4(KH + rbase + off, to_tf32(x_), to_tf32(y_), to_tf32(z_), to_tf32(w_));
            }
        }
        {
            uint32_t tokb = (uint32_t)(vtok * 4);
#pragma unroll
            for (int i = 0; i < 4; i++) {
                float x_, y_, z_, w_;
                LDSV4(x_, y_, z_, w_, rvd + i * 16);
                int d0 = vdb + i * 4;
                STSB32(VS + (uint32_t)((d0 + 0) * 256) + (tokb ^ (uint32_t)(((d0 + 0) & 7) << 4)), to_tf32(x_));
                STSB32(VS + (uint32_t)((d0 + 1) * 256) + (tokb ^ (uint32_t)(((d0 + 1) & 7) << 4)), to_tf32(y_));
                STSB32(VS + (uint32_t)((d0 + 2) * 256) + (tokb ^ (uint32_t)(((d0 + 2) & 7) << 4)), to_tf32(z_));
                STSB32(VS + (uint32_t)((d0 + 3) * 256) + (tokb ^ (uint32_t)(((d0 + 3) & 7) << 4)), to_tf32(w_));
            }
        }
        if (kt + 1 < 16) {
            const float* kg = kv_base + (long)((kt + 1) * 64 + krow) * 1536 + kq4 * 16;
            const float* vg = kv_base + (long)((kt + 1) * 64 + vtok) * 1536 + 512 + vdb;
#pragma unroll
            for (int i = 0; i < 4; i++) {
                CP_ASYNC16(rkd + i * 16, kg + i * 4);
                CP_ASYNC16(rvd + i * 16, vg + i * 4);
            }
            CP_COMMIT();
        }
        __syncthreads();

        float sacc[8][4];
#pragma unroll
        for (int ni = 0; ni < 8; ni++)
#pragma unroll
            for (int q = 0; q < 4; q++) sacc[ni][q] = 0.f;

#pragma unroll
        for (int kk = 0; kk < 8; kk++) {
            uint32_t bOff = ((uint32_t)(kk * 32) + bKsel) ^ swl;
#pragma unroll
            for (int j = 0; j < 4; j++) {
                uint32_t r0, r1, r2, r3;
                LDSM4(r0, r1, r2, r3, KH + (uint32_t)((bRow + j * 16) * 256) + bOff);
                uint32_t bh0[2] = {r0, r1}, bh1[2] = {r2, r3};
                MMA_TF32(sacc[2 * j],     qh[kk], bh0);
                MMA_TF32(sacc[2 * j + 1], qh[kk], bh1);
            }
        }

        float cm0 = -1e30f, cm1 = -1e30f;
#pragma unroll
        for (int ni = 0; ni < 8; ni++) {
            cm0 = fmaxf(cm0, fmaxf(sacc[ni][0], sacc[ni][1]));
            cm1 = fmaxf(cm1, fmaxf(sacc[ni][2], sacc[ni][3]));
        }
        cm0 = fmaxf(cm0, __shfl_xor_sync(0xffffffffu, cm0, 1));
        cm0 = fmaxf(cm0, __shfl_xor_sync(0xffffffffu, cm0, 2));
        cm1 = fmaxf(cm1, __shfl_xor_sync(0xffffffffu, cm1, 1));
        cm1 = fmaxf(cm1, __shfl_xor_sync(0xffffffffu, cm1, 2));

        float nm0 = fmaxf(m0, cm0), nm1 = fmaxf(m1, cm1);
        float a0 = __expf(m0 - nm0), a1 = __expf(m1 - nm1);
        float rs0 = 0.f, rs1 = 0.f;
        const uint32_t pr0 = PS + (uint32_t)((wid * 16 + qr) * 256);
        const uint32_t pr1 = PS + (uint32_t)((wid * 16 + qr + 8) * 256);
        const uint32_t sw0 = (uint32_t)((qr & 7) << 4);
        const uint32_t sw1 = (uint32_t)(((qr + 8) & 7) << 4);
#pragma unroll
        for (int ni = 0; ni < 8; ni++) {
            float p0 = __expf(sacc[ni][0] - nm0);
            float p1 = __expf(sacc[ni][1] - nm0);
            float p2 = __expf(sacc[ni][2] - nm1);
            float p3 = __expf(sacc[ni][3] - nm1);
            float q0 = to_tf32(p0), q1 = to_tf32(p1), q2 = to_tf32(p2), q3 = to_tf32(p3);
            rs0 += q0 + q1; rs1 += q2 + q3;
            uint32_t cb = (uint32_t)(ni * 32 + qc * 8);
            STSV2(pr0 + (cb ^ sw0), q0, q1);
            STSV2(pr1 + (cb ^ sw1), q2, q3);
        }
        rs0 += __shfl_xor_sync(0xffffffffu, rs0, 1);
        rs0 += __shfl_xor_sync(0xffffffffu, rs0, 2);
        rs1 += __shfl_xor_sync(0xffffffffu, rs1, 1);
        rs1 += __shfl_xor_sync(0xffffffffu, rs1, 2);
        m0 = nm0; m1 = nm1;
        l0 = l0 * a0 + rs0; l1 = l1 * a1 + rs1;
#pragma unroll
        for (int ni = 0; ni < 8; ni++) {
            oacc[ni][0] *= a0; oacc[ni][1] *= a0;
            oacc[ni][2] *= a1; oacc[ni][3] *= a1;
        }
        __syncwarp();

#pragma unroll
        for (int kk = 0; kk < 8; kk++) {
            uint32_t kb = (uint32_t)(kk * 32);
            uint32_t ap[4];
            LDSM4(ap[0], ap[1], ap[2], ap[3], PS + aBase + ((kb + aKsel) ^ swl));
            uint32_t bOff = (kb + bKsel) ^ swl;
#pragma unroll
            for (int j = 0; j < 4; j++) {
                uint32_t r0, r1, r2, r3;
                LDSM4(r0, r1, r2, r3, VS + (uint32_t)((bRow + j * 16) * 256) + bOff);
                uint32_t bv0[2] = {r0, r1}, bv1[2] = {r2, r3};
                MMA_TF32(oacc[2 * j],     ap, bv0);
                MMA_TF32(oacc[2 * j + 1], ap, bv1);
            }
        }
    }

    float inv0 = 1.f / l0, inv1 = 1.f / l1;
    long r0g = (long)(b * 1024 + qt * 128 + wid * 16 + qr) * 512 + h * 64;
    long r1g = r0g + 8 * 512;
#pragma unroll
    for (int ni = 0; ni < 8; ni++) {
        int col = ni * 8 + qc * 2;
        *(float2*)&g_out_hi[r0g + col] = make_float2(oacc[ni][0] * inv0, oacc[ni][1] * inv0);
        *(float2*)&g_out_hi[r1g + col] = make_float2(oacc[ni][2] * inv1, oacc[ni][3] * inv1);
    }
}

// ---------------- lo-branch windowed attention + fused hi upsample-add (unchanged) ----------------
__global__ void __launch_bounds__(256) lo_attn_kernel() {
    int gid  = blockIdx.x * blockDim.x + threadIdx.x;
    int warp = gid >> 5;
    int lane = gid & 31;
    int h = warp & 7;
    int w = (warp >> 3) & 1023;
    int b = warp >> 13;

    const float* base = g_qkv_lo + (long)((b * 1024 + w) * 4) * 1536 + h * 64 + 2 * lane;
    float2 q[4], k[4], v[4];
#pragma unroll
    for (int t = 0; t < 4; t++) {
        q[t] = *(const float2*)(base + (long)t * 1536);
        k[t] = *(const float2*)(base + (long)t * 1536 + 512);
        v[t] = *(const float2*)(base + (long)t * 1536 + 1024);
    }

    float lg[4][4];
#pragma unroll
    for (int ti = 0; ti < 4; ti++)
#pragma unroll
        for (int tj = 0; tj < 4; tj++) {
            float p = q[ti].x * k[tj].x + q[ti].y * k[tj].y;
            p += __shfl_xor_sync(0xffffffffu, p, 16);
            p += __shfl_xor_sync(0xffffffffu, p, 8);
            p += __shfl_xor_sync(0xffffffffu, p, 4);
            p += __shfl_xor_sync(0xffffffffu, p, 2);
            p += __shfl_xor_sync(0xffffffffu, p, 1);
            lg[ti][tj] = p * SCALE;
        }

    int hh = w >> 5, wh = w & 31;
    long hibase = (long)b * 1024 * 512;
    int ccol = h * 64 + 2 * lane;
#pragma unroll
    for (int ti = 0; ti < 4; ti++) {
        float mx = fmaxf(fmaxf(lg[ti][0], lg[ti][1]), fmaxf(lg[ti][2], lg[ti][3]));
        float e0 = __expf(lg[ti][0] - mx);
        float e1 = __expf(lg[ti][1] - mx);
        float e2 = __expf(lg[ti][2] - mx);
        float e3 = __expf(lg[ti][3] - mx);
        float is = 1.f / (e0 + e1 + e2 + e3);
        float ox = (e0 * v[0].x + e1 * v[1].x + e2 * v[2].x + e3 * v[3].x) * is;
        float oy = (e0 * v[0].y + e1 * v[1].y + e2 * v[2].y + e3 * v[3].y) * is;

        int y  = 2 * hh + (ti >> 1);
        int xq = 2 * wh + (ti & 1);
        float sy = 0.5f * y - 0.25f;
        int   y0 = (int)floorf(sy);
        float fy = sy - (float)y0;
        int   y1 = min(y0 + 1, 31); y0 = max(y0, 0);
        float sx = 0.5f * xq - 0.25f;
        int   x0 = (int)floorf(sx);
        float fx = sx - (float)x0;
        int   x1 = min(x0 + 1, 31); x0 = max(x0, 0);
        float w00 = (1.f - fy) * (1.f - fx), w01 = (1.f - fy) * fx;
        float w10 = fy * (1.f - fx),         w11 = fy * fx;

        float2 v00 = *(const float2*)&g_out_hi[hibase + (long)(y0 * 32 + x0) * 512 + ccol];
        float2 v01 = *(const float2*)&g_out_hi[hibase + (long)(y0 * 32 + x1) * 512 + ccol];
        float2 v10 = *(const float2*)&g_out_hi[hibase + (long)(y1 * 32 + x0) * 512 + ccol];
        float2 v11 = *(const float2*)&g_out_hi[hibase + (long)(y1 * 32 + x1) * 512 + ccol];
        float hx = w00 * v00.x + w01 * v01.x + w10 * v10.x + w11 * v11.x;
        float hy = w00 * v00.y + w01 * v01.y + w10 * v10.y + w11 * v11.y;

        int pos = y * 64 + xq;
        *(float2*)&g_comb[(long)(b * 4096 + pos) * 512 + ccol] =
            make_float2(to_tf32(ox + hx), to_tf32(oy + hy));
    }
}

// ---------------- launch (dual-stream overlap: lo-GEMM ∥ hi-GEMM+flash) ----------------
extern "C" void kernel_launch(void* const* d_in, const int* in_sizes, int n_in,
                              void* d_out, int out_size) {
    const float* x     = (const float*)d_in[0];
    const float* Wqkv  = (const float*)d_in[1];
    const float* Wproj = (const float*)d_in[2];
    const float* bproj = (const float*)d_in[3];
    float* out = (float*)d_out;

    float *xhi, *qkvhi, *win, *qkvlo, *comb, *wqr, *wpr;
    cudaGetSymbolAddress((void**)&xhi,   g_xhi);
    cudaGetSymbolAddress((void**)&qkvhi, g_qkv_hi);
    cudaGetSymbolAddress((void**)&win,   g_win);
    cudaGetSymbolAddress((void**)&qkvlo, g_qkv_lo);
    cudaGetSymbolAddress((void**)&comb,  g_comb);
    cudaGetSymbolAddress((void**)&wqr,   g_wq_r);
    cudaGetSymbolAddress((void**)&wpr,   g_wp_r);

    cudaFuncSetAttribute(mma_gemm<false>, cudaFuncAttributeMaxDynamicSharedMemorySize, GEMM_SMEM);
    cudaFuncSetAttribute(mma_gemm<true>,  cudaFuncAttributeMaxDynamicSharedMemorySize, GEMM_SMEM);
    cudaFuncSetAttribute(flash_hi_tc,     cudaFuncAttributeMaxDynamicSharedMemorySize, FLASH_SMEM);

    // one-time side stream + fork/join events (host objects only; no device mem)
    static cudaStream_t s2 = nullptr;
    static cudaEvent_t evFork = nullptr, evJoin = nullptr;
    if (s2 == nullptr) {
        cudaStreamCreateWithFlags(&s2, cudaStreamNonBlocking);
        cudaEventCreateWithFlags(&evFork, cudaEventDisableTiming);
        cudaEventCreateWithFlags(&evJoin, cudaEventDisableTiming);
    }

    // 0. weight rounding + prep (main stream)
    round_w_kernel<<<1024, 256>>>(Wqkv, Wproj);
    prep_kernel<<<16384, 256>>>(x);

    // fork: lo QKV GEMM on side stream
    cudaEventRecord(evFork, 0);
    cudaStreamWaitEvent(s2, evFork, 0);
    mma_gemm<false><<<dim3(12, 256), 256, GEMM_SMEM, s2>>>(win, wqr, nullptr, qkvlo, 32768, 1536, 512);
    cudaEventRecord(evJoin, s2);

    // main stream: hi QKV GEMM -> flash attention (overlaps with lo GEMM)
    mma_gemm<false><<<dim3(12, 64), 256, GEMM_SMEM>>>(xhi, wqr, nullptr, qkvhi, 8192, 1536, 512);
    flash_hi_tc<<<dim3(8, 64), 256, FLASH_SMEM>>>();

    // join, then lo attention (+ upsample-add) and output projection
    cudaStreamWaitEvent(0, evJoin, 0);
    lo_attn_kernel<<<8192, 256>>>();
    mma_gemm<true><<<dim3(4, 256), 256, GEMM_SMEM>>>(comb, wpr, bproj, out, 32768, 512, 512);
}